// round 1
// baseline (speedup 1.0000x reference)
#include <cuda_runtime.h>
#include <cstdint>

#define B_TOK 4096
#define D_INV 2048
#define NF    16384
#define TOPK  32
#define KAUX  256
#define DEADTH 100

// ---------------- scratch (device globals; no allocation allowed) ----------
__device__ float  g_pre[(size_t)B_TOK * NF];     // 256 MB
__device__ int    g_tk_idx[B_TOK * TOPK];
__device__ float  g_tk_val[B_TOK * TOPK];
__device__ int    g_tk_cnt[B_TOK];
__device__ int    g_ax_idx[B_TOK * KAUX];
__device__ float  g_ax_val[B_TOK * KAUX];
__device__ int    g_ax_cnt[B_TOK];
__device__ int    g_active[NF];
__device__ int    g_dead[NF];
__device__ double g_pmse[B_TOK];
__device__ double g_paux[B_TOK];

// ---------------- f32x2 packed-FMA helpers (FFMA2, sm_100+) ----------------
__device__ __forceinline__ unsigned long long pk2(float lo, float hi) {
    unsigned long long r;
    asm("mov.b64 %0, {%1, %2};" : "=l"(r) : "f"(lo), "f"(hi));
    return r;
}
__device__ __forceinline__ void fma2(unsigned long long& acc,
                                     unsigned long long a, unsigned long long b) {
    asm("fma.rn.f32x2 %0, %1, %2, %0;" : "+l"(acc) : "l"(a), "l"(b));
}
__device__ __forceinline__ float2 upk2(unsigned long long v) {
    float2 r;
    asm("mov.b64 {%0, %1}, %2;" : "=f"(r.x), "=f"(r.y) : "l"(v));
    return r;
}

// ---------------- encoder GEMM: pre = x @ W_enc + b_enc --------------------
// A [4096,2048] row-major, B [2048,16384] row-major, C [4096,16384] row-major
// 128x128 tile, BK=16, 256 threads, 8x8 per thread, f32x2 packed accumulators.
__global__ __launch_bounds__(256, 2)
void gemm_enc_kernel(const float* __restrict__ A, const float* __restrict__ B,
                     const float* __restrict__ bias) {
    __shared__ float As[16][128];
    __shared__ float Bs[16][128];

    const int Kd = D_INV, N = NF;
    const int bm = blockIdx.y, bn = blockIdx.x;
    const int tid = threadIdx.x;
    const int tx = tid % 16, ty = tid / 16;

    const int arow  = tid >> 2;          // 0..63
    const int acol4 = (tid & 3) * 4;     // 0,4,8,12
    const int brow  = tid >> 5;          // 0..7
    const int bcol4 = (tid & 31) * 4;    // 0..124

    const float* Ab = A + (size_t)(bm * 128) * Kd;
    const float* Bb = B + bn * 128;

    unsigned long long accp[8][4];
#pragma unroll
    for (int i = 0; i < 8; i++)
#pragma unroll
        for (int j = 0; j < 4; j++) accp[i][j] = 0ull;

    for (int kt = 0; kt < Kd; kt += 16) {
#pragma unroll
        for (int h = 0; h < 2; h++) {
            int r = arow + 64 * h;
            float4 v = *(const float4*)(Ab + (size_t)r * Kd + kt + acol4);
            As[acol4 + 0][r] = v.x;
            As[acol4 + 1][r] = v.y;
            As[acol4 + 2][r] = v.z;
            As[acol4 + 3][r] = v.w;
        }
#pragma unroll
        for (int h = 0; h < 2; h++) {
            int r = brow + 8 * h;
            *(float4*)&Bs[r][bcol4] = *(const float4*)(Bb + (size_t)(kt + r) * N + bcol4);
        }
        __syncthreads();

#pragma unroll
        for (int kk = 0; kk < 16; kk++) {
            float4 a0 = *(const float4*)&As[kk][ty * 4];
            float4 a1 = *(const float4*)&As[kk][64 + ty * 4];
            float4 b0 = *(const float4*)&Bs[kk][tx * 4];
            float4 b1 = *(const float4*)&Bs[kk][64 + tx * 4];
            unsigned long long bp[4];
            bp[0] = pk2(b0.x, b0.y); bp[1] = pk2(b0.z, b0.w);
            bp[2] = pk2(b1.x, b1.y); bp[3] = pk2(b1.z, b1.w);
            float av[8] = {a0.x, a0.y, a0.z, a0.w, a1.x, a1.y, a1.z, a1.w};
#pragma unroll
            for (int i = 0; i < 8; i++) {
                unsigned long long ap = pk2(av[i], av[i]);
                fma2(accp[i][0], ap, bp[0]);
                fma2(accp[i][1], ap, bp[1]);
                fma2(accp[i][2], ap, bp[2]);
                fma2(accp[i][3], ap, bp[3]);
            }
        }
        __syncthreads();
    }

    // epilogue: add bias, store
    const int row0 = bm * 128, col0 = bn * 128;
    float bb[8];
#pragma unroll
    for (int jh = 0; jh < 2; jh++) {
        int c = col0 + jh * 64 + tx * 4;
        float4 bv = *(const float4*)(bias + c);
        bb[jh * 4 + 0] = bv.x; bb[jh * 4 + 1] = bv.y;
        bb[jh * 4 + 2] = bv.z; bb[jh * 4 + 3] = bv.w;
    }
#pragma unroll
    for (int ih = 0; ih < 2; ih++) {
#pragma unroll
        for (int ii = 0; ii < 4; ii++) {
            int i = ih * 4 + ii;
            int r = row0 + ih * 64 + ty * 4 + ii;
            float* Crow = g_pre + (size_t)r * NF;
#pragma unroll
            for (int jh = 0; jh < 2; jh++) {
                int c = col0 + jh * 64 + tx * 4;
                float2 lo = upk2(accp[i][jh * 2 + 0]);
                float2 hi = upk2(accp[i][jh * 2 + 1]);
                float4 outv;
                outv.x = lo.x + bb[jh * 4 + 0];
                outv.y = lo.y + bb[jh * 4 + 1];
                outv.z = hi.x + bb[jh * 4 + 2];
                outv.w = hi.y + bb[jh * 4 + 3];
                *(float4*)&Crow[c] = outv;
            }
        }
    }
}

// ---------------- misc small kernels ---------------------------------------
__global__ void init_active_kernel() {
    int f = blockIdx.x * blockDim.x + threadIdx.x;
    if (f < NF) g_active[f] = 0;
}

__global__ void dead_kernel(const long long* __restrict__ steps) {
    int f = blockIdx.x * blockDim.x + threadIdx.x;
    if (f < NF)
        g_dead[f] = (g_active[f] == 0 && (steps[f] + 1) >= (long long)DEADTH) ? 1 : 0;
}

// ---------------- exact per-row top-k via 4-pass radix select --------------
// one block (256 thr) per row; keys kept in dynamic smem.
// is_aux=0: k=TOPK, writes coeffs + active + g_tk lists
// is_aux=1: k=KAUX, masks non-dead features to key 0, writes g_ax lists
__global__ __launch_bounds__(256)
void topk_kernel(int k, int is_aux, float* __restrict__ coeffs_out) {
    extern __shared__ unsigned sh[];
    unsigned* keys = sh;          // NF entries
    unsigned* hist = sh + NF;     // 256 entries
    __shared__ int s_bin, s_rem, s_cnt, s_pos;

    const int r = blockIdx.x;
    const int tid = threadIdx.x;
    const float* row = g_pre + (size_t)r * NF;

    for (int i = tid; i < NF; i += 256) {
        unsigned u = __float_as_uint(row[i]);
        u = (u & 0x80000000u) ? ~u : (u | 0x80000000u);  // order-preserving map
        if (is_aux && g_dead[i] == 0) u = 0u;            // masked = -inf (< any real key)
        keys[i] = u;
    }
    __syncthreads();

    unsigned prefix = 0;
    int remaining = k;
#pragma unroll
    for (int shift = 24; shift >= 0; shift -= 8) {
        hist[tid] = 0;  // blockDim==256
        __syncthreads();
        unsigned himask = (shift == 24) ? 0u : (0xFFFFFFFFu << (shift + 8));
        for (int i = tid; i < NF; i += 256) {
            unsigned u = keys[i];
            if ((u & himask) == prefix) atomicAdd(&hist[(u >> shift) & 255u], 1u);
        }
        __syncthreads();
        if (tid == 0) {
            int cum = 0, b = 255;
            for (; b > 0; b--) {
                int c = (int)hist[b];
                if (cum + c >= remaining) break;
                cum += c;
            }
            s_bin = b;
            s_rem = remaining - cum;
        }
        __syncthreads();
        prefix |= ((unsigned)s_bin) << shift;
        remaining = s_rem;
        __syncthreads();
    }

    if (tid == 0) { s_cnt = 0; s_pos = 0; }
    __syncthreads();

    const unsigned thr = prefix;  // exact key of k-th largest
    int* idx_out = is_aux ? g_ax_idx : g_tk_idx;
    float* val_out = is_aux ? g_ax_val : g_tk_val;
    const int stride = is_aux ? KAUX : TOPK;

    for (int i = tid; i < NF; i += 256) {
        unsigned u = keys[i];
        if (u > thr) {
            atomicAdd(&s_cnt, 1);
            // recover float from key (masked keys can never be > thr)
            unsigned bits = (u & 0x80000000u) ? (u ^ 0x80000000u) : ~u;
            float v = __uint_as_float(bits);
            if (v > 0.f) {  // relu
                int p = atomicAdd(&s_pos, 1);
                idx_out[r * stride + p] = i;
                val_out[r * stride + p] = v;
                if (!is_aux) {
                    coeffs_out[(size_t)r * NF + i] = v;
                    g_active[i] = 1;
                }
            }
        }
    }
    __syncthreads();

    if (tid == 0) {
        int need = k - s_cnt;  // ties at threshold to take
        if (thr != 0u) {       // thr==0 => ties are masked (-inf) -> relu 0
            for (int i = 0; i < NF && need > 0; i++) {
                if (keys[i] == thr) {
                    need--;
                    unsigned bits = (thr & 0x80000000u) ? (thr ^ 0x80000000u) : ~thr;
                    float v = __uint_as_float(bits);
                    if (v > 0.f) {
                        int p = s_pos++;
                        idx_out[r * stride + p] = i;
                        val_out[r * stride + p] = v;
                        if (!is_aux) {
                            coeffs_out[(size_t)r * NF + i] = v;
                            g_active[i] = 1;
                        }
                    }
                }
            }
        }
        if (is_aux) g_ax_cnt[r] = s_pos; else g_tk_cnt[r] = s_pos;
    }
}

// ---------------- sparse decode + deterministic MSE/aux partials -----------
__global__ __launch_bounds__(256)
void decode_kernel(const float* __restrict__ x, const float* __restrict__ Wd,
                   const float* __restrict__ bd, float* __restrict__ recon) {
    const int r = blockIdx.x, tid = threadIdx.x;
    __shared__ int   sidx[KAUX];
    __shared__ float sval[KAUX];
    __shared__ double sred[256];

    const int cnt = g_tk_cnt[r];
    if (tid < cnt) { sidx[tid] = g_tk_idx[r * TOPK + tid]; sval[tid] = g_tk_val[r * TOPK + tid]; }
    __syncthreads();

    float bdv[8], acc[8];
#pragma unroll
    for (int j = 0; j < 8; j++) { bdv[j] = bd[tid + 256 * j]; acc[j] = bdv[j]; }

    for (int t = 0; t < cnt; t++) {
        const float* w = Wd + (size_t)sidx[t] * D_INV;
        float v = sval[t];
#pragma unroll
        for (int j = 0; j < 8; j++) acc[j] += v * w[tid + 256 * j];
    }

    float xr[8];
#pragma unroll
    for (int j = 0; j < 8; j++) xr[j] = x[(size_t)r * D_INV + tid + 256 * j];

    double pm = 0.0;
#pragma unroll
    for (int j = 0; j < 8; j++) {
        recon[(size_t)r * D_INV + tid + 256 * j] = acc[j];
        float e = acc[j] - xr[j];
        pm += (double)e * (double)e;
    }

    __syncthreads();  // before reusing sidx/sval
    const int acnt = g_ax_cnt[r];
    if (tid < acnt) { sidx[tid] = g_ax_idx[r * KAUX + tid]; sval[tid] = g_ax_val[r * KAUX + tid]; }
    __syncthreads();

    float aacc[8];
#pragma unroll
    for (int j = 0; j < 8; j++) aacc[j] = bdv[j];
    for (int t = 0; t < acnt; t++) {
        const float* w = Wd + (size_t)sidx[t] * D_INV;
        float v = sval[t];
#pragma unroll
        for (int j = 0; j < 8; j++) aacc[j] += v * w[tid + 256 * j];
    }

    double pa = 0.0;
#pragma unroll
    for (int j = 0; j < 8; j++) {
        float resid = xr[j] - acc[j];
        float e = aacc[j] - resid;
        pa += (double)e * (double)e;
    }

    // deterministic block tree reductions
    sred[tid] = pm; __syncthreads();
    for (int s = 128; s > 0; s >>= 1) { if (tid < s) sred[tid] += sred[tid + s]; __syncthreads(); }
    if (tid == 0) g_pmse[r] = sred[0];
    __syncthreads();
    sred[tid] = pa; __syncthreads();
    for (int s = 128; s > 0; s >>= 1) { if (tid < s) sred[tid] += sred[tid + s]; __syncthreads(); }
    if (tid == 0) g_paux[r] = sred[0];
}

__global__ void finalize_kernel(float* __restrict__ scal) {
    __shared__ double sm[256], sa[256];
    const int tid = threadIdx.x;
    double m = 0.0, a = 0.0;
    for (int i = tid; i < B_TOK; i += 256) { m += g_pmse[i]; a += g_paux[i]; }
    sm[tid] = m; sa[tid] = a; __syncthreads();
    for (int s = 128; s > 0; s >>= 1) {
        if (tid < s) { sm[tid] += sm[tid + s]; sa[tid] += sa[tid + s]; }
        __syncthreads();
    }
    if (tid == 0) {
        const double denom = (double)B_TOK * (double)D_INV;
        double mse = sm[0] / denom;
        double aux = sa[0] / denom;
        scal[0] = (float)(mse + aux);
        scal[1] = (float)mse;
        scal[2] = (float)aux;
    }
}

// ---------------- launch ----------------------------------------------------
extern "C" void kernel_launch(void* const* d_in, const int* in_sizes, int n_in,
                              void* d_out, int out_size) {
    const float*     x     = (const float*)d_in[0];
    const float*     We    = (const float*)d_in[1];
    const float*     be    = (const float*)d_in[2];
    const float*     Wd    = (const float*)d_in[3];
    const float*     bd    = (const float*)d_in[4];
    const long long* steps = (const long long*)d_in[5];

    float* out    = (float*)d_out;
    float* recon  = out;                                       // [4096,2048]
    float* coeffs = out + (size_t)B_TOK * D_INV;               // [4096,16384]
    float* scal   = coeffs + (size_t)B_TOK * NF;               // loss, mse, aux

    const size_t topk_smem = (size_t)(NF + 256) * sizeof(unsigned);
    cudaFuncSetAttribute(topk_kernel, cudaFuncAttributeMaxDynamicSharedMemorySize,
                         (int)topk_smem);

    // zero coeffs region + active flags
    cudaMemsetAsync(coeffs, 0, (size_t)B_TOK * NF * sizeof(float));
    init_active_kernel<<<(NF + 255) / 256, 256>>>();

    // encoder GEMM -> g_pre
    gemm_enc_kernel<<<dim3(NF / 128, B_TOK / 128), 256>>>(x, We, be);

    // main top-32 (writes coeffs, lists, active flags)
    topk_kernel<<<B_TOK, 256, topk_smem>>>(TOPK, 0, coeffs);

    // dead mask
    dead_kernel<<<(NF + 255) / 256, 256>>>(steps);

    // aux top-256 over dead features
    topk_kernel<<<B_TOK, 256, topk_smem>>>(KAUX, 1, nullptr);

    // sparse decode + partial sums
    decode_kernel<<<B_TOK, 256>>>(x, Wd, bd, recon);

    // deterministic final reduction + scalars
    finalize_kernel<<<1, 256>>>(scal);
}

// round 3
// speedup vs baseline: 1.0537x; 1.0537x over previous
#include <cuda_runtime.h>
#include <cstdint>

#define B_TOK 4096
#define D_INV 2048
#define NF    16384
#define TOPK  32
#define KAUX  256
#define DEADTH 100

// GEMM tiling
#define TM 128
#define TN 128
#define BK 32
#define NIT (D_INV / BK)          // 64
#define ROWF 36                   // padded row stride in floats (conflict-free)
#define PLANE_F (128 * ROWF)      // 4608 floats per plane
#define STAGE_F (4 * PLANE_F)     // Ahi|Alo|Bhi|Blo
#define GEMM_SMEM (2 * STAGE_F * 4)  // 147456 bytes

// ---------------- scratch (device globals; no allocation allowed) ----------
__device__ float  g_pre[(size_t)B_TOK * NF];     // 256 MB
__device__ float  g_Ahi[(size_t)B_TOK * D_INV];
__device__ float  g_Alo[(size_t)B_TOK * D_INV];
__device__ float  g_Bhi[(size_t)NF * D_INV];     // transposed [NF][D_INV]
__device__ float  g_Blo[(size_t)NF * D_INV];
__device__ int    g_tk_idx[B_TOK * TOPK];
__device__ float  g_tk_val[B_TOK * TOPK];
__device__ int    g_tk_cnt[B_TOK];
__device__ int    g_ax_idx[B_TOK * KAUX];
__device__ float  g_ax_val[B_TOK * KAUX];
__device__ int    g_ax_cnt[B_TOK];
__device__ int    g_active[NF];
__device__ int    g_dead[NF];
__device__ double g_pmse[B_TOK];
__device__ double g_paux[B_TOK];

// ---------------- helpers ----------------------------------------------------
__device__ __forceinline__ uint32_t smem_u32(const void* p) {
    uint32_t a;
    asm("{ .reg .u64 t; cvta.to.shared.u64 t, %1; cvt.u32.u64 %0, t; }"
        : "=r"(a) : "l"(p));
    return a;
}
__device__ __forceinline__ void cpa16(uint32_t dst, const void* src) {
    asm volatile("cp.async.cg.shared.global [%0], [%1], 16;" :: "r"(dst), "l"(src));
}
__device__ __forceinline__ void tf32_split(float v, float& hi, float& lo) {
    uint32_t hb; asm("cvt.rna.tf32.f32 %0, %1;" : "=r"(hb) : "f"(v));
    hi = __uint_as_float(hb);
    float r = v - hi;
    uint32_t lb; asm("cvt.rna.tf32.f32 %0, %1;" : "=r"(lb) : "f"(r));
    lo = __uint_as_float(lb);
}

#define MMA_TF32(C, A, B) \
    asm volatile("mma.sync.aligned.m16n8k8.row.col.f32.tf32.tf32.f32 " \
        "{%0,%1,%2,%3}, {%4,%5,%6,%7}, {%8,%9}, {%0,%1,%2,%3};" \
        : "+f"((C)[0]), "+f"((C)[1]), "+f"((C)[2]), "+f"((C)[3]) \
        : "r"((A)[0]), "r"((A)[1]), "r"((A)[2]), "r"((A)[3]), \
          "r"((B)[0]), "r"((B)[1]))

// ---------------- convert pre-pass ------------------------------------------
__global__ __launch_bounds__(256) void conv_a_kernel(const float* __restrict__ A) {
    size_t i = (size_t)blockIdx.x * 256 + threadIdx.x;   // float4 index
    const float4 v = ((const float4*)A)[i];
    float4 h, l;
    tf32_split(v.x, h.x, l.x);
    tf32_split(v.y, h.y, l.y);
    tf32_split(v.z, h.z, l.z);
    tf32_split(v.w, h.w, l.w);
    ((float4*)g_Ahi)[i] = h;
    ((float4*)g_Alo)[i] = l;
}

// B [D_INV][NF] -> Bt planes [NF][D_INV], hi/lo, via 32x32 smem transpose
__global__ __launch_bounds__(256) void conv_b_kernel(const float* __restrict__ B) {
    __shared__ float sh[32][33];
    const int n0 = blockIdx.x * 32;
    const int k0 = blockIdx.y * 32;
    const int tx = threadIdx.x & 31, ty = threadIdx.x >> 5;
#pragma unroll
    for (int q = 0; q < 4; q++) {
        int k = ty + q * 8;
        sh[k][tx] = B[(size_t)(k0 + k) * NF + n0 + tx];
    }
    __syncthreads();
#pragma unroll
    for (int q = 0; q < 4; q++) {
        int n = ty + q * 8;
        float v = sh[tx][n];
        float h, l;
        tf32_split(v, h, l);
        size_t o = (size_t)(n0 + n) * D_INV + k0 + tx;
        g_Bhi[o] = h;
        g_Blo[o] = l;
    }
}

// ---------------- mma.sync tf32 GEMM: g_pre = x @ W_enc + b_enc -------------
// 3xTF32 emulation: D += Ah*Bh + Ah*Bl + Al*Bh. 128x128 tile, BK=32, 8 warps.
__global__ __launch_bounds__(256, 1)
void gemm_mma_kernel(const float* __restrict__ bias) {
    extern __shared__ float sm4[];
    const int tid = threadIdx.x;
    const int w = tid >> 5, lane = tid & 31;
    const int m0 = blockIdx.x * TM;
    const int n0 = blockIdx.y * TN;
    const int wmBase = (w & 1) * 64;
    const int wnBase = (w >> 1) * 32;

    float c[4][4][4];
#pragma unroll
    for (int mi = 0; mi < 4; mi++)
#pragma unroll
        for (int ni = 0; ni < 4; ni++)
#pragma unroll
            for (int j = 0; j < 4; j++) c[mi][ni][j] = 0.f;

    auto loadStage = [&](int s, int kt) {
        float* stf = sm4 + s * STAGE_F;
#pragma unroll
        for (int q = 0; q < 16; q++) {
            int t = tid + q * 256;
            int isB = t >> 11;                 // 0: A, 1: B
            int tb = t & 2047;
            int pf = tb >> 10;                 // 0: hi, 1: lo
            int rem = tb & 1023;
            int row = rem >> 3, cc = rem & 7;
            float* dst = stf + (isB * 2 + pf) * PLANE_F + row * ROWF + cc * 4;
            const float* base = isB ? (pf ? g_Blo : g_Bhi) : (pf ? g_Alo : g_Ahi);
            const float* src = base + (size_t)((isB ? n0 : m0) + row) * D_INV + kt + cc * 4;
            cpa16(smem_u32(dst), src);
        }
        asm volatile("cp.async.commit_group;");
    };

    loadStage(0, 0);
    loadStage(1, BK);

    for (int i = 0; i < NIT; i++) {
        if (i < NIT - 1) asm volatile("cp.async.wait_group 1;" ::: "memory");
        else             asm volatile("cp.async.wait_group 0;" ::: "memory");
        __syncthreads();

        const uint32_t* As0 = (const uint32_t*)(sm4 + (i & 1) * STAGE_F);
        const uint32_t* As1 = As0 + PLANE_F;
        const uint32_t* Bs0 = As0 + 2 * PLANE_F;
        const uint32_t* Bs1 = As0 + 3 * PLANE_F;

#pragma unroll
        for (int ks = 0; ks < 4; ks++) {
            const int k0 = ks * 8 + (lane & 3);
            uint32_t ah[4][4], al[4][4], bh[4][2], bl[4][2];
#pragma unroll
            for (int mi = 0; mi < 4; mi++) {
                int r0 = wmBase + mi * 16 + (lane >> 2);
                ah[mi][0] = As0[r0 * ROWF + k0];
                ah[mi][1] = As0[(r0 + 8) * ROWF + k0];
                ah[mi][2] = As0[r0 * ROWF + k0 + 4];
                ah[mi][3] = As0[(r0 + 8) * ROWF + k0 + 4];
                al[mi][0] = As1[r0 * ROWF + k0];
                al[mi][1] = As1[(r0 + 8) * ROWF + k0];
                al[mi][2] = As1[r0 * ROWF + k0 + 4];
                al[mi][3] = As1[(r0 + 8) * ROWF + k0 + 4];
            }
#pragma unroll
            for (int ni = 0; ni < 4; ni++) {
                int n = wnBase + ni * 8 + (lane >> 2);
                bh[ni][0] = Bs0[n * ROWF + k0];
                bh[ni][1] = Bs0[n * ROWF + k0 + 4];
                bl[ni][0] = Bs1[n * ROWF + k0];
                bl[ni][1] = Bs1[n * ROWF + k0 + 4];
            }
#pragma unroll
            for (int mi = 0; mi < 4; mi++)
#pragma unroll
                for (int ni = 0; ni < 4; ni++) {
                    MMA_TF32(c[mi][ni], ah[mi], bh[ni]);
                    MMA_TF32(c[mi][ni], ah[mi], bl[ni]);
                    MMA_TF32(c[mi][ni], al[mi], bh[ni]);
                }
        }
        __syncthreads();
        if (i + 2 < NIT) loadStage(i & 1, (i + 2) * BK);
    }

    // epilogue: add bias, store float2 per fragment half
#pragma unroll
    for (int mi = 0; mi < 4; mi++) {
        int row0 = m0 + wmBase + mi * 16 + (lane >> 2);
#pragma unroll
        for (int ni = 0; ni < 4; ni++) {
            int col = n0 + wnBase + ni * 8 + 2 * (lane & 3);
            float2 bv = *(const float2*)(bias + col);
            float2 o0, o1;
            o0.x = c[mi][ni][0] + bv.x; o0.y = c[mi][ni][1] + bv.y;
            o1.x = c[mi][ni][2] + bv.x; o1.y = c[mi][ni][3] + bv.y;
            *(float2*)(g_pre + (size_t)row0 * NF + col) = o0;
            *(float2*)(g_pre + (size_t)(row0 + 8) * NF + col) = o1;
        }
    }
}

// ---------------- misc small kernels ---------------------------------------
__global__ void init_active_kernel() {
    int f = blockIdx.x * blockDim.x + threadIdx.x;
    if (f < NF) g_active[f] = 0;
}

__global__ void dead_kernel(const long long* __restrict__ steps) {
    int f = blockIdx.x * blockDim.x + threadIdx.x;
    if (f < NF)
        g_dead[f] = (g_active[f] == 0 && (steps[f] + 1) >= (long long)DEADTH) ? 1 : 0;
}

// ---------------- exact per-row top-k via 4-pass radix select --------------
__global__ __launch_bounds__(256)
void topk_kernel(int k, int is_aux, float* __restrict__ coeffs_out) {
    extern __shared__ unsigned sh[];
    unsigned* keys = sh;          // NF entries
    unsigned* hist = sh + NF;     // 256 entries
    __shared__ int s_bin, s_rem, s_cnt, s_pos;

    const int r = blockIdx.x;
    const int tid = threadIdx.x;
    const float* row = g_pre + (size_t)r * NF;

    for (int i = tid; i < NF; i += 256) {
        unsigned u = __float_as_uint(row[i]);
        u = (u & 0x80000000u) ? ~u : (u | 0x80000000u);
        if (is_aux && g_dead[i] == 0) u = 0u;
        keys[i] = u;
    }
    __syncthreads();

    unsigned prefix = 0;
    int remaining = k;
#pragma unroll
    for (int shift = 24; shift >= 0; shift -= 8) {
        hist[tid] = 0;
        __syncthreads();
        unsigned himask = (shift == 24) ? 0u : (0xFFFFFFFFu << (shift + 8));
        for (int i = tid; i < NF; i += 256) {
            unsigned u = keys[i];
            if ((u & himask) == prefix) atomicAdd(&hist[(u >> shift) & 255u], 1u);
        }
        __syncthreads();
        if (tid == 0) {
            int cum = 0, b = 255;
            for (; b > 0; b--) {
                int cnt = (int)hist[b];
                if (cum + cnt >= remaining) break;
                cum += cnt;
            }
            s_bin = b;
            s_rem = remaining - cum;
        }
        __syncthreads();
        prefix |= ((unsigned)s_bin) << shift;
        remaining = s_rem;
        __syncthreads();
    }

    if (tid == 0) { s_cnt = 0; s_pos = 0; }
    __syncthreads();

    const unsigned thr = prefix;
    int* idx_out = is_aux ? g_ax_idx : g_tk_idx;
    float* val_out = is_aux ? g_ax_val : g_tk_val;
    const int stride = is_aux ? KAUX : TOPK;

    for (int i = tid; i < NF; i += 256) {
        unsigned u = keys[i];
        if (u > thr) {
            atomicAdd(&s_cnt, 1);
            unsigned bits = (u & 0x80000000u) ? (u ^ 0x80000000u) : ~u;
            float v = __uint_as_float(bits);
            if (v > 0.f) {
                int p = atomicAdd(&s_pos, 1);
                idx_out[r * stride + p] = i;
                val_out[r * stride + p] = v;
                if (!is_aux) {
                    coeffs_out[(size_t)r * NF + i] = v;
                    g_active[i] = 1;
                }
            }
        }
    }
    __syncthreads();

    if (tid == 0) {
        int need = k - s_cnt;
        if (thr != 0u) {
            for (int i = 0; i < NF && need > 0; i++) {
                if (keys[i] == thr) {
                    need--;
                    unsigned bits = (thr & 0x80000000u) ? (thr ^ 0x80000000u) : ~thr;
                    float v = __uint_as_float(bits);
                    if (v > 0.f) {
                        int p = s_pos++;
                        idx_out[r * stride + p] = i;
                        val_out[r * stride + p] = v;
                        if (!is_aux) {
                            coeffs_out[(size_t)r * NF + i] = v;
                            g_active[i] = 1;
                        }
                    }
                }
            }
        }
        if (is_aux) g_ax_cnt[r] = s_pos; else g_tk_cnt[r] = s_pos;
    }
}

// ---------------- sparse decode + deterministic MSE/aux partials -----------
__global__ __launch_bounds__(256)
void decode_kernel(const float* __restrict__ x, const float* __restrict__ Wd,
                   const float* __restrict__ bd, float* __restrict__ recon) {
    const int r = blockIdx.x, tid = threadIdx.x;
    __shared__ int   sidx[KAUX];
    __shared__ float sval[KAUX];
    __shared__ double sred[256];

    const int cnt = g_tk_cnt[r];
    if (tid < cnt) { sidx[tid] = g_tk_idx[r * TOPK + tid]; sval[tid] = g_tk_val[r * TOPK + tid]; }
    __syncthreads();

    float bdv[8], acc[8];
#pragma unroll
    for (int j = 0; j < 8; j++) { bdv[j] = bd[tid + 256 * j]; acc[j] = bdv[j]; }

    for (int t = 0; t < cnt; t++) {
        const float* wv = Wd + (size_t)sidx[t] * D_INV;
        float v = sval[t];
#pragma unroll
        for (int j = 0; j < 8; j++) acc[j] += v * wv[tid + 256 * j];
    }

    float xr[8];
#pragma unroll
    for (int j = 0; j < 8; j++) xr[j] = x[(size_t)r * D_INV + tid + 256 * j];

    double pm = 0.0;
#pragma unroll
    for (int j = 0; j < 8; j++) {
        recon[(size_t)r * D_INV + tid + 256 * j] = acc[j];
        float e = acc[j] - xr[j];
        pm += (double)e * (double)e;
    }

    __syncthreads();
    const int acnt = g_ax_cnt[r];
    if (tid < acnt) { sidx[tid] = g_ax_idx[r * KAUX + tid]; sval[tid] = g_ax_val[r * KAUX + tid]; }
    __syncthreads();

    float aacc[8];
#pragma unroll
    for (int j = 0; j < 8; j++) aacc[j] = bdv[j];
    for (int t = 0; t < acnt; t++) {
        const float* wv = Wd + (size_t)sidx[t] * D_INV;
        float v = sval[t];
#pragma unroll
        for (int j = 0; j < 8; j++) aacc[j] += v * wv[tid + 256 * j];
    }

    double pa = 0.0;
#pragma unroll
    for (int j = 0; j < 8; j++) {
        float resid = xr[j] - acc[j];
        float e = aacc[j] - resid;
        pa += (double)e * (double)e;
    }

    sred[tid] = pm; __syncthreads();
    for (int s = 128; s > 0; s >>= 1) { if (tid < s) sred[tid] += sred[tid + s]; __syncthreads(); }
    if (tid == 0) g_pmse[r] = sred[0];
    __syncthreads();
    sred[tid] = pa; __syncthreads();
    for (int s = 128; s > 0; s >>= 1) { if (tid < s) sred[tid] += sred[tid + s]; __syncthreads(); }
    if (tid == 0) g_paux[r] = sred[0];
}

__global__ void finalize_kernel(float* __restrict__ scal) {
    __shared__ double sm[256], sa[256];
    const int tid = threadIdx.x;
    double m = 0.0, a = 0.0;
    for (int i = tid; i < B_TOK; i += 256) { m += g_pmse[i]; a += g_paux[i]; }
    sm[tid] = m; sa[tid] = a; __syncthreads();
    for (int s = 128; s > 0; s >>= 1) {
        if (tid < s) { sm[tid] += sm[tid + s]; sa[tid] += sa[tid + s]; }
        __syncthreads();
    }
    if (tid == 0) {
        const double denom = (double)B_TOK * (double)D_INV;
        double mse = sm[0] / denom;
        double aux = sa[0] / denom;
        scal[0] = (float)(mse + aux);
        scal[1] = (float)mse;
        scal[2] = (float)aux;
    }
}

// ---------------- launch ----------------------------------------------------
extern "C" void kernel_launch(void* const* d_in, const int* in_sizes, int n_in,
                              void* d_out, int out_size) {
    const float*     x     = (const float*)d_in[0];
    const float*     We    = (const float*)d_in[1];
    const float*     be    = (const float*)d_in[2];
    const float*     Wd    = (const float*)d_in[3];
    const float*     bd    = (const float*)d_in[4];
    const long long* steps = (const long long*)d_in[5];

    float* out    = (float*)d_out;
    float* recon  = out;                                       // [4096,2048]
    float* coeffs = out + (size_t)B_TOK * D_INV;               // [4096,16384]
    float* scal   = coeffs + (size_t)B_TOK * NF;               // loss, mse, aux

    const size_t topk_smem = (size_t)(NF + 256) * sizeof(unsigned);
    cudaFuncSetAttribute(topk_kernel, cudaFuncAttributeMaxDynamicSharedMemorySize,
                         (int)topk_smem);
    cudaFuncSetAttribute(gemm_mma_kernel, cudaFuncAttributeMaxDynamicSharedMemorySize,
                         GEMM_SMEM);

    // zero coeffs region + active flags
    cudaMemsetAsync(coeffs, 0, (size_t)B_TOK * NF * sizeof(float));
    init_active_kernel<<<(NF + 255) / 256, 256>>>();

    // tf32 hi/lo conversion (A elementwise, B transposed to K-major)
    conv_a_kernel<<<(B_TOK * D_INV / 4 + 255) / 256, 256>>>(x);
    conv_b_kernel<<<dim3(NF / 32, D_INV / 32), 256>>>(We);

    // tensor-core encoder GEMM -> g_pre (3xTF32 emulation via mma.sync)
    gemm_mma_kernel<<<dim3(B_TOK / TM, NF / TN), 256, GEMM_SMEM>>>(be);

    // main top-32 (writes coeffs, lists, active flags)
    topk_kernel<<<B_TOK, 256, topk_smem>>>(TOPK, 0, coeffs);

    // dead mask
    dead_kernel<<<(NF + 255) / 256, 256>>>(steps);

    // aux top-256 over dead features
    topk_kernel<<<B_TOK, 256, topk_smem>>>(KAUX, 1, nullptr);

    // sparse decode + partial sums
    decode_kernel<<<B_TOK, 256>>>(x, Wd, bd, recon);

    // deterministic final reduction + scalars
    finalize_kernel<<<1, 256>>>(scal);
}

// round 5
// speedup vs baseline: 2.8529x; 2.7076x over previous
#include <cuda_runtime.h>
#include <cuda_bf16.h>
#include <cstdint>

#define B_TOK 4096
#define D_INV 2048
#define NF    16384
#define TOPK  32
#define KAUX  256
#define DEADTH 100

// GEMM tiling
#define TM 128
#define TN 128
#define BK 32
#define NIT (D_INV / BK)          // 64
#define STAGE_U32 8192            // 4 planes x 2048 u32 (32KB)
#define GEMM_SMEM (4 * STAGE_U32 * 4)   // 131072 bytes, 4 stages

#define CAND_MAX 256

// ---------------- scratch (device globals; no allocation allowed) ----------
__device__ float    g_pre[(size_t)B_TOK * NF];        // 256 MB
__device__ uint32_t g_Ahi16u[(size_t)B_TOK * D_INV / 2];   // bf16 pairs
__device__ uint32_t g_Alo16u[(size_t)B_TOK * D_INV / 2];
__device__ uint32_t g_Bhi16u[(size_t)NF * D_INV / 2];      // transposed [NF][D/2]
__device__ uint32_t g_Blo16u[(size_t)NF * D_INV / 2];
__device__ int    g_tk_idx[B_TOK * TOPK];
__device__ float  g_tk_val[B_TOK * TOPK];
__device__ int    g_tk_cnt[B_TOK];
__device__ int    g_ax_idx[B_TOK * KAUX];
__device__ float  g_ax_val[B_TOK * KAUX];
__device__ int    g_ax_cnt[B_TOK];
__device__ int    g_active[NF];
__device__ int    g_dead[NF];
__device__ double g_pmse[B_TOK];
__device__ double g_paux[B_TOK];

// ---------------- helpers ----------------------------------------------------
__device__ __forceinline__ uint32_t smem_u32(const void* p) {
    uint32_t a;
    asm("{ .reg .u64 t; cvta.to.shared.u64 t, %1; cvt.u32.u64 %0, t; }"
        : "=r"(a) : "l"(p));
    return a;
}
__device__ __forceinline__ void cpa16(uint32_t dst, const void* src) {
    asm volatile("cp.async.cg.shared.global [%0], [%1], 16;" :: "r"(dst), "l"(src));
}
__device__ __forceinline__ uint32_t pkbf(__nv_bfloat16 a, __nv_bfloat16 b) {
    __nv_bfloat162 t = __halves2bfloat162(a, b);
    return *reinterpret_cast<uint32_t*>(&t);
}
__device__ __forceinline__ unsigned f2k(float v) {
    unsigned u = __float_as_uint(v);
    return (u & 0x80000000u) ? ~u : (u | 0x80000000u);
}
__device__ __forceinline__ float k2f(unsigned u) {
    unsigned b = (u & 0x80000000u) ? (u ^ 0x80000000u) : ~u;
    return __uint_as_float(b);
}
// swizzled smem index within a plane: 128 rows x 16 u32, 16B-granule XOR
__device__ __forceinline__ int sidx(int r, int j) {
    return r * 16 + ((((j >> 2) ^ ((r >> 1) & 3)) << 2) | (j & 3));
}

#define MMA_BF16(C, A, B) \
    asm volatile("mma.sync.aligned.m16n8k16.row.col.f32.bf16.bf16.f32 " \
        "{%0,%1,%2,%3}, {%4,%5,%6,%7}, {%8,%9}, {%0,%1,%2,%3};" \
        : "+f"((C)[0]), "+f"((C)[1]), "+f"((C)[2]), "+f"((C)[3]) \
        : "r"((A)[0]), "r"((A)[1]), "r"((A)[2]), "r"((A)[3]), \
          "r"((B)[0]), "r"((B)[1]))

// ---------------- convert pre-pass (bf16 hi/lo split) -----------------------
__global__ __launch_bounds__(256) void conv_a_kernel(const float* __restrict__ A) {
    size_t i = (size_t)blockIdx.x * 256 + threadIdx.x;   // float4 index
    const float4 v = ((const float4*)A)[i];
    __nv_bfloat16 hx = __float2bfloat16_rn(v.x), hy = __float2bfloat16_rn(v.y);
    __nv_bfloat16 hz = __float2bfloat16_rn(v.z), hw = __float2bfloat16_rn(v.w);
    __nv_bfloat16 lx = __float2bfloat16_rn(v.x - __bfloat162float(hx));
    __nv_bfloat16 ly = __float2bfloat16_rn(v.y - __bfloat162float(hy));
    __nv_bfloat16 lz = __float2bfloat16_rn(v.z - __bfloat162float(hz));
    __nv_bfloat16 lw = __float2bfloat16_rn(v.w - __bfloat162float(hw));
    ((uint2*)g_Ahi16u)[i] = make_uint2(pkbf(hx, hy), pkbf(hz, hw));
    ((uint2*)g_Alo16u)[i] = make_uint2(pkbf(lx, ly), pkbf(lz, lw));
}

// B [D_INV][NF] -> [NF][D_INV/2] bf16-pair planes via 32x32 smem transpose
__global__ __launch_bounds__(256) void conv_b_kernel(const float* __restrict__ B) {
    __shared__ float sh[32][33];
    const int n0 = blockIdx.x * 32;
    const int k0 = blockIdx.y * 32;
    const int tx = threadIdx.x & 31, ty = threadIdx.x >> 5;
#pragma unroll
    for (int q = 0; q < 4; q++) {
        int k = ty + q * 8;
        sh[k][tx] = B[(size_t)(k0 + k) * NF + n0 + tx];
    }
    __syncthreads();
#pragma unroll
    for (int q = 0; q < 2; q++) {
        int idx = threadIdx.x + q * 256;   // 0..511
        int n = idx & 31, kp = idx >> 5;   // kp 0..15
        float v0 = sh[kp * 2][n], v1 = sh[kp * 2 + 1][n];
        __nv_bfloat16 h0 = __float2bfloat16_rn(v0), h1 = __float2bfloat16_rn(v1);
        __nv_bfloat16 l0 = __float2bfloat16_rn(v0 - __bfloat162float(h0));
        __nv_bfloat16 l1 = __float2bfloat16_rn(v1 - __bfloat162float(h1));
        size_t o = (size_t)(n0 + n) * (D_INV / 2) + (k0 >> 1) + kp;
        g_Bhi16u[o] = pkbf(h0, h1);
        g_Blo16u[o] = pkbf(l0, l1);
    }
}

// ---------------- bf16 3-term mma.sync GEMM: g_pre = x @ W_enc + b_enc ------
// 128x128 tile, BK=32, 512 threads (16 warps, 32x32 warp tiles), 4-stage pipe.
__global__ __launch_bounds__(512, 1)
void gemm_bf16_kernel(const float* __restrict__ bias) {
    extern __shared__ uint32_t smw[];   // 4 stages x 8192 u32
    const int tid = threadIdx.x;
    const int w = tid >> 5, lane = tid & 31;
    const int m0 = blockIdx.x * TM;
    const int n0 = blockIdx.y * TN;
    const int wm = (w & 3) * 32;
    const int wn = (w >> 2) * 32;
    const int lr = lane >> 2, lc = lane & 3;

    float c[2][4][4];
#pragma unroll
    for (int mi = 0; mi < 2; mi++)
#pragma unroll
        for (int ni = 0; ni < 4; ni++)
#pragma unroll
            for (int j = 0; j < 4; j++) c[mi][ni][j] = 0.f;

    auto loadStage = [&](int s, int kt) {
        uint32_t* st = smw + s * STAGE_U32;
        const int ktu = kt >> 1;
#pragma unroll
        for (int q = 0; q < 4; q++) {
            int t = tid + q * 512;            // 0..2047
            int isB = t >> 10, tb = t & 1023;
            int pl = tb >> 9, rem = tb & 511;
            int row = rem >> 2, ch = rem & 3;
            const uint32_t* base = isB ? (pl ? g_Blo16u : g_Bhi16u)
                                       : (pl ? g_Alo16u : g_Ahi16u);
            const uint32_t* src = base +
                (size_t)((isB ? n0 : m0) + row) * (D_INV / 2) + ktu + ch * 4;
            uint32_t* dst = st + (isB * 2 + pl) * 2048 + row * 16 +
                            ((ch ^ ((row >> 1) & 3)) << 2);
            cpa16(smem_u32(dst), src);
        }
    };

    loadStage(0, 0);
    asm volatile("cp.async.commit_group;");
    loadStage(1, BK);
    asm volatile("cp.async.commit_group;");
    loadStage(2, 2 * BK);
    asm volatile("cp.async.commit_group;");

    for (int i = 0; i < NIT; i++) {
        asm volatile("cp.async.wait_group 2;" ::: "memory");
        __syncthreads();

        const uint32_t* Ah = smw + (i & 3) * STAGE_U32;
        const uint32_t* Al = Ah + 2048;
        const uint32_t* Bh = Ah + 4096;
        const uint32_t* Bl = Ah + 6144;

#pragma unroll
        for (int ks = 0; ks < 2; ks++) {
            const int jb = ks * 8 + lc;
            uint32_t ah[2][4], al[2][4], bh[4][2], bl[4][2];
#pragma unroll
            for (int mi = 0; mi < 2; mi++) {
                int r = wm + mi * 16 + lr;
                ah[mi][0] = Ah[sidx(r, jb)];
                ah[mi][1] = Ah[sidx(r + 8, jb)];
                ah[mi][2] = Ah[sidx(r, jb + 4)];
                ah[mi][3] = Ah[sidx(r + 8, jb + 4)];
                al[mi][0] = Al[sidx(r, jb)];
                al[mi][1] = Al[sidx(r + 8, jb)];
                al[mi][2] = Al[sidx(r, jb + 4)];
                al[mi][3] = Al[sidx(r + 8, jb + 4)];
            }
#pragma unroll
            for (int ni = 0; ni < 4; ni++) {
                int n = wn + ni * 8 + lr;
                bh[ni][0] = Bh[sidx(n, jb)];
                bh[ni][1] = Bh[sidx(n, jb + 4)];
                bl[ni][0] = Bl[sidx(n, jb)];
                bl[ni][1] = Bl[sidx(n, jb + 4)];
            }
#pragma unroll
            for (int mi = 0; mi < 2; mi++)
#pragma unroll
                for (int ni = 0; ni < 4; ni++) {
                    MMA_BF16(c[mi][ni], ah[mi], bh[ni]);
                    MMA_BF16(c[mi][ni], ah[mi], bl[ni]);
                    MMA_BF16(c[mi][ni], al[mi], bh[ni]);
                }
        }
        if (i + 3 < NIT) loadStage((i + 3) & 3, (i + 3) * BK);
        asm volatile("cp.async.commit_group;");
    }

    // epilogue: add bias, store
#pragma unroll
    for (int mi = 0; mi < 2; mi++) {
        int row = m0 + wm + mi * 16 + lr;
#pragma unroll
        for (int ni = 0; ni < 4; ni++) {
            int col = n0 + wn + ni * 8 + lc * 2;
            float2 bv = *(const float2*)(bias + col);
            float2 o0, o1;
            o0.x = c[mi][ni][0] + bv.x; o0.y = c[mi][ni][1] + bv.y;
            o1.x = c[mi][ni][2] + bv.x; o1.y = c[mi][ni][3] + bv.y;
            *(float2*)(g_pre + (size_t)row * NF + col) = o0;
            *(float2*)(g_pre + (size_t)(row + 8) * NF + col) = o1;
        }
    }
}

// ---------------- misc small kernels ---------------------------------------
__global__ void init_active_kernel() {
    int f = blockIdx.x * blockDim.x + threadIdx.x;
    if (f < NF) g_active[f] = 0;
}

__global__ void dead_kernel(const long long* __restrict__ steps) {
    int f = blockIdx.x * blockDim.x + threadIdx.x;
    if (f < NF)
        g_dead[f] = (g_active[f] == 0 && (steps[f] + 1) >= (long long)DEADTH) ? 1 : 0;
}

// ---------------- exact per-row top-k via 4-pass radix select ---------------
// main (is_aux=0): band refinement around the approx 32nd value; borderline
// candidates are recomputed EXACTLY from the original fp32 x and W_enc.
__global__ __launch_bounds__(256)
void topk_kernel(int k, int is_aux, float* __restrict__ coeffs_out,
                 const float* __restrict__ xin, const float* __restrict__ Wenc,
                 const float* __restrict__ be) {
    extern __shared__ unsigned sh[];
    unsigned* keys = sh;                               // NF
    unsigned* hist = sh + NF;                          // 256
    int*      cand_idx = (int*)(hist + 256);           // 256
    unsigned* cand_key = (unsigned*)(cand_idx + 256);  // 256
    float*    exv = (float*)(cand_key + 256);          // 256
    double*   redd = (double*)(exv + 256);             // 256 doubles
    __shared__ int s_bin, s_rem, s_cnt, s_pos, s_nhi, s_nc;

    const int r = blockIdx.x;
    const int tid = threadIdx.x;
    const float* row = g_pre + (size_t)r * NF;

    for (int i = tid; i < NF; i += 256) {
        unsigned u = f2k(row[i]);
        if (is_aux && g_dead[i] == 0) u = 0u;
        keys[i] = u;
    }
    __syncthreads();

    unsigned prefix = 0;
    int remaining = k;
#pragma unroll
    for (int shift = 24; shift >= 0; shift -= 8) {
        hist[tid] = 0;
        __syncthreads();
        unsigned himask = (shift == 24) ? 0u : (0xFFFFFFFFu << (shift + 8));
        for (int i = tid; i < NF; i += 256) {
            unsigned u = keys[i];
            if ((u & himask) == prefix) atomicAdd(&hist[(u >> shift) & 255u], 1u);
        }
        __syncthreads();
        if (tid == 0) {
            int cum = 0, b = 255;
            for (; b > 0; b--) {
                int cnt = (int)hist[b];
                if (cum + cnt >= remaining) break;
                cum += cnt;
            }
            s_bin = b;
            s_rem = remaining - cum;
        }
        __syncthreads();
        prefix |= ((unsigned)s_bin) << shift;
        remaining = s_rem;
        __syncthreads();
    }
    const unsigned thr = prefix;

    if (tid == 0) { s_cnt = 0; s_pos = 0; s_nhi = 0; s_nc = 0; }
    __syncthreads();

    if (!is_aux) {
        // -------- main top-32 with band refinement --------
        const float DELTA = 1e-4f;
        const float v32 = k2f(thr);
        const unsigned khi = f2k(v32 + DELTA);
        const unsigned klo = f2k(v32 - DELTA);

        for (int i = tid; i < NF; i += 256) {
            unsigned u = keys[i];
            if (u > khi) {
                atomicAdd(&s_nhi, 1);
                float v = k2f(u);
                if (v > 0.f) {
                    int p = atomicAdd(&s_pos, 1);
                    g_tk_idx[r * TOPK + p] = i;
                    g_tk_val[r * TOPK + p] = v;
                    coeffs_out[(size_t)r * NF + i] = v;
                    g_active[i] = 1;
                }
            } else if (u >= klo) {
                int p = atomicAdd(&s_nc, 1);
                if (p < CAND_MAX) { cand_idx[p] = i; cand_key[p] = u; }
            }
        }
        __syncthreads();

        const int need = TOPK - s_nhi;
        const int nc = (s_nc < CAND_MAX) ? s_nc : CAND_MAX;

        auto sel_write = [&](int i, float v) {
            if (v > 0.f) {
                int p = atomicAdd(&s_pos, 1);
                g_tk_idx[r * TOPK + p] = i;
                g_tk_val[r * TOPK + p] = v;
                coeffs_out[(size_t)r * NF + i] = v;
                g_active[i] = 1;
            }
        };

        if (nc == need) {
            // fast path: whole band selected (typical: band = {v32}, need = 1)
            if (tid < nc) sel_write(cand_idx[tid], k2f(cand_key[tid]));
        } else {
            // rare: EXACT recompute of candidates from fp32 x / W_enc
            const float* xr = xin + (size_t)r * D_INV;
            for (int t = 0; t < nc; t++) {
                const float* Wc = Wenc + cand_idx[t];
                double part = 0.0;
#pragma unroll
                for (int q = 0; q < 8; q++) {
                    int p = tid + q * 256;
                    part += (double)xr[p] * (double)Wc[(size_t)p * NF];
                }
                redd[tid] = part; __syncthreads();
                for (int s = 128; s > 0; s >>= 1) {
                    if (tid < s) redd[tid] += redd[tid + s];
                    __syncthreads();
                }
                if (tid == 0) exv[t] = (float)(redd[0] + (double)be[cand_idx[t]]);
                __syncthreads();
            }
            if (tid < nc) {
                float mv = exv[tid];
                int mi = cand_idx[tid];
                int rank = 0;
                for (int u = 0; u < nc; u++) {
                    if (exv[u] > mv || (exv[u] == mv && cand_idx[u] < mi)) rank++;
                }
                if (rank < need) sel_write(mi, mv);
            }
        }
        __syncthreads();
        if (tid == 0) g_tk_cnt[r] = s_pos;
    } else {
        // -------- aux top-256: approx selection (flip impact negligible) ----
        for (int i = tid; i < NF; i += 256) {
            unsigned u = keys[i];
            if (u > thr) {
                atomicAdd(&s_cnt, 1);
                float v = k2f(u);
                if (v > 0.f) {
                    int p = atomicAdd(&s_pos, 1);
                    g_ax_idx[r * KAUX + p] = i;
                    g_ax_val[r * KAUX + p] = v;
                }
            }
        }
        __syncthreads();
        if (tid == 0) {
            int need = k - s_cnt;
            if (thr != 0u) {
                for (int i = 0; i < NF && need > 0; i++) {
                    if (keys[i] == thr) {
                        need--;
                        float v = k2f(thr);
                        if (v > 0.f) {
                            int p = s_pos++;
                            g_ax_idx[r * KAUX + p] = i;
                            g_ax_val[r * KAUX + p] = v;
                        }
                    }
                }
            }
            g_ax_cnt[r] = s_pos;
        }
    }
}

// ---------------- sparse decode + deterministic MSE/aux partials -----------
__global__ __launch_bounds__(256)
void decode_kernel(const float* __restrict__ x, const float* __restrict__ Wd,
                   const float* __restrict__ bd, float* __restrict__ recon) {
    const int r = blockIdx.x, tid = threadIdx.x;
    __shared__ int   sidx_[KAUX];
    __shared__ float sval[KAUX];
    __shared__ double sred[256];

    const int cnt = g_tk_cnt[r];
    if (tid < cnt) { sidx_[tid] = g_tk_idx[r * TOPK + tid]; sval[tid] = g_tk_val[r * TOPK + tid]; }
    __syncthreads();

    float bdv[8], acc[8];
#pragma unroll
    for (int j = 0; j < 8; j++) { bdv[j] = bd[tid + 256 * j]; acc[j] = bdv[j]; }

    for (int t = 0; t < cnt; t++) {
        const float* wv = Wd + (size_t)sidx_[t] * D_INV;
        float v = sval[t];
#pragma unroll
        for (int j = 0; j < 8; j++) acc[j] += v * wv[tid + 256 * j];
    }

    float xr[8];
#pragma unroll
    for (int j = 0; j < 8; j++) xr[j] = x[(size_t)r * D_INV + tid + 256 * j];

    double pm = 0.0;
#pragma unroll
    for (int j = 0; j < 8; j++) {
        recon[(size_t)r * D_INV + tid + 256 * j] = acc[j];
        float e = acc[j] - xr[j];
        pm += (double)e * (double)e;
    }

    __syncthreads();
    const int acnt = g_ax_cnt[r];
    if (tid < acnt) { sidx_[tid] = g_ax_idx[r * KAUX + tid]; sval[tid] = g_ax_val[r * KAUX + tid]; }
    __syncthreads();

    float aacc[8];
#pragma unroll
    for (int j = 0; j < 8; j++) aacc[j] = bdv[j];
    for (int t = 0; t < acnt; t++) {
        const float* wv = Wd + (size_t)sidx_[t] * D_INV;
        float v = sval[t];
#pragma unroll
        for (int j = 0; j < 8; j++) aacc[j] += v * wv[tid + 256 * j];
    }

    double pa = 0.0;
#pragma unroll
    for (int j = 0; j < 8; j++) {
        float resid = xr[j] - acc[j];
        float e = aacc[j] - resid;
        pa += (double)e * (double)e;
    }

    sred[tid] = pm; __syncthreads();
    for (int s = 128; s > 0; s >>= 1) { if (tid < s) sred[tid] += sred[tid + s]; __syncthreads(); }
    if (tid == 0) g_pmse[r] = sred[0];
    __syncthreads();
    sred[tid] = pa; __syncthreads();
    for (int s = 128; s > 0; s >>= 1) { if (tid < s) sred[tid] += sred[tid + s]; __syncthreads(); }
    if (tid == 0) g_paux[r] = sred[0];
}

__global__ void finalize_kernel(float* __restrict__ scal) {
    __shared__ double sm[256], sa[256];
    const int tid = threadIdx.x;
    double m = 0.0, a = 0.0;
    for (int i = tid; i < B_TOK; i += 256) { m += g_pmse[i]; a += g_paux[i]; }
    sm[tid] = m; sa[tid] = a; __syncthreads();
    for (int s = 128; s > 0; s >>= 1) {
        if (tid < s) { sm[tid] += sm[tid + s]; sa[tid] += sa[tid + s]; }
        __syncthreads();
    }
    if (tid == 0) {
        const double denom = (double)B_TOK * (double)D_INV;
        double mse = sm[0] / denom;
        double aux = sa[0] / denom;
        scal[0] = (float)(mse + aux);
        scal[1] = (float)mse;
        scal[2] = (float)aux;
    }
}

// ---------------- launch ----------------------------------------------------
extern "C" void kernel_launch(void* const* d_in, const int* in_sizes, int n_in,
                              void* d_out, int out_size) {
    const float*     x     = (const float*)d_in[0];
    const float*     We    = (const float*)d_in[1];
    const float*     be    = (const float*)d_in[2];
    const float*     Wd    = (const float*)d_in[3];
    const float*     bd    = (const float*)d_in[4];
    const long long* steps = (const long long*)d_in[5];

    float* out    = (float*)d_out;
    float* recon  = out;                                       // [4096,2048]
    float* coeffs = out + (size_t)B_TOK * D_INV;               // [4096,16384]
    float* scal   = coeffs + (size_t)B_TOK * NF;               // loss, mse, aux

    const size_t topk_smem = (size_t)(NF + 4 * 256) * 4 + 256 * 8;  // 71680 B
    cudaFuncSetAttribute(topk_kernel, cudaFuncAttributeMaxDynamicSharedMemorySize,
                         (int)topk_smem);
    cudaFuncSetAttribute(gemm_bf16_kernel, cudaFuncAttributeMaxDynamicSharedMemorySize,
                         GEMM_SMEM);

    // zero coeffs region + active flags
    cudaMemsetAsync(coeffs, 0, (size_t)B_TOK * NF * sizeof(float));
    init_active_kernel<<<(NF + 255) / 256, 256>>>();

    // bf16 hi/lo conversion (A elementwise, B transposed to K-major)
    conv_a_kernel<<<(B_TOK * D_INV / 4) / 256, 256>>>(x);
    conv_b_kernel<<<dim3(NF / 32, D_INV / 32), 256>>>(We);

    // tensor-core encoder GEMM -> g_pre (3-term bf16 split via mma.sync)
    gemm_bf16_kernel<<<dim3(B_TOK / TM, NF / TN), 512, GEMM_SMEM>>>(be);

    // main top-32 (band-refined; exact fp32 recompute for borderline)
    topk_kernel<<<B_TOK, 256, topk_smem>>>(TOPK, 0, coeffs, x, We, be);

    // dead mask
    dead_kernel<<<(NF + 255) / 256, 256>>>(steps);

    // aux top-256 over dead features
    topk_kernel<<<B_TOK, 256, topk_smem>>>(KAUX, 1, nullptr, x, We, be);

    // sparse decode + partial sums
    decode_kernel<<<B_TOK, 256>>>(x, Wd, bd, recon);

    // deterministic final reduction + scalars
    finalize_kernel<<<1, 256>>>(scal);
}

// round 6
// speedup vs baseline: 3.0678x; 1.0753x over previous
#include <cuda_runtime.h>
#include <cuda_bf16.h>
#include <cstdint>

#define B_TOK 4096
#define D_INV 2048
#define NF    16384
#define TOPK  32
#define KAUX  256
#define DEADTH 100

// GEMM tiling
#define TM 128
#define TN 128
#define BK 32
#define NIT (D_INV / BK)          // 64
#define STAGE_U32 8192            // 4 planes x 2048 u32 (32KB)
#define GEMM_SMEM (4 * STAGE_U32 * 4)   // 131072 bytes, 4 stages

#define CAND_MAX 256

// ---------------- scratch (device globals; no allocation allowed) ----------
__device__ float    g_pre[(size_t)B_TOK * NF];        // 256 MB
__device__ uint32_t g_Ahi16u[(size_t)B_TOK * D_INV / 2];   // bf16 pairs
__device__ uint32_t g_Alo16u[(size_t)B_TOK * D_INV / 2];
__device__ uint32_t g_Bhi16u[(size_t)NF * D_INV / 2];      // transposed [NF][D/2]
__device__ uint32_t g_Blo16u[(size_t)NF * D_INV / 2];
__device__ uint32_t g_Wd16u[(size_t)NF * D_INV / 2];       // bf16 W_dec (aux only)
__device__ int    g_tk_idx[B_TOK * TOPK];
__device__ float  g_tk_val[B_TOK * TOPK];
__device__ int    g_tk_cnt[B_TOK];
__device__ int    g_ax_idx[B_TOK * KAUX];
__device__ float  g_ax_val[B_TOK * KAUX];
__device__ int    g_ax_cnt[B_TOK];
__device__ int    g_active[NF];
__device__ int    g_dead[NF];
__device__ double g_pmse[B_TOK];
__device__ double g_paux[B_TOK];

// ---------------- helpers ----------------------------------------------------
__device__ __forceinline__ uint32_t smem_u32(const void* p) {
    uint32_t a;
    asm("{ .reg .u64 t; cvta.to.shared.u64 t, %1; cvt.u32.u64 %0, t; }"
        : "=r"(a) : "l"(p));
    return a;
}
__device__ __forceinline__ void cpa16(uint32_t dst, const void* src) {
    asm volatile("cp.async.cg.shared.global [%0], [%1], 16;" :: "r"(dst), "l"(src));
}
__device__ __forceinline__ uint32_t pkbf(__nv_bfloat16 a, __nv_bfloat16 b) {
    __nv_bfloat162 t = __halves2bfloat162(a, b);
    return *reinterpret_cast<uint32_t*>(&t);
}
__device__ __forceinline__ float2 upbf(uint32_t u) {
    __nv_bfloat162 t = *reinterpret_cast<__nv_bfloat162*>(&u);
    return __bfloat1622float2(t);
}
__device__ __forceinline__ unsigned f2k(float v) {
    unsigned u = __float_as_uint(v);
    return (u & 0x80000000u) ? ~u : (u | 0x80000000u);
}
__device__ __forceinline__ float k2f(unsigned u) {
    unsigned b = (u & 0x80000000u) ? (u ^ 0x80000000u) : ~u;
    return __uint_as_float(b);
}

#define MMA_BF16(C, A, B) \
    asm volatile("mma.sync.aligned.m16n8k16.row.col.f32.bf16.bf16.f32 " \
        "{%0,%1,%2,%3}, {%4,%5,%6,%7}, {%8,%9}, {%0,%1,%2,%3};" \
        : "+f"((C)[0]), "+f"((C)[1]), "+f"((C)[2]), "+f"((C)[3]) \
        : "r"((A)[0]), "r"((A)[1]), "r"((A)[2]), "r"((A)[3]), \
          "r"((B)[0]), "r"((B)[1]))

#define LDSM4(R0, R1, R2, R3, ADDR) \
    asm volatile("ldmatrix.sync.aligned.m8n8.x4.shared.b16 {%0,%1,%2,%3}, [%4];" \
        : "=r"(R0), "=r"(R1), "=r"(R2), "=r"(R3) : "r"(ADDR))

// ---------------- convert pre-pass (bf16 hi/lo split) -----------------------
__global__ __launch_bounds__(256) void conv_a_kernel(const float* __restrict__ A) {
    size_t i = (size_t)blockIdx.x * 256 + threadIdx.x;   // float4 index
    const float4 v = ((const float4*)A)[i];
    __nv_bfloat16 hx = __float2bfloat16_rn(v.x), hy = __float2bfloat16_rn(v.y);
    __nv_bfloat16 hz = __float2bfloat16_rn(v.z), hw = __float2bfloat16_rn(v.w);
    __nv_bfloat16 lx = __float2bfloat16_rn(v.x - __bfloat162float(hx));
    __nv_bfloat16 ly = __float2bfloat16_rn(v.y - __bfloat162float(hy));
    __nv_bfloat16 lz = __float2bfloat16_rn(v.z - __bfloat162float(hz));
    __nv_bfloat16 lw = __float2bfloat16_rn(v.w - __bfloat162float(hw));
    ((uint2*)g_Ahi16u)[i] = make_uint2(pkbf(hx, hy), pkbf(hz, hw));
    ((uint2*)g_Alo16u)[i] = make_uint2(pkbf(lx, ly), pkbf(lz, lw));
}

// W_dec [NF][D_INV] -> single bf16 plane (aux decode only)
__global__ __launch_bounds__(256) void conv_wd_kernel(const float* __restrict__ Wd) {
    size_t i = (size_t)blockIdx.x * 256 + threadIdx.x;   // float4 index
    const float4 v = ((const float4*)Wd)[i];
    uint2 o;
    o.x = pkbf(__float2bfloat16_rn(v.x), __float2bfloat16_rn(v.y));
    o.y = pkbf(__float2bfloat16_rn(v.z), __float2bfloat16_rn(v.w));
    ((uint2*)g_Wd16u)[i] = o;
}

// B [D_INV][NF] -> [NF][D_INV/2] bf16-pair planes via 32x32 smem transpose
__global__ __launch_bounds__(256) void conv_b_kernel(const float* __restrict__ B) {
    __shared__ float sh[32][33];
    const int n0 = blockIdx.x * 32;
    const int k0 = blockIdx.y * 32;
    const int tx = threadIdx.x & 31, ty = threadIdx.x >> 5;
#pragma unroll
    for (int q = 0; q < 4; q++) {
        int k = ty + q * 8;
        sh[k][tx] = B[(size_t)(k0 + k) * NF + n0 + tx];
    }
    __syncthreads();
#pragma unroll
    for (int q = 0; q < 2; q++) {
        int idx = threadIdx.x + q * 256;   // 0..511
        int n = idx & 31, kp = idx >> 5;   // kp 0..15
        float v0 = sh[kp * 2][n], v1 = sh[kp * 2 + 1][n];
        __nv_bfloat16 h0 = __float2bfloat16_rn(v0), h1 = __float2bfloat16_rn(v1);
        __nv_bfloat16 l0 = __float2bfloat16_rn(v0 - __bfloat162float(h0));
        __nv_bfloat16 l1 = __float2bfloat16_rn(v1 - __bfloat162float(h1));
        size_t o = (size_t)(n0 + n) * (D_INV / 2) + (k0 >> 1) + kp;
        g_Bhi16u[o] = pkbf(h0, h1);
        g_Blo16u[o] = pkbf(l0, l1);
    }
}

// ---------------- bf16 3-term mma.sync GEMM: g_pre = x @ W_enc + b_enc ------
// 128x128 tile, BK=32, 512 threads, 4-stage cp.async pipe, ldmatrix fragments.
__global__ __launch_bounds__(512, 1)
void gemm_bf16_kernel(const float* __restrict__ bias) {
    extern __shared__ uint32_t smw[];   // 4 stages x 8192 u32
    const int tid = threadIdx.x;
    const int w = tid >> 5, lane = tid & 31;
    const int m0 = blockIdx.x * TM;
    const int n0 = blockIdx.y * TN;
    const int wm = (w & 3) * 32;
    const int wn = (w >> 2) * 32;
    const int lr = lane >> 2, lc = lane & 3;
    const uint32_t smbase = smem_u32(smw);

    float c[2][4][4];
#pragma unroll
    for (int mi = 0; mi < 2; mi++)
#pragma unroll
        for (int ni = 0; ni < 4; ni++)
#pragma unroll
            for (int j = 0; j < 4; j++) c[mi][ni][j] = 0.f;

    auto loadStage = [&](int s, int kt) {
        uint32_t* st = smw + s * STAGE_U32;
        const int ktu = kt >> 1;
#pragma unroll
        for (int q = 0; q < 4; q++) {
            int t = tid + q * 512;            // 0..2047
            int isB = t >> 10, tb = t & 1023;
            int pl = tb >> 9, rem = tb & 511;
            int row = rem >> 2, ch = rem & 3;
            const uint32_t* base = isB ? (pl ? g_Blo16u : g_Bhi16u)
                                       : (pl ? g_Alo16u : g_Ahi16u);
            const uint32_t* src = base +
                (size_t)((isB ? n0 : m0) + row) * (D_INV / 2) + ktu + ch * 4;
            uint32_t* dst = st + (isB * 2 + pl) * 2048 + row * 16 +
                            ((ch ^ ((row >> 1) & 3)) << 2);
            cpa16(smem_u32(dst), src);
        }
    };

    loadStage(0, 0);
    asm volatile("cp.async.commit_group;");
    loadStage(1, BK);
    asm volatile("cp.async.commit_group;");
    loadStage(2, 2 * BK);
    asm volatile("cp.async.commit_group;");

    // lane-derived ldmatrix address components (constant per thread)
    const int a_rowadd = ((lane >> 3) & 1) * 8 + (lane & 7);   // + chunk add lane>>4
    const int a_chadd  = lane >> 4;
    const int b_rowadd = (lane >> 4) * 8 + (lane & 7);
    const int b_chadd  = (lane >> 3) & 1;

    for (int i = 0; i < NIT; i++) {
        asm volatile("cp.async.wait_group 2;" ::: "memory");
        __syncthreads();

        const uint32_t sb = smbase + (i & 3) * (STAGE_U32 * 4);  // byte base

#pragma unroll
        for (int ks = 0; ks < 2; ks++) {
            const int c0 = 2 * ks;
            uint32_t ah[2][4], al[2][4], bh[4][2], bl[4][2];
#pragma unroll
            for (int mi = 0; mi < 2; mi++) {
                int R = wm + mi * 16 + a_rowadd;
                int ch = c0 + a_chadd;
                uint32_t off = (uint32_t)(R * 16 + ((ch ^ ((R >> 1) & 3)) << 2)) * 4;
                LDSM4(ah[mi][0], ah[mi][1], ah[mi][2], ah[mi][3], sb + off);
                LDSM4(al[mi][0], al[mi][1], al[mi][2], al[mi][3], sb + 8192 + off);
            }
#pragma unroll
            for (int nip = 0; nip < 2; nip++) {
                int N = wn + nip * 16 + b_rowadd;
                int ch = c0 + b_chadd;
                uint32_t off = (uint32_t)(N * 16 + ((ch ^ ((N >> 1) & 3)) << 2)) * 4;
                LDSM4(bh[2 * nip][0], bh[2 * nip][1],
                      bh[2 * nip + 1][0], bh[2 * nip + 1][1], sb + 16384 + off);
                LDSM4(bl[2 * nip][0], bl[2 * nip][1],
                      bl[2 * nip + 1][0], bl[2 * nip + 1][1], sb + 24576 + off);
            }
#pragma unroll
            for (int mi = 0; mi < 2; mi++)
#pragma unroll
                for (int ni = 0; ni < 4; ni++) {
                    MMA_BF16(c[mi][ni], ah[mi], bh[ni]);
                    MMA_BF16(c[mi][ni], ah[mi], bl[ni]);
                    MMA_BF16(c[mi][ni], al[mi], bh[ni]);
                }
        }
        if (i + 3 < NIT) loadStage((i + 3) & 3, (i + 3) * BK);
        asm volatile("cp.async.commit_group;");
    }

    // epilogue: add bias, store
#pragma unroll
    for (int mi = 0; mi < 2; mi++) {
        int row = m0 + wm + mi * 16 + lr;
#pragma unroll
        for (int ni = 0; ni < 4; ni++) {
            int col = n0 + wn + ni * 8 + lc * 2;
            float2 bv = *(const float2*)(bias + col);
            float2 o0, o1;
            o0.x = c[mi][ni][0] + bv.x; o0.y = c[mi][ni][1] + bv.y;
            o1.x = c[mi][ni][2] + bv.x; o1.y = c[mi][ni][3] + bv.y;
            *(float2*)(g_pre + (size_t)row * NF + col) = o0;
            *(float2*)(g_pre + (size_t)(row + 8) * NF + col) = o1;
        }
    }
}

// ---------------- misc small kernels ---------------------------------------
__global__ void init_active_kernel() {
    int f = blockIdx.x * blockDim.x + threadIdx.x;
    if (f < NF) g_active[f] = 0;
}

__global__ void dead_kernel(const long long* __restrict__ steps) {
    int f = blockIdx.x * blockDim.x + threadIdx.x;
    if (f < NF)
        g_dead[f] = (g_active[f] == 0 && (steps[f] + 1) >= (long long)DEADTH) ? 1 : 0;
}

// ---------------- exact per-row top-k via 4-pass radix select ---------------
__global__ __launch_bounds__(256)
void topk_kernel(int k, int is_aux, float* __restrict__ coeffs_out,
                 const float* __restrict__ xin, const float* __restrict__ Wenc,
                 const float* __restrict__ be) {
    extern __shared__ unsigned sh[];
    unsigned* keys = sh;                               // NF
    unsigned* hist = sh + NF;                          // 256
    int*      cand_idx = (int*)(hist + 256);           // 256
    unsigned* cand_key = (unsigned*)(cand_idx + 256);  // 256
    float*    exv = (float*)(cand_key + 256);          // 256
    double*   redd = (double*)(exv + 256);             // 256 doubles
    __shared__ int s_bin, s_rem, s_cnt, s_pos, s_nhi, s_nc;

    const int r = blockIdx.x;
    const int tid = threadIdx.x;
    const float* row = g_pre + (size_t)r * NF;

    for (int i = tid; i < NF; i += 256) {
        unsigned u = f2k(row[i]);
        if (is_aux && g_dead[i] == 0) u = 0u;
        keys[i] = u;
    }
    __syncthreads();

    unsigned prefix = 0;
    int remaining = k;
#pragma unroll
    for (int shift = 24; shift >= 0; shift -= 8) {
        hist[tid] = 0;
        __syncthreads();
        unsigned himask = (shift == 24) ? 0u : (0xFFFFFFFFu << (shift + 8));
        for (int i = tid; i < NF; i += 256) {
            unsigned u = keys[i];
            if ((u & himask) == prefix) atomicAdd(&hist[(u >> shift) & 255u], 1u);
        }
        __syncthreads();
        if (tid == 0) {
            int cum = 0, b = 255;
            for (; b > 0; b--) {
                int cnt = (int)hist[b];
                if (cum + cnt >= remaining) break;
                cum += cnt;
            }
            s_bin = b;
            s_rem = remaining - cum;
        }
        __syncthreads();
        prefix |= ((unsigned)s_bin) << shift;
        remaining = s_rem;
        __syncthreads();
    }
    const unsigned thr = prefix;

    if (tid == 0) { s_cnt = 0; s_pos = 0; s_nhi = 0; s_nc = 0; }
    __syncthreads();

    if (!is_aux) {
        // -------- main top-32 with band refinement --------
        const float DELTA = 1e-4f;
        const float v32 = k2f(thr);
        const unsigned khi = f2k(v32 + DELTA);
        const unsigned klo = f2k(v32 - DELTA);

        for (int i = tid; i < NF; i += 256) {
            unsigned u = keys[i];
            if (u > khi) {
                atomicAdd(&s_nhi, 1);
                float v = k2f(u);
                if (v > 0.f) {
                    int p = atomicAdd(&s_pos, 1);
                    g_tk_idx[r * TOPK + p] = i;
                    g_tk_val[r * TOPK + p] = v;
                    coeffs_out[(size_t)r * NF + i] = v;
                    g_active[i] = 1;
                }
            } else if (u >= klo) {
                int p = atomicAdd(&s_nc, 1);
                if (p < CAND_MAX) { cand_idx[p] = i; cand_key[p] = u; }
            }
        }
        __syncthreads();

        const int need = TOPK - s_nhi;
        const int nc = (s_nc < CAND_MAX) ? s_nc : CAND_MAX;

        auto sel_write = [&](int i, float v) {
            if (v > 0.f) {
                int p = atomicAdd(&s_pos, 1);
                g_tk_idx[r * TOPK + p] = i;
                g_tk_val[r * TOPK + p] = v;
                coeffs_out[(size_t)r * NF + i] = v;
                g_active[i] = 1;
            }
        };

        if (nc == need) {
            if (tid < nc) sel_write(cand_idx[tid], k2f(cand_key[tid]));
        } else {
            // rare: EXACT recompute of candidates from fp32 x / W_enc
            const float* xr = xin + (size_t)r * D_INV;
            for (int t = 0; t < nc; t++) {
                const float* Wc = Wenc + cand_idx[t];
                double part = 0.0;
#pragma unroll
                for (int q = 0; q < 8; q++) {
                    int p = tid + q * 256;
                    part += (double)xr[p] * (double)Wc[(size_t)p * NF];
                }
                redd[tid] = part; __syncthreads();
                for (int s = 128; s > 0; s >>= 1) {
                    if (tid < s) redd[tid] += redd[tid + s];
                    __syncthreads();
                }
                if (tid == 0) exv[t] = (float)(redd[0] + (double)be[cand_idx[t]]);
                __syncthreads();
            }
            if (tid < nc) {
                float mv = exv[tid];
                int mi = cand_idx[tid];
                int rank = 0;
                for (int u = 0; u < nc; u++) {
                    if (exv[u] > mv || (exv[u] == mv && cand_idx[u] < mi)) rank++;
                }
                if (rank < need) sel_write(mi, mv);
            }
        }
        __syncthreads();
        if (tid == 0) g_tk_cnt[r] = s_pos;
    } else {
        // -------- aux top-256: approx selection (flip impact negligible) ----
        for (int i = tid; i < NF; i += 256) {
            unsigned u = keys[i];
            if (u > thr) {
                atomicAdd(&s_cnt, 1);
                float v = k2f(u);
                if (v > 0.f) {
                    int p = atomicAdd(&s_pos, 1);
                    g_ax_idx[r * KAUX + p] = i;
                    g_ax_val[r * KAUX + p] = v;
                }
            }
        }
        __syncthreads();
        if (tid == 0) {
            int need = k - s_cnt;
            if (thr != 0u) {
                for (int i = 0; i < NF && need > 0; i++) {
                    if (keys[i] == thr) {
                        need--;
                        float v = k2f(thr);
                        if (v > 0.f) {
                            int p = s_pos++;
                            g_ax_idx[r * KAUX + p] = i;
                            g_ax_val[r * KAUX + p] = v;
                        }
                    }
                }
            }
            g_ax_cnt[r] = s_pos;
        }
    }
}

// ---------------- sparse decode + deterministic MSE/aux partials -----------
// main recon: fp32 W_dec; aux: bf16 W_dec (halves the dominant traffic)
__global__ __launch_bounds__(256)
void decode_kernel(const float* __restrict__ x, const float* __restrict__ Wd,
                   const float* __restrict__ bd, float* __restrict__ recon) {
    const int r = blockIdx.x, tid = threadIdx.x;
    __shared__ int   sidx_[KAUX];
    __shared__ float sval[KAUX];
    __shared__ double sred[256];

    const int cnt = g_tk_cnt[r];
    if (tid < cnt) { sidx_[tid] = g_tk_idx[r * TOPK + tid]; sval[tid] = g_tk_val[r * TOPK + tid]; }
    __syncthreads();

    // column mapping: pair q -> elements (tid + 256*q)*2 + {0,1}
    float2 bdv[4], acc[4];
#pragma unroll
    for (int q = 0; q < 4; q++) {
        bdv[q] = *(const float2*)(bd + (size_t)(tid + 256 * q) * 2);
        acc[q] = bdv[q];
    }

    for (int t = 0; t < cnt; t++) {
        const float* wv = Wd + (size_t)sidx_[t] * D_INV;
        float v = sval[t];
#pragma unroll
        for (int q = 0; q < 4; q++) {
            float2 wq = *(const float2*)(wv + (size_t)(tid + 256 * q) * 2);
            acc[q].x += v * wq.x;
            acc[q].y += v * wq.y;
        }
    }

    float2 xr[4];
#pragma unroll
    for (int q = 0; q < 4; q++)
        xr[q] = *(const float2*)(x + (size_t)r * D_INV + (size_t)(tid + 256 * q) * 2);

    double pm = 0.0;
#pragma unroll
    for (int q = 0; q < 4; q++) {
        *(float2*)(recon + (size_t)r * D_INV + (size_t)(tid + 256 * q) * 2) = acc[q];
        float ex = acc[q].x - xr[q].x, ey = acc[q].y - xr[q].y;
        pm += (double)ex * ex + (double)ey * ey;
    }

    __syncthreads();
    const int acnt = g_ax_cnt[r];
    if (tid < acnt) { sidx_[tid] = g_ax_idx[r * KAUX + tid]; sval[tid] = g_ax_val[r * KAUX + tid]; }
    __syncthreads();

    float2 aacc[4];
#pragma unroll
    for (int q = 0; q < 4; q++) aacc[q] = bdv[q];
    for (int t = 0; t < acnt; t++) {
        const uint32_t* wq = g_Wd16u + (size_t)sidx_[t] * (D_INV / 2);
        float v = sval[t];
#pragma unroll
        for (int q = 0; q < 4; q++) {
            float2 wf = upbf(wq[tid + 256 * q]);
            aacc[q].x += v * wf.x;
            aacc[q].y += v * wf.y;
        }
    }

    double pa = 0.0;
#pragma unroll
    for (int q = 0; q < 4; q++) {
        float rx = xr[q].x - acc[q].x, ry = xr[q].y - acc[q].y;
        float ex = aacc[q].x - rx, ey = aacc[q].y - ry;
        pa += (double)ex * ex + (double)ey * ey;
    }

    sred[tid] = pm; __syncthreads();
    for (int s = 128; s > 0; s >>= 1) { if (tid < s) sred[tid] += sred[tid + s]; __syncthreads(); }
    if (tid == 0) g_pmse[r] = sred[0];
    __syncthreads();
    sred[tid] = pa; __syncthreads();
    for (int s = 128; s > 0; s >>= 1) { if (tid < s) sred[tid] += sred[tid + s]; __syncthreads(); }
    if (tid == 0) g_paux[r] = sred[0];
}

__global__ void finalize_kernel(float* __restrict__ scal) {
    __shared__ double sm[256], sa[256];
    const int tid = threadIdx.x;
    double m = 0.0, a = 0.0;
    for (int i = tid; i < B_TOK; i += 256) { m += g_pmse[i]; a += g_paux[i]; }
    sm[tid] = m; sa[tid] = a; __syncthreads();
    for (int s = 128; s > 0; s >>= 1) {
        if (tid < s) { sm[tid] += sm[tid + s]; sa[tid] += sa[tid + s]; }
        __syncthreads();
    }
    if (tid == 0) {
        const double denom = (double)B_TOK * (double)D_INV;
        double mse = sm[0] / denom;
        double aux = sa[0] / denom;
        scal[0] = (float)(mse + aux);
        scal[1] = (float)mse;
        scal[2] = (float)aux;
    }
}

// ---------------- launch ----------------------------------------------------
extern "C" void kernel_launch(void* const* d_in, const int* in_sizes, int n_in,
                              void* d_out, int out_size) {
    const float*     x     = (const float*)d_in[0];
    const float*     We    = (const float*)d_in[1];
    const float*     be    = (const float*)d_in[2];
    const float*     Wd    = (const float*)d_in[3];
    const float*     bd    = (const float*)d_in[4];
    const long long* steps = (const long long*)d_in[5];

    float* out    = (float*)d_out;
    float* recon  = out;                                       // [4096,2048]
    float* coeffs = out + (size_t)B_TOK * D_INV;               // [4096,16384]
    float* scal   = coeffs + (size_t)B_TOK * NF;               // loss, mse, aux

    const size_t topk_smem = (size_t)(NF + 4 * 256) * 4 + 256 * 8;  // 71680 B
    cudaFuncSetAttribute(topk_kernel, cudaFuncAttributeMaxDynamicSharedMemorySize,
                         (int)topk_smem);
    cudaFuncSetAttribute(gemm_bf16_kernel, cudaFuncAttributeMaxDynamicSharedMemorySize,
                         GEMM_SMEM);

    // zero coeffs region + active flags
    cudaMemsetAsync(coeffs, 0, (size_t)B_TOK * NF * sizeof(float));
    init_active_kernel<<<(NF + 255) / 256, 256>>>();

    // bf16 hi/lo conversion (A elementwise, B transposed to K-major), Wd bf16
    conv_a_kernel<<<(B_TOK * D_INV / 4) / 256, 256>>>(x);
    conv_b_kernel<<<dim3(NF / 32, D_INV / 32), 256>>>(We);
    conv_wd_kernel<<<((size_t)NF * D_INV / 4) / 256, 256>>>(Wd);

    // tensor-core encoder GEMM -> g_pre (3-term bf16 split via mma.sync+ldmatrix)
    gemm_bf16_kernel<<<dim3(B_TOK / TM, NF / TN), 512, GEMM_SMEM>>>(be);

    // main top-32 (band-refined; exact fp32 recompute for borderline)
    topk_kernel<<<B_TOK, 256, topk_smem>>>(TOPK, 0, coeffs, x, We, be);

    // dead mask
    dead_kernel<<<(NF + 255) / 256, 256>>>(steps);

    // aux top-256 over dead features
    topk_kernel<<<B_TOK, 256, topk_smem>>>(KAUX, 1, nullptr, x, We, be);

    // sparse decode + partial sums (aux via bf16 W_dec)
    decode_kernel<<<B_TOK, 256>>>(x, Wd, bd, recon);

    // deterministic final reduction + scalars
    finalize_kernel<<<1, 256>>>(scal);
}

// round 7
// speedup vs baseline: 3.6972x; 1.2052x over previous
#include <cuda_runtime.h>
#include <cuda_fp16.h>
#include <cuda_bf16.h>
#include <cstdint>

#define B_TOK 4096
#define D_INV 2048
#define NF    16384
#define TOPK  32
#define KAUX  256
#define DEADTH 100

// GEMM tiling
#define TM 128
#define TN 128
#define BK 32
#define NIT (D_INV / BK)          // 64
#define STAGE_U32 6144            // 3 planes x 2048 u32 (24KB)
#define GEMM_SMEM (4 * STAGE_U32 * 4)   // 98304 bytes, 4 stages

#define CAND_MAX 256

// ---------------- scratch (device globals; no allocation allowed) ----------
__device__ float    g_pre[(size_t)B_TOK * NF];        // 256 MB
__device__ uint32_t g_Ah16u[(size_t)B_TOK * D_INV / 2];   // fp16 pairs (hi)
__device__ uint32_t g_Al16u[(size_t)B_TOK * D_INV / 2];   // fp16 pairs (lo)
__device__ uint32_t g_B16u[(size_t)NF * D_INV / 2];       // fp16 W_enc^T [NF][D/2]
__device__ uint32_t g_Wd16u[(size_t)NF * D_INV / 2];      // bf16 W_dec (aux only)
__device__ int    g_tk_idx[B_TOK * TOPK];
__device__ float  g_tk_val[B_TOK * TOPK];
__device__ int    g_tk_cnt[B_TOK];
__device__ int    g_ax_idx[B_TOK * KAUX];
__device__ float  g_ax_val[B_TOK * KAUX];
__device__ int    g_ax_cnt[B_TOK];
__device__ int    g_active[NF];
__device__ int    g_dead[NF];
__device__ double g_pmse[B_TOK];
__device__ double g_paux[B_TOK];

// ---------------- helpers ----------------------------------------------------
__device__ __forceinline__ uint32_t smem_u32(const void* p) {
    uint32_t a;
    asm("{ .reg .u64 t; cvta.to.shared.u64 t, %1; cvt.u32.u64 %0, t; }"
        : "=r"(a) : "l"(p));
    return a;
}
__device__ __forceinline__ void cpa16(uint32_t dst, const void* src) {
    asm volatile("cp.async.cg.shared.global [%0], [%1], 16;" :: "r"(dst), "l"(src));
}
__device__ __forceinline__ uint32_t pkh(__half a, __half b) {
    __half2 t = __halves2half2(a, b);
    return *reinterpret_cast<uint32_t*>(&t);
}
__device__ __forceinline__ uint32_t pkbf(__nv_bfloat16 a, __nv_bfloat16 b) {
    __nv_bfloat162 t = __halves2bfloat162(a, b);
    return *reinterpret_cast<uint32_t*>(&t);
}
__device__ __forceinline__ float2 upbf(uint32_t u) {
    __nv_bfloat162 t = *reinterpret_cast<__nv_bfloat162*>(&u);
    return __bfloat1622float2(t);
}
__device__ __forceinline__ unsigned f2k(float v) {
    unsigned u = __float_as_uint(v);
    return (u & 0x80000000u) ? ~u : (u | 0x80000000u);
}
__device__ __forceinline__ float k2f(unsigned u) {
    unsigned b = (u & 0x80000000u) ? (u ^ 0x80000000u) : ~u;
    return __uint_as_float(b);
}

#define MMA_F16(C, A, B) \
    asm volatile("mma.sync.aligned.m16n8k16.row.col.f32.f16.f16.f32 " \
        "{%0,%1,%2,%3}, {%4,%5,%6,%7}, {%8,%9}, {%0,%1,%2,%3};" \
        : "+f"((C)[0]), "+f"((C)[1]), "+f"((C)[2]), "+f"((C)[3]) \
        : "r"((A)[0]), "r"((A)[1]), "r"((A)[2]), "r"((A)[3]), \
          "r"((B)[0]), "r"((B)[1]))

#define LDSM4(R0, R1, R2, R3, ADDR) \
    asm volatile("ldmatrix.sync.aligned.m8n8.x4.shared.b16 {%0,%1,%2,%3}, [%4];" \
        : "=r"(R0), "=r"(R1), "=r"(R2), "=r"(R3) : "r"(ADDR))

// ---------------- convert pre-pass (A fp16 hi/lo split) ---------------------
__global__ __launch_bounds__(256) void conv_a_kernel(const float* __restrict__ A) {
    size_t i = (size_t)blockIdx.x * 256 + threadIdx.x;   // float4 index
    const float4 v = ((const float4*)A)[i];
    __half hx = __float2half_rn(v.x), hy = __float2half_rn(v.y);
    __half hz = __float2half_rn(v.z), hw = __float2half_rn(v.w);
    __half lx = __float2half_rn(v.x - __half2float(hx));
    __half ly = __float2half_rn(v.y - __half2float(hy));
    __half lz = __float2half_rn(v.z - __half2float(hz));
    __half lw = __float2half_rn(v.w - __half2float(hw));
    ((uint2*)g_Ah16u)[i] = make_uint2(pkh(hx, hy), pkh(hz, hw));
    ((uint2*)g_Al16u)[i] = make_uint2(pkh(lx, ly), pkh(lz, lw));
}

// W_dec [NF][D_INV] -> single bf16 plane (aux decode only)
__global__ __launch_bounds__(256) void conv_wd_kernel(const float* __restrict__ Wd) {
    size_t i = (size_t)blockIdx.x * 256 + threadIdx.x;   // float4 index
    const float4 v = ((const float4*)Wd)[i];
    uint2 o;
    o.x = pkbf(__float2bfloat16_rn(v.x), __float2bfloat16_rn(v.y));
    o.y = pkbf(__float2bfloat16_rn(v.z), __float2bfloat16_rn(v.w));
    ((uint2*)g_Wd16u)[i] = o;
}

// B [D_INV][NF] -> [NF][D_INV/2] fp16-pair plane via 32x32 smem transpose
__global__ __launch_bounds__(256) void conv_b_kernel(const float* __restrict__ B) {
    __shared__ float sh[32][33];
    const int n0 = blockIdx.x * 32;
    const int k0 = blockIdx.y * 32;
    const int tx = threadIdx.x & 31, ty = threadIdx.x >> 5;
#pragma unroll
    for (int q = 0; q < 4; q++) {
        int k = ty + q * 8;
        sh[k][tx] = B[(size_t)(k0 + k) * NF + n0 + tx];
    }
    __syncthreads();
#pragma unroll
    for (int q = 0; q < 2; q++) {
        int idx = threadIdx.x + q * 256;   // 0..511
        int n = idx & 31, kp = idx >> 5;   // kp 0..15
        float v0 = sh[kp * 2][n], v1 = sh[kp * 2 + 1][n];
        size_t o = (size_t)(n0 + n) * (D_INV / 2) + (k0 >> 1) + kp;
        g_B16u[o] = pkh(__float2half_rn(v0), __float2half_rn(v1));
    }
}

// ---------------- fp16 2-term mma.sync GEMM: g_pre = x @ W_enc + b_enc ------
// pre = (Ah + Al) * B16. 128x128 tile, BK=32, 512 threads, 4-stage pipeline.
__global__ __launch_bounds__(512, 1)
void gemm_f16_kernel(const float* __restrict__ bias) {
    extern __shared__ uint32_t smw[];   // 4 stages x 6144 u32
    const int tid = threadIdx.x;
    const int w = tid >> 5, lane = tid & 31;
    const int m0 = blockIdx.x * TM;
    const int n0 = blockIdx.y * TN;
    const int wm = (w & 3) * 32;
    const int wn = (w >> 2) * 32;
    const int lr = lane >> 2, lc = lane & 3;
    const uint32_t smbase = smem_u32(smw);

    float c[2][4][4];
#pragma unroll
    for (int mi = 0; mi < 2; mi++)
#pragma unroll
        for (int ni = 0; ni < 4; ni++)
#pragma unroll
            for (int j = 0; j < 4; j++) c[mi][ni][j] = 0.f;

    auto loadStage = [&](int s, int kt) {
        uint32_t* st = smw + s * STAGE_U32;
        const int ktu = kt >> 1;
#pragma unroll
        for (int q = 0; q < 3; q++) {
            int t = tid + q * 512;            // 0..1535
            int pl = t >> 9;                  // 0: Ah, 1: Al, 2: B
            int rem = t & 511;
            int row = rem >> 2, ch = rem & 3;
            const uint32_t* base = (pl == 0) ? g_Ah16u : (pl == 1) ? g_Al16u : g_B16u;
            const uint32_t* src = base +
                (size_t)((pl == 2 ? n0 : m0) + row) * (D_INV / 2) + ktu + ch * 4;
            uint32_t* dst = st + pl * 2048 + row * 16 +
                            ((ch ^ ((row >> 1) & 3)) << 2);
            cpa16(smem_u32(dst), src);
        }
    };

    loadStage(0, 0);
    asm volatile("cp.async.commit_group;");
    loadStage(1, BK);
    asm volatile("cp.async.commit_group;");
    loadStage(2, 2 * BK);
    asm volatile("cp.async.commit_group;");

    const int a_rowadd = ((lane >> 3) & 1) * 8 + (lane & 7);
    const int a_chadd  = lane >> 4;
    const int b_rowadd = (lane >> 4) * 8 + (lane & 7);
    const int b_chadd  = (lane >> 3) & 1;

    for (int i = 0; i < NIT; i++) {
        asm volatile("cp.async.wait_group 2;" ::: "memory");
        __syncthreads();

        const uint32_t sb = smbase + (i & 3) * (STAGE_U32 * 4);  // byte base

#pragma unroll
        for (int ks = 0; ks < 2; ks++) {
            const int c0 = 2 * ks;
            uint32_t ah[2][4], al[2][4], bb[4][2];
#pragma unroll
            for (int mi = 0; mi < 2; mi++) {
                int R = wm + mi * 16 + a_rowadd;
                int ch = c0 + a_chadd;
                uint32_t off = (uint32_t)(R * 16 + ((ch ^ ((R >> 1) & 3)) << 2)) * 4;
                LDSM4(ah[mi][0], ah[mi][1], ah[mi][2], ah[mi][3], sb + off);
                LDSM4(al[mi][0], al[mi][1], al[mi][2], al[mi][3], sb + 8192 + off);
            }
#pragma unroll
            for (int nip = 0; nip < 2; nip++) {
                int N = wn + nip * 16 + b_rowadd;
                int ch = c0 + b_chadd;
                uint32_t off = (uint32_t)(N * 16 + ((ch ^ ((N >> 1) & 3)) << 2)) * 4;
                LDSM4(bb[2 * nip][0], bb[2 * nip][1],
                      bb[2 * nip + 1][0], bb[2 * nip + 1][1], sb + 16384 + off);
            }
#pragma unroll
            for (int mi = 0; mi < 2; mi++)
#pragma unroll
                for (int ni = 0; ni < 4; ni++) {
                    MMA_F16(c[mi][ni], ah[mi], bb[ni]);
                    MMA_F16(c[mi][ni], al[mi], bb[ni]);
                }
        }
        if (i + 3 < NIT) loadStage((i + 3) & 3, (i + 3) * BK);
        asm volatile("cp.async.commit_group;");
    }

    // epilogue: add bias, store
#pragma unroll
    for (int mi = 0; mi < 2; mi++) {
        int row = m0 + wm + mi * 16 + lr;
#pragma unroll
        for (int ni = 0; ni < 4; ni++) {
            int col = n0 + wn + ni * 8 + lc * 2;
            float2 bv = *(const float2*)(bias + col);
            float2 o0, o1;
            o0.x = c[mi][ni][0] + bv.x; o0.y = c[mi][ni][1] + bv.y;
            o1.x = c[mi][ni][2] + bv.x; o1.y = c[mi][ni][3] + bv.y;
            *(float2*)(g_pre + (size_t)row * NF + col) = o0;
            *(float2*)(g_pre + (size_t)(row + 8) * NF + col) = o1;
        }
    }
}

// ---------------- misc small kernels ---------------------------------------
__global__ void init_active_kernel() {
    int f = blockIdx.x * blockDim.x + threadIdx.x;
    if (f < NF) g_active[f] = 0;
}

__global__ void dead_kernel(const long long* __restrict__ steps) {
    int f = blockIdx.x * blockDim.x + threadIdx.x;
    if (f < NF)
        g_dead[f] = (g_active[f] == 0 && (steps[f] + 1) >= (long long)DEADTH) ? 1 : 0;
}

// ---------------- exact per-row top-k via 4-pass radix select ---------------
__global__ __launch_bounds__(256)
void topk_kernel(int k, int is_aux, float* __restrict__ coeffs_out,
                 const float* __restrict__ xin, const float* __restrict__ Wenc,
                 const float* __restrict__ be) {
    extern __shared__ unsigned sh[];
    unsigned* keys = sh;                               // NF
    unsigned* hist = sh + NF;                          // 256
    int*      cand_idx = (int*)(hist + 256);           // 256
    unsigned* cand_key = (unsigned*)(cand_idx + 256);  // 256
    float*    exv = (float*)(cand_key + 256);          // 256
    double*   redd = (double*)(exv + 256);             // 256 doubles
    __shared__ int s_bin, s_rem, s_cnt, s_pos, s_nhi, s_nc;

    const int r = blockIdx.x;
    const int tid = threadIdx.x;
    const float* row = g_pre + (size_t)r * NF;

    for (int i = tid; i < NF; i += 256) {
        unsigned u = f2k(row[i]);
        if (is_aux && g_dead[i] == 0) u = 0u;
        keys[i] = u;
    }
    __syncthreads();

    unsigned prefix = 0;
    int remaining = k;
#pragma unroll
    for (int shift = 24; shift >= 0; shift -= 8) {
        hist[tid] = 0;
        __syncthreads();
        unsigned himask = (shift == 24) ? 0u : (0xFFFFFFFFu << (shift + 8));
        for (int i = tid; i < NF; i += 256) {
            unsigned u = keys[i];
            if ((u & himask) == prefix) atomicAdd(&hist[(u >> shift) & 255u], 1u);
        }
        __syncthreads();
        if (tid == 0) {
            int cum = 0, b = 255;
            for (; b > 0; b--) {
                int cnt = (int)hist[b];
                if (cum + cnt >= remaining) break;
                cum += cnt;
            }
            s_bin = b;
            s_rem = remaining - cum;
        }
        __syncthreads();
        prefix |= ((unsigned)s_bin) << shift;
        remaining = s_rem;
        __syncthreads();
    }
    const unsigned thr = prefix;

    if (tid == 0) { s_cnt = 0; s_pos = 0; s_nhi = 0; s_nc = 0; }
    __syncthreads();

    if (!is_aux) {
        // -------- main top-32 with band refinement (fp16-GEMM noise: 8e-4) --
        const float DELTA = 8e-4f;
        const float v32 = k2f(thr);
        const unsigned khi = f2k(v32 + DELTA);
        const unsigned klo = f2k(v32 - DELTA);

        for (int i = tid; i < NF; i += 256) {
            unsigned u = keys[i];
            if (u > khi) {
                atomicAdd(&s_nhi, 1);
                float v = k2f(u);
                if (v > 0.f) {
                    int p = atomicAdd(&s_pos, 1);
                    g_tk_idx[r * TOPK + p] = i;
                    g_tk_val[r * TOPK + p] = v;
                    coeffs_out[(size_t)r * NF + i] = v;
                    g_active[i] = 1;
                }
            } else if (u >= klo) {
                int p = atomicAdd(&s_nc, 1);
                if (p < CAND_MAX) { cand_idx[p] = i; cand_key[p] = u; }
            }
        }
        __syncthreads();

        const int need = TOPK - s_nhi;
        const int nc = (s_nc < CAND_MAX) ? s_nc : CAND_MAX;

        auto sel_write = [&](int i, float v) {
            if (v > 0.f) {
                int p = atomicAdd(&s_pos, 1);
                g_tk_idx[r * TOPK + p] = i;
                g_tk_val[r * TOPK + p] = v;
                coeffs_out[(size_t)r * NF + i] = v;
                g_active[i] = 1;
            }
        };

        if (nc == need) {
            if (tid < nc) sel_write(cand_idx[tid], k2f(cand_key[tid]));
        } else {
            // EXACT recompute of candidates from fp32 x / W_enc
            const float* xr = xin + (size_t)r * D_INV;
            for (int t = 0; t < nc; t++) {
                const float* Wc = Wenc + cand_idx[t];
                double part = 0.0;
#pragma unroll
                for (int q = 0; q < 8; q++) {
                    int p = tid + q * 256;
                    part += (double)xr[p] * (double)Wc[(size_t)p * NF];
                }
                redd[tid] = part; __syncthreads();
                for (int s = 128; s > 0; s >>= 1) {
                    if (tid < s) redd[tid] += redd[tid + s];
                    __syncthreads();
                }
                if (tid == 0) exv[t] = (float)(redd[0] + (double)be[cand_idx[t]]);
                __syncthreads();
            }
            if (tid < nc) {
                float mv = exv[tid];
                int mi = cand_idx[tid];
                int rank = 0;
                for (int u = 0; u < nc; u++) {
                    if (exv[u] > mv || (exv[u] == mv && cand_idx[u] < mi)) rank++;
                }
                if (rank < need) sel_write(mi, mv);
            }
        }
        __syncthreads();
        if (tid == 0) g_tk_cnt[r] = s_pos;
    } else {
        // -------- aux top-256: approx selection (flip impact negligible) ----
        for (int i = tid; i < NF; i += 256) {
            unsigned u = keys[i];
            if (u > thr) {
                atomicAdd(&s_cnt, 1);
                float v = k2f(u);
                if (v > 0.f) {
                    int p = atomicAdd(&s_pos, 1);
                    g_ax_idx[r * KAUX + p] = i;
                    g_ax_val[r * KAUX + p] = v;
                }
            }
        }
        __syncthreads();
        if (tid == 0) {
            int need = k - s_cnt;
            if (thr != 0u) {
                for (int i = 0; i < NF && need > 0; i++) {
                    if (keys[i] == thr) {
                        need--;
                        float v = k2f(thr);
                        if (v > 0.f) {
                            int p = s_pos++;
                            g_ax_idx[r * KAUX + p] = i;
                            g_ax_val[r * KAUX + p] = v;
                        }
                    }
                }
            }
            g_ax_cnt[r] = s_pos;
        }
    }
}

// ---------------- sparse decode + deterministic MSE/aux partials -----------
__global__ __launch_bounds__(256)
void decode_kernel(const float* __restrict__ x, const float* __restrict__ Wd,
                   const float* __restrict__ bd, float* __restrict__ recon) {
    const int r = blockIdx.x, tid = threadIdx.x;
    __shared__ int   sidx_[KAUX];
    __shared__ float sval[KAUX];
    __shared__ double sred[256];

    const int cnt = g_tk_cnt[r];
    if (tid < cnt) { sidx_[tid] = g_tk_idx[r * TOPK + tid]; sval[tid] = g_tk_val[r * TOPK + tid]; }
    __syncthreads();

    float2 bdv[4], acc[4];
#pragma unroll
    for (int q = 0; q < 4; q++) {
        bdv[q] = *(const float2*)(bd + (size_t)(tid + 256 * q) * 2);
        acc[q] = bdv[q];
    }

    for (int t = 0; t < cnt; t++) {
        const float* wv = Wd + (size_t)sidx_[t] * D_INV;
        float v = sval[t];
#pragma unroll
        for (int q = 0; q < 4; q++) {
            float2 wq = *(const float2*)(wv + (size_t)(tid + 256 * q) * 2);
            acc[q].x += v * wq.x;
            acc[q].y += v * wq.y;
        }
    }

    float2 xr[4];
#pragma unroll
    for (int q = 0; q < 4; q++)
        xr[q] = *(const float2*)(x + (size_t)r * D_INV + (size_t)(tid + 256 * q) * 2);

    double pm = 0.0;
#pragma unroll
    for (int q = 0; q < 4; q++) {
        *(float2*)(recon + (size_t)r * D_INV + (size_t)(tid + 256 * q) * 2) = acc[q];
        float ex = acc[q].x - xr[q].x, ey = acc[q].y - xr[q].y;
        pm += (double)ex * ex + (double)ey * ey;
    }

    __syncthreads();
    const int acnt = g_ax_cnt[r];
    if (tid < acnt) { sidx_[tid] = g_ax_idx[r * KAUX + tid]; sval[tid] = g_ax_val[r * KAUX + tid]; }
    __syncthreads();

    float2 aacc[4];
#pragma unroll
    for (int q = 0; q < 4; q++) aacc[q] = bdv[q];
    for (int t = 0; t < acnt; t++) {
        const uint32_t* wq = g_Wd16u + (size_t)sidx_[t] * (D_INV / 2);
        float v = sval[t];
#pragma unroll
        for (int q = 0; q < 4; q++) {
            float2 wf = upbf(wq[tid + 256 * q]);
            aacc[q].x += v * wf.x;
            aacc[q].y += v * wf.y;
        }
    }

    double pa = 0.0;
#pragma unroll
    for (int q = 0; q < 4; q++) {
        float rx = xr[q].x - acc[q].x, ry = xr[q].y - acc[q].y;
        float ex = aacc[q].x - rx, ey = aacc[q].y - ry;
        pa += (double)ex * ex + (double)ey * ey;
    }

    sred[tid] = pm; __syncthreads();
    for (int s = 128; s > 0; s >>= 1) { if (tid < s) sred[tid] += sred[tid + s]; __syncthreads(); }
    if (tid == 0) g_pmse[r] = sred[0];
    __syncthreads();
    sred[tid] = pa; __syncthreads();
    for (int s = 128; s > 0; s >>= 1) { if (tid < s) sred[tid] += sred[tid + s]; __syncthreads(); }
    if (tid == 0) g_paux[r] = sred[0];
}

__global__ void finalize_kernel(float* __restrict__ scal) {
    __shared__ double sm[256], sa[256];
    const int tid = threadIdx.x;
    double m = 0.0, a = 0.0;
    for (int i = tid; i < B_TOK; i += 256) { m += g_pmse[i]; a += g_paux[i]; }
    sm[tid] = m; sa[tid] = a; __syncthreads();
    for (int s = 128; s > 0; s >>= 1) {
        if (tid < s) { sm[tid] += sm[tid + s]; sa[tid] += sa[tid + s]; }
        __syncthreads();
    }
    if (tid == 0) {
        const double denom = (double)B_TOK * (double)D_INV;
        double mse = sm[0] / denom;
        double aux = sa[0] / denom;
        scal[0] = (float)(mse + aux);
        scal[1] = (float)mse;
        scal[2] = (float)aux;
    }
}

// ---------------- launch ----------------------------------------------------
extern "C" void kernel_launch(void* const* d_in, const int* in_sizes, int n_in,
                              void* d_out, int out_size) {
    const float*     x     = (const float*)d_in[0];
    const float*     We    = (const float*)d_in[1];
    const float*     be    = (const float*)d_in[2];
    const float*     Wd    = (const float*)d_in[3];
    const float*     bd    = (const float*)d_in[4];
    const long long* steps = (const long long*)d_in[5];

    float* out    = (float*)d_out;
    float* recon  = out;                                       // [4096,2048]
    float* coeffs = out + (size_t)B_TOK * D_INV;               // [4096,16384]
    float* scal   = coeffs + (size_t)B_TOK * NF;               // loss, mse, aux

    const size_t topk_smem = (size_t)(NF + 4 * 256) * 4 + 256 * 8;  // 71680 B
    cudaFuncSetAttribute(topk_kernel, cudaFuncAttributeMaxDynamicSharedMemorySize,
                         (int)topk_smem);
    cudaFuncSetAttribute(gemm_f16_kernel, cudaFuncAttributeMaxDynamicSharedMemorySize,
                         GEMM_SMEM);

    // zero coeffs region + active flags
    cudaMemsetAsync(coeffs, 0, (size_t)B_TOK * NF * sizeof(float));
    init_active_kernel<<<(NF + 255) / 256, 256>>>();

    // fp16 conversion (A split hi/lo, B transposed + rounded), Wd bf16
    conv_a_kernel<<<(B_TOK * D_INV / 4) / 256, 256>>>(x);
    conv_b_kernel<<<dim3(NF / 32, D_INV / 32), 256>>>(We);
    conv_wd_kernel<<<((size_t)NF * D_INV / 4) / 256, 256>>>(Wd);

    // tensor-core encoder GEMM -> g_pre (2-term fp16 split via mma.sync)
    gemm_f16_kernel<<<dim3(B_TOK / TM, NF / TN), 512, GEMM_SMEM>>>(be);

    // main top-32 (band-refined; exact fp32 recompute for borderline)
    topk_kernel<<<B_TOK, 256, topk_smem>>>(TOPK, 0, coeffs, x, We, be);

    // dead mask
    dead_kernel<<<(NF + 255) / 256, 256>>>(steps);

    // aux top-256 over dead features
    topk_kernel<<<B_TOK, 256, topk_smem>>>(KAUX, 1, nullptr, x, We, be);

    // sparse decode + partial sums (aux via bf16 W_dec)
    decode_kernel<<<B_TOK, 256>>>(x, Wd, bd, recon);

    // deterministic final reduction + scalars
    finalize_kernel<<<1, 256>>>(scal);
}

// round 8
// speedup vs baseline: 4.6336x; 1.2533x over previous
#include <cuda_runtime.h>
#include <cuda_fp16.h>
#include <cstdint>

#define B_TOK 4096
#define D_INV 2048
#define NF    16384
#define TOPK  32
#define KAUX  256
#define DEADTH 100

// GEMM tiling
#define TM 128
#define TN 128
#define BK 64
#define NIT (D_INV / BK)          // 32
#define STAGE_U32 8192            // 2 planes x 128 rows x 32 u32 (32KB)
#define GEMM_SMEM (4 * STAGE_U32 * 4)   // 131072 bytes, 4 stages

#define CAND_MAX 256

// ---------------- scratch (device globals; no allocation allowed) ----------
__device__ float    g_pre[(size_t)B_TOK * NF];        // 256 MB
__device__ uint32_t g_A16u[(size_t)B_TOK * D_INV / 2];    // fp16 pairs
__device__ uint32_t g_B16u[(size_t)NF * D_INV / 2];       // fp16 W_enc^T [NF][D/2]
__device__ uint32_t g_Wd16u[(size_t)NF * D_INV / 2];      // fp16 W_dec
__device__ int    g_tk_idx[B_TOK * TOPK];
__device__ float  g_tk_val[B_TOK * TOPK];
__device__ int    g_tk_cnt[B_TOK];
__device__ int    g_ax_idx[B_TOK * KAUX];
__device__ float  g_ax_val[B_TOK * KAUX];
__device__ int    g_ax_cnt[B_TOK];
__device__ int    g_active[NF];
__device__ int    g_dead[NF];
__device__ double g_pmse[B_TOK];
__device__ double g_paux[B_TOK];

// ---------------- helpers ----------------------------------------------------
__device__ __forceinline__ uint32_t smem_u32(const void* p) {
    uint32_t a;
    asm("{ .reg .u64 t; cvta.to.shared.u64 t, %1; cvt.u32.u64 %0, t; }"
        : "=r"(a) : "l"(p));
    return a;
}
__device__ __forceinline__ void cpa16(uint32_t dst, const void* src) {
    asm volatile("cp.async.cg.shared.global [%0], [%1], 16;" :: "r"(dst), "l"(src));
}
__device__ __forceinline__ uint32_t pkh(__half a, __half b) {
    __half2 t = __halves2half2(a, b);
    return *reinterpret_cast<uint32_t*>(&t);
}
__device__ __forceinline__ float2 uph(uint32_t u) {
    __half2 t = *reinterpret_cast<__half2*>(&u);
    return __half22float2(t);
}
__device__ __forceinline__ unsigned f2k(float v) {
    unsigned u = __float_as_uint(v);
    return (u & 0x80000000u) ? ~u : (u | 0x80000000u);
}
__device__ __forceinline__ float k2f(unsigned u) {
    unsigned b = (u & 0x80000000u) ? (u ^ 0x80000000u) : ~u;
    return __uint_as_float(b);
}

#define MMA_F16(C, A, B) \
    asm volatile("mma.sync.aligned.m16n8k16.row.col.f32.f16.f16.f32 " \
        "{%0,%1,%2,%3}, {%4,%5,%6,%7}, {%8,%9}, {%0,%1,%2,%3};" \
        : "+f"((C)[0]), "+f"((C)[1]), "+f"((C)[2]), "+f"((C)[3]) \
        : "r"((A)[0]), "r"((A)[1]), "r"((A)[2]), "r"((A)[3]), \
          "r"((B)[0]), "r"((B)[1]))

#define LDSM4(R0, R1, R2, R3, ADDR) \
    asm volatile("ldmatrix.sync.aligned.m8n8.x4.shared.b16 {%0,%1,%2,%3}, [%4];" \
        : "=r"(R0), "=r"(R1), "=r"(R2), "=r"(R3) : "r"(ADDR))

// ---------------- convert pre-pass -------------------------------------------
__global__ __launch_bounds__(256) void conv_a_kernel(const float* __restrict__ A) {
    size_t i = (size_t)blockIdx.x * 256 + threadIdx.x;   // float4 index
    const float4 v = ((const float4*)A)[i];
    ((uint2*)g_A16u)[i] = make_uint2(
        pkh(__float2half_rn(v.x), __float2half_rn(v.y)),
        pkh(__float2half_rn(v.z), __float2half_rn(v.w)));
}

// W_dec [NF][D_INV] -> fp16 plane (used by both decodes)
__global__ __launch_bounds__(256) void conv_wd_kernel(const float* __restrict__ Wd) {
    size_t i = (size_t)blockIdx.x * 256 + threadIdx.x;   // float4 index
    const float4 v = ((const float4*)Wd)[i];
    ((uint2*)g_Wd16u)[i] = make_uint2(
        pkh(__float2half_rn(v.x), __float2half_rn(v.y)),
        pkh(__float2half_rn(v.z), __float2half_rn(v.w)));
}

// B [D_INV][NF] -> [NF][D_INV/2] fp16-pair plane via 32x32 smem transpose
__global__ __launch_bounds__(256) void conv_b_kernel(const float* __restrict__ B) {
    __shared__ float sh[32][33];
    const int n0 = blockIdx.x * 32;
    const int k0 = blockIdx.y * 32;
    const int tx = threadIdx.x & 31, ty = threadIdx.x >> 5;
#pragma unroll
    for (int q = 0; q < 4; q++) {
        int k = ty + q * 8;
        sh[k][tx] = B[(size_t)(k0 + k) * NF + n0 + tx];
    }
    __syncthreads();
#pragma unroll
    for (int q = 0; q < 2; q++) {
        int idx = threadIdx.x + q * 256;   // 0..511
        int n = idx & 31, kp = idx >> 5;   // kp 0..15
        float v0 = sh[kp * 2][n], v1 = sh[kp * 2 + 1][n];
        size_t o = (size_t)(n0 + n) * (D_INV / 2) + (k0 >> 1) + kp;
        g_B16u[o] = pkh(__float2half_rn(v0), __float2half_rn(v1));
    }
}

// ---------------- single-term fp16 mma.sync GEMM ----------------------------
// pre = A16 * B16 + bias. 128x128 tile, BK=64, 512 threads, 4-stage pipeline.
// smem plane: 128 rows x 32 u32 (128B rows); chunk swizzle ch ^ (row & 7).
__global__ __launch_bounds__(512, 1)
void gemm_f16_kernel(const float* __restrict__ bias) {
    extern __shared__ uint32_t smw[];   // 4 stages x 8192 u32
    const int tid = threadIdx.x;
    const int w = tid >> 5, lane = tid & 31;
    const int m0 = blockIdx.x * TM;
    const int n0 = blockIdx.y * TN;
    const int wm = (w & 3) * 32;
    const int wn = (w >> 2) * 32;
    const int lr = lane >> 2, lc = lane & 3;
    const uint32_t smbase = smem_u32(smw);

    float c[2][4][4];
#pragma unroll
    for (int mi = 0; mi < 2; mi++)
#pragma unroll
        for (int ni = 0; ni < 4; ni++)
#pragma unroll
            for (int j = 0; j < 4; j++) c[mi][ni][j] = 0.f;

    auto loadStage = [&](int s, int kt) {
        uint32_t* st = smw + s * STAGE_U32;
        const int ktu = kt >> 1;          // u32 offset (32 u32 per BK)
#pragma unroll
        for (int q = 0; q < 4; q++) {
            int t = tid + q * 512;        // 0..2047
            int pl = t >> 10;             // 0: A, 1: B
            int rem = t & 1023;
            int row = rem >> 3, ch = rem & 7;
            const uint32_t* base = pl ? g_B16u : g_A16u;
            const uint32_t* src = base +
                (size_t)((pl ? n0 : m0) + row) * (D_INV / 2) + ktu + ch * 4;
            uint32_t* dst = st + pl * 4096 + row * 32 + ((ch ^ (row & 7)) << 2);
            cpa16(smem_u32(dst), src);
        }
    };

    loadStage(0, 0);
    asm volatile("cp.async.commit_group;");
    loadStage(1, BK);
    asm volatile("cp.async.commit_group;");
    loadStage(2, 2 * BK);
    asm volatile("cp.async.commit_group;");

    const int a_rowadd = ((lane >> 3) & 1) * 8 + (lane & 7);
    const int a_chadd  = lane >> 4;
    const int b_rowadd = (lane >> 4) * 8 + (lane & 7);
    const int b_chadd  = (lane >> 3) & 1;

    for (int i = 0; i < NIT; i++) {
        asm volatile("cp.async.wait_group 2;" ::: "memory");
        __syncthreads();

        const uint32_t sb = smbase + (i & 3) * (STAGE_U32 * 4);  // byte base

#pragma unroll
        for (int ks = 0; ks < 4; ks++) {
            const int c0 = 2 * ks;
            uint32_t aa[2][4], bb[4][2];
#pragma unroll
            for (int mi = 0; mi < 2; mi++) {
                int R = wm + mi * 16 + a_rowadd;
                int ch = c0 + a_chadd;
                uint32_t off = (uint32_t)(R * 32 + ((ch ^ (R & 7)) << 2)) * 4;
                LDSM4(aa[mi][0], aa[mi][1], aa[mi][2], aa[mi][3], sb + off);
            }
#pragma unroll
            for (int nip = 0; nip < 2; nip++) {
                int N = wn + nip * 16 + b_rowadd;
                int ch = c0 + b_chadd;
                uint32_t off = (uint32_t)(N * 32 + ((ch ^ (N & 7)) << 2)) * 4;
                LDSM4(bb[2 * nip][0], bb[2 * nip][1],
                      bb[2 * nip + 1][0], bb[2 * nip + 1][1], sb + 16384 + off);
            }
#pragma unroll
            for (int mi = 0; mi < 2; mi++)
#pragma unroll
                for (int ni = 0; ni < 4; ni++)
                    MMA_F16(c[mi][ni], aa[mi], bb[ni]);
        }
        if (i + 3 < NIT) loadStage((i + 3) & 3, (i + 3) * BK);
        asm volatile("cp.async.commit_group;");
    }

    // epilogue: add bias, store
#pragma unroll
    for (int mi = 0; mi < 2; mi++) {
        int row = m0 + wm + mi * 16 + lr;
#pragma unroll
        for (int ni = 0; ni < 4; ni++) {
            int col = n0 + wn + ni * 8 + lc * 2;
            float2 bv = *(const float2*)(bias + col);
            float2 o0, o1;
            o0.x = c[mi][ni][0] + bv.x; o0.y = c[mi][ni][1] + bv.y;
            o1.x = c[mi][ni][2] + bv.x; o1.y = c[mi][ni][3] + bv.y;
            *(float2*)(g_pre + (size_t)row * NF + col) = o0;
            *(float2*)(g_pre + (size_t)(row + 8) * NF + col) = o1;
        }
    }
}

// ---------------- misc small kernels ---------------------------------------
__global__ void init_active_kernel() {
    int f = blockIdx.x * blockDim.x + threadIdx.x;
    if (f < NF) g_active[f] = 0;
}

__global__ void dead_kernel(const long long* __restrict__ steps) {
    int f = blockIdx.x * blockDim.x + threadIdx.x;
    if (f < NF)
        g_dead[f] = (g_active[f] == 0 && (steps[f] + 1) >= (long long)DEADTH) ? 1 : 0;
}

// ---------------- exact per-row top-k via 4-pass radix select ---------------
__global__ __launch_bounds__(256)
void topk_kernel(int k, int is_aux, float* __restrict__ coeffs_out,
                 const float* __restrict__ xin, const float* __restrict__ Wenc,
                 const float* __restrict__ be) {
    extern __shared__ unsigned sh[];
    unsigned* keys = sh;                               // NF
    unsigned* hist = sh + NF;                          // 256
    int*      cand_idx = (int*)(hist + 256);           // 256
    unsigned* cand_key = (unsigned*)(cand_idx + 256);  // 256
    float*    exv = (float*)(cand_key + 256);          // 256
    double*   redd = (double*)(exv + 256);             // 256 doubles
    __shared__ int s_bin, s_rem, s_cnt, s_pos, s_nhi, s_nc;

    const int r = blockIdx.x;
    const int tid = threadIdx.x;
    const float* row = g_pre + (size_t)r * NF;

    for (int i = tid; i < NF; i += 256) {
        unsigned u = f2k(row[i]);
        if (is_aux && g_dead[i] == 0) u = 0u;
        keys[i] = u;
    }
    __syncthreads();

    unsigned prefix = 0;
    int remaining = k;
#pragma unroll
    for (int shift = 24; shift >= 0; shift -= 8) {
        hist[tid] = 0;
        __syncthreads();
        unsigned himask = (shift == 24) ? 0u : (0xFFFFFFFFu << (shift + 8));
        for (int i = tid; i < NF; i += 256) {
            unsigned u = keys[i];
            if ((u & himask) == prefix) atomicAdd(&hist[(u >> shift) & 255u], 1u);
        }
        __syncthreads();
        if (tid == 0) {
            int cum = 0, b = 255;
            for (; b > 0; b--) {
                int cnt = (int)hist[b];
                if (cum + cnt >= remaining) break;
                cum += cnt;
            }
            s_bin = b;
            s_rem = remaining - cum;
        }
        __syncthreads();
        prefix |= ((unsigned)s_bin) << shift;
        remaining = s_rem;
        __syncthreads();
    }
    const unsigned thr = prefix;

    if (tid == 0) { s_cnt = 0; s_pos = 0; s_nhi = 0; s_nc = 0; }
    __syncthreads();

    if (!is_aux) {
        // -------- main top-32 with band refinement (1-term fp16 noise) ------
        const float DELTA = 2.4e-3f;
        const float v32 = k2f(thr);
        const unsigned khi = f2k(v32 + DELTA);
        const unsigned klo = f2k(v32 - DELTA);

        for (int i = tid; i < NF; i += 256) {
            unsigned u = keys[i];
            if (u > khi) {
                atomicAdd(&s_nhi, 1);
                float v = k2f(u);
                if (v > 0.f) {
                    int p = atomicAdd(&s_pos, 1);
                    g_tk_idx[r * TOPK + p] = i;
                    g_tk_val[r * TOPK + p] = v;
                    coeffs_out[(size_t)r * NF + i] = v;
                    g_active[i] = 1;
                }
            } else if (u >= klo) {
                int p = atomicAdd(&s_nc, 1);
                if (p < CAND_MAX) { cand_idx[p] = i; cand_key[p] = u; }
            }
        }
        __syncthreads();

        const int need = TOPK - s_nhi;
        const int nc = (s_nc < CAND_MAX) ? s_nc : CAND_MAX;

        auto sel_write = [&](int i, float v) {
            if (v > 0.f) {
                int p = atomicAdd(&s_pos, 1);
                g_tk_idx[r * TOPK + p] = i;
                g_tk_val[r * TOPK + p] = v;
                coeffs_out[(size_t)r * NF + i] = v;
                g_active[i] = 1;
            }
        };

        if (nc == need) {
            if (tid < nc) sel_write(cand_idx[tid], k2f(cand_key[tid]));
        } else {
            // EXACT recompute of candidates from fp32 x / W_enc
            const float* xr = xin + (size_t)r * D_INV;
            for (int t = 0; t < nc; t++) {
                const float* Wc = Wenc + cand_idx[t];
                double part = 0.0;
#pragma unroll
                for (int q = 0; q < 8; q++) {
                    int p = tid + q * 256;
                    part += (double)xr[p] * (double)Wc[(size_t)p * NF];
                }
                redd[tid] = part; __syncthreads();
                for (int s = 128; s > 0; s >>= 1) {
                    if (tid < s) redd[tid] += redd[tid + s];
                    __syncthreads();
                }
                if (tid == 0) exv[t] = (float)(redd[0] + (double)be[cand_idx[t]]);
                __syncthreads();
            }
            if (tid < nc) {
                float mv = exv[tid];
                int mi = cand_idx[tid];
                int rank = 0;
                for (int u = 0; u < nc; u++) {
                    if (exv[u] > mv || (exv[u] == mv && cand_idx[u] < mi)) rank++;
                }
                if (rank < need) sel_write(mi, mv);
            }
        }
        __syncthreads();
        if (tid == 0) g_tk_cnt[r] = s_pos;
    } else {
        // -------- aux top-256: approx selection (flip impact negligible) ----
        for (int i = tid; i < NF; i += 256) {
            unsigned u = keys[i];
            if (u > thr) {
                atomicAdd(&s_cnt, 1);
                float v = k2f(u);
                if (v > 0.f) {
                    int p = atomicAdd(&s_pos, 1);
                    g_ax_idx[r * KAUX + p] = i;
                    g_ax_val[r * KAUX + p] = v;
                }
            }
        }
        __syncthreads();
        if (tid == 0) {
            int need = k - s_cnt;
            if (thr != 0u) {
                for (int i = 0; i < NF && need > 0; i++) {
                    if (keys[i] == thr) {
                        need--;
                        float v = k2f(thr);
                        if (v > 0.f) {
                            int p = s_pos++;
                            g_ax_idx[r * KAUX + p] = i;
                            g_ax_val[r * KAUX + p] = v;
                        }
                    }
                }
            }
            g_ax_cnt[r] = s_pos;
        }
    }
}

// ---------------- sparse decode + deterministic MSE/aux partials -----------
// both decodes read the fp16 W_dec plane; accumulation in fp32.
__global__ __launch_bounds__(256)
void decode_kernel(const float* __restrict__ x,
                   const float* __restrict__ bd, float* __restrict__ recon) {
    const int r = blockIdx.x, tid = threadIdx.x;
    __shared__ int   sidx_[KAUX];
    __shared__ float sval[KAUX];
    __shared__ double sred[256];

    const int cnt = g_tk_cnt[r];
    if (tid < cnt) { sidx_[tid] = g_tk_idx[r * TOPK + tid]; sval[tid] = g_tk_val[r * TOPK + tid]; }
    __syncthreads();

    float2 bdv[4], acc[4];
#pragma unroll
    for (int q = 0; q < 4; q++) {
        bdv[q] = *(const float2*)(bd + (size_t)(tid + 256 * q) * 2);
        acc[q] = bdv[q];
    }

    for (int t = 0; t < cnt; t++) {
        const uint32_t* wq = g_Wd16u + (size_t)sidx_[t] * (D_INV / 2);
        float v = sval[t];
#pragma unroll
        for (int q = 0; q < 4; q++) {
            float2 wf = uph(wq[tid + 256 * q]);
            acc[q].x += v * wf.x;
            acc[q].y += v * wf.y;
        }
    }

    float2 xr[4];
#pragma unroll
    for (int q = 0; q < 4; q++)
        xr[q] = *(const float2*)(x + (size_t)r * D_INV + (size_t)(tid + 256 * q) * 2);

    double pm = 0.0;
#pragma unroll
    for (int q = 0; q < 4; q++) {
        *(float2*)(recon + (size_t)r * D_INV + (size_t)(tid + 256 * q) * 2) = acc[q];
        float ex = acc[q].x - xr[q].x, ey = acc[q].y - xr[q].y;
        pm += (double)ex * ex + (double)ey * ey;
    }

    __syncthreads();
    const int acnt = g_ax_cnt[r];
    if (tid < acnt) { sidx_[tid] = g_ax_idx[r * KAUX + tid]; sval[tid] = g_ax_val[r * KAUX + tid]; }
    __syncthreads();

    float2 aacc[4];
#pragma unroll
    for (int q = 0; q < 4; q++) aacc[q] = bdv[q];
    for (int t = 0; t < acnt; t++) {
        const uint32_t* wq = g_Wd16u + (size_t)sidx_[t] * (D_INV / 2);
        float v = sval[t];
#pragma unroll
        for (int q = 0; q < 4; q++) {
            float2 wf = uph(wq[tid + 256 * q]);
            aacc[q].x += v * wf.x;
            aacc[q].y += v * wf.y;
        }
    }

    double pa = 0.0;
#pragma unroll
    for (int q = 0; q < 4; q++) {
        float rx = xr[q].x - acc[q].x, ry = xr[q].y - acc[q].y;
        float ex = aacc[q].x - rx, ey = aacc[q].y - ry;
        pa += (double)ex * ex + (double)ey * ey;
    }

    sred[tid] = pm; __syncthreads();
    for (int s = 128; s > 0; s >>= 1) { if (tid < s) sred[tid] += sred[tid + s]; __syncthreads(); }
    if (tid == 0) g_pmse[r] = sred[0];
    __syncthreads();
    sred[tid] = pa; __syncthreads();
    for (int s = 128; s > 0; s >>= 1) { if (tid < s) sred[tid] += sred[tid + s]; __syncthreads(); }
    if (tid == 0) g_paux[r] = sred[0];
}

__global__ void finalize_kernel(float* __restrict__ scal) {
    __shared__ double sm[256], sa[256];
    const int tid = threadIdx.x;
    double m = 0.0, a = 0.0;
    for (int i = tid; i < B_TOK; i += 256) { m += g_pmse[i]; a += g_paux[i]; }
    sm[tid] = m; sa[tid] = a; __syncthreads();
    for (int s = 128; s > 0; s >>= 1) {
        if (tid < s) { sm[tid] += sm[tid + s]; sa[tid] += sa[tid + s]; }
        __syncthreads();
    }
    if (tid == 0) {
        const double denom = (double)B_TOK * (double)D_INV;
        double mse = sm[0] / denom;
        double aux = sa[0] / denom;
        scal[0] = (float)(mse + aux);
        scal[1] = (float)mse;
        scal[2] = (float)aux;
    }
}

// ---------------- launch ----------------------------------------------------
extern "C" void kernel_launch(void* const* d_in, const int* in_sizes, int n_in,
                              void* d_out, int out_size) {
    const float*     x     = (const float*)d_in[0];
    const float*     We    = (const float*)d_in[1];
    const float*     be    = (const float*)d_in[2];
    const float*     Wd    = (const float*)d_in[3];
    const float*     bd    = (const float*)d_in[4];
    const long long* steps = (const long long*)d_in[5];

    float* out    = (float*)d_out;
    float* recon  = out;                                       // [4096,2048]
    float* coeffs = out + (size_t)B_TOK * D_INV;               // [4096,16384]
    float* scal   = coeffs + (size_t)B_TOK * NF;               // loss, mse, aux

    const size_t topk_smem = (size_t)(NF + 4 * 256) * 4 + 256 * 8;  // 71680 B
    cudaFuncSetAttribute(topk_kernel, cudaFuncAttributeMaxDynamicSharedMemorySize,
                         (int)topk_smem);
    cudaFuncSetAttribute(gemm_f16_kernel, cudaFuncAttributeMaxDynamicSharedMemorySize,
                         GEMM_SMEM);

    // zero coeffs region + active flags
    cudaMemsetAsync(coeffs, 0, (size_t)B_TOK * NF * sizeof(float));
    init_active_kernel<<<(NF + 255) / 256, 256>>>();

    // fp16 conversion (A rounded, B transposed + rounded, Wd rounded)
    conv_a_kernel<<<(B_TOK * D_INV / 4) / 256, 256>>>(x);
    conv_b_kernel<<<dim3(NF / 32, D_INV / 32), 256>>>(We);
    conv_wd_kernel<<<((size_t)NF * D_INV / 4) / 256, 256>>>(Wd);

    // tensor-core encoder GEMM -> g_pre (single-term fp16 via mma.sync)
    gemm_f16_kernel<<<dim3(B_TOK / TM, NF / TN), 512, GEMM_SMEM>>>(be);

    // main top-32 (band-refined; exact fp32 recompute for borderline)
    topk_kernel<<<B_TOK, 256, topk_smem>>>(TOPK, 0, coeffs, x, We, be);

    // dead mask
    dead_kernel<<<(NF + 255) / 256, 256>>>(steps);

    // aux top-256 over dead features
    topk_kernel<<<B_TOK, 256, topk_smem>>>(KAUX, 1, nullptr, x, We, be);

    // sparse decode + partial sums (fp16 W_dec for both paths)
    decode_kernel<<<B_TOK, 256>>>(x, bd, recon);

    // deterministic final reduction + scalars
    finalize_kernel<<<1, 256>>>(scal);
}

// round 9
// speedup vs baseline: 6.3677x; 1.3742x over previous
#include <cuda_runtime.h>
#include <cuda_fp16.h>
#include <cstdint>

#define B_TOK 4096
#define D_INV 2048
#define NF    16384
#define TOPK  32
#define KAUX  256
#define DEADTH 100

// GEMM tiling
#define TM 128
#define TN 128
#define BK 64
#define NIT (D_INV / BK)          // 32
#define STAGE_U32 8192            // 2 planes x 128 rows x 32 u32 (32KB)
#define GEMM_SMEM (4 * STAGE_U32 * 4)   // 131072 bytes, 4 stages

#define CAND_MAX 256

// ---------------- scratch (device globals; no allocation allowed) ----------
__device__ __half   g_pre[(size_t)B_TOK * NF];        // 128 MB (fp16)
__device__ uint32_t g_A16u[(size_t)B_TOK * D_INV / 2];    // fp16 pairs
__device__ uint32_t g_B16u[(size_t)NF * D_INV / 2];       // fp16 W_enc^T [NF][D/2]
__device__ uint32_t g_Wd16u[(size_t)NF * D_INV / 2];      // fp16 W_dec
__device__ int    g_tk_idx[B_TOK * TOPK];
__device__ float  g_tk_val[B_TOK * TOPK];
__device__ int    g_tk_cnt[B_TOK];
__device__ int    g_ax_idx[B_TOK * KAUX];
__device__ float  g_ax_val[B_TOK * KAUX];
__device__ int    g_ax_cnt[B_TOK];
__device__ int    g_active[NF];
__device__ int    g_dead[NF];
__device__ double g_pmse[B_TOK];
__device__ double g_paux[B_TOK];

// ---------------- helpers ----------------------------------------------------
__device__ __forceinline__ uint32_t smem_u32(const void* p) {
    uint32_t a;
    asm("{ .reg .u64 t; cvta.to.shared.u64 t, %1; cvt.u32.u64 %0, t; }"
        : "=r"(a) : "l"(p));
    return a;
}
__device__ __forceinline__ void cpa16(uint32_t dst, const void* src) {
    asm volatile("cp.async.cg.shared.global [%0], [%1], 16;" :: "r"(dst), "l"(src));
}
__device__ __forceinline__ uint32_t pkh(__half a, __half b) {
    __half2 t = __halves2half2(a, b);
    return *reinterpret_cast<uint32_t*>(&t);
}
__device__ __forceinline__ float2 uph(uint32_t u) {
    __half2 t = *reinterpret_cast<__half2*>(&u);
    return __half22float2(t);
}
// order-preserving 16-bit key map for fp16 bits
__device__ __forceinline__ unsigned short mapk16(unsigned short h) {
    return (h & 0x8000u) ? (unsigned short)(~h) : (unsigned short)(h | 0x8000u);
}
__device__ __forceinline__ float val16(unsigned u) {
    unsigned short b = (u & 0x8000u) ? (unsigned short)(u ^ 0x8000u)
                                     : (unsigned short)(~u & 0xFFFFu);
    return __half2float(__ushort_as_half(b));
}

#define MMA_F16(C, A, B) \
    asm volatile("mma.sync.aligned.m16n8k16.row.col.f32.f16.f16.f32 " \
        "{%0,%1,%2,%3}, {%4,%5,%6,%7}, {%8,%9}, {%0,%1,%2,%3};" \
        : "+f"((C)[0]), "+f"((C)[1]), "+f"((C)[2]), "+f"((C)[3]) \
        : "r"((A)[0]), "r"((A)[1]), "r"((A)[2]), "r"((A)[3]), \
          "r"((B)[0]), "r"((B)[1]))

#define LDSM4(R0, R1, R2, R3, ADDR) \
    asm volatile("ldmatrix.sync.aligned.m8n8.x4.shared.b16 {%0,%1,%2,%3}, [%4];" \
        : "=r"(R0), "=r"(R1), "=r"(R2), "=r"(R3) : "r"(ADDR))

// ---------------- convert pre-pass -------------------------------------------
__global__ __launch_bounds__(256) void conv_a_kernel(const float* __restrict__ A) {
    size_t i = (size_t)blockIdx.x * 256 + threadIdx.x;   // float4 index
    const float4 v = ((const float4*)A)[i];
    ((uint2*)g_A16u)[i] = make_uint2(
        pkh(__float2half_rn(v.x), __float2half_rn(v.y)),
        pkh(__float2half_rn(v.z), __float2half_rn(v.w)));
}

__global__ __launch_bounds__(256) void conv_wd_kernel(const float* __restrict__ Wd) {
    size_t i = (size_t)blockIdx.x * 256 + threadIdx.x;   // float4 index
    const float4 v = ((const float4*)Wd)[i];
    ((uint2*)g_Wd16u)[i] = make_uint2(
        pkh(__float2half_rn(v.x), __float2half_rn(v.y)),
        pkh(__float2half_rn(v.z), __float2half_rn(v.w)));
}

// B [D_INV][NF] -> [NF][D_INV/2] fp16-pair plane via 32x32 smem transpose
__global__ __launch_bounds__(256) void conv_b_kernel(const float* __restrict__ B) {
    __shared__ float sh[32][33];
    const int n0 = blockIdx.x * 32;
    const int k0 = blockIdx.y * 32;
    const int tx = threadIdx.x & 31, ty = threadIdx.x >> 5;
#pragma unroll
    for (int q = 0; q < 4; q++) {
        int k = ty + q * 8;
        sh[k][tx] = B[(size_t)(k0 + k) * NF + n0 + tx];
    }
    __syncthreads();
#pragma unroll
    for (int q = 0; q < 2; q++) {
        int idx = threadIdx.x + q * 256;   // 0..511
        int n = idx & 31, kp = idx >> 5;   // kp 0..15
        float v0 = sh[kp * 2][n], v1 = sh[kp * 2 + 1][n];
        size_t o = (size_t)(n0 + n) * (D_INV / 2) + (k0 >> 1) + kp;
        g_B16u[o] = pkh(__float2half_rn(v0), __float2half_rn(v1));
    }
}

// ---------------- single-term fp16 mma.sync GEMM ----------------------------
__global__ __launch_bounds__(512, 1)
void gemm_f16_kernel(const float* __restrict__ bias) {
    extern __shared__ uint32_t smw[];   // 4 stages x 8192 u32
    const int tid = threadIdx.x;
    const int w = tid >> 5, lane = tid & 31;
    const int m0 = blockIdx.x * TM;
    const int n0 = blockIdx.y * TN;
    const int wm = (w & 3) * 32;
    const int wn = (w >> 2) * 32;
    const int lr = lane >> 2, lc = lane & 3;
    const uint32_t smbase = smem_u32(smw);

    float c[2][4][4];
#pragma unroll
    for (int mi = 0; mi < 2; mi++)
#pragma unroll
        for (int ni = 0; ni < 4; ni++)
#pragma unroll
            for (int j = 0; j < 4; j++) c[mi][ni][j] = 0.f;

    auto loadStage = [&](int s, int kt) {
        uint32_t* st = smw + s * STAGE_U32;
        const int ktu = kt >> 1;
#pragma unroll
        for (int q = 0; q < 4; q++) {
            int t = tid + q * 512;
            int pl = t >> 10;
            int rem = t & 1023;
            int row = rem >> 3, ch = rem & 7;
            const uint32_t* base = pl ? g_B16u : g_A16u;
            const uint32_t* src = base +
                (size_t)((pl ? n0 : m0) + row) * (D_INV / 2) + ktu + ch * 4;
            uint32_t* dst = st + pl * 4096 + row * 32 + ((ch ^ (row & 7)) << 2);
            cpa16(smem_u32(dst), src);
        }
    };

    loadStage(0, 0);
    asm volatile("cp.async.commit_group;");
    loadStage(1, BK);
    asm volatile("cp.async.commit_group;");
    loadStage(2, 2 * BK);
    asm volatile("cp.async.commit_group;");

    const int a_rowadd = ((lane >> 3) & 1) * 8 + (lane & 7);
    const int a_chadd  = lane >> 4;
    const int b_rowadd = (lane >> 4) * 8 + (lane & 7);
    const int b_chadd  = (lane >> 3) & 1;

    for (int i = 0; i < NIT; i++) {
        asm volatile("cp.async.wait_group 2;" ::: "memory");
        __syncthreads();

        const uint32_t sb = smbase + (i & 3) * (STAGE_U32 * 4);

#pragma unroll
        for (int ks = 0; ks < 4; ks++) {
            const int c0 = 2 * ks;
            uint32_t aa[2][4], bb[4][2];
#pragma unroll
            for (int mi = 0; mi < 2; mi++) {
                int R = wm + mi * 16 + a_rowadd;
                int ch = c0 + a_chadd;
                uint32_t off = (uint32_t)(R * 32 + ((ch ^ (R & 7)) << 2)) * 4;
                LDSM4(aa[mi][0], aa[mi][1], aa[mi][2], aa[mi][3], sb + off);
            }
#pragma unroll
            for (int nip = 0; nip < 2; nip++) {
                int N = wn + nip * 16 + b_rowadd;
                int ch = c0 + b_chadd;
                uint32_t off = (uint32_t)(N * 32 + ((ch ^ (N & 7)) << 2)) * 4;
                LDSM4(bb[2 * nip][0], bb[2 * nip][1],
                      bb[2 * nip + 1][0], bb[2 * nip + 1][1], sb + 16384 + off);
            }
#pragma unroll
            for (int mi = 0; mi < 2; mi++)
#pragma unroll
                for (int ni = 0; ni < 4; ni++)
                    MMA_F16(c[mi][ni], aa[mi], bb[ni]);
        }
        if (i + 3 < NIT) loadStage((i + 3) & 3, (i + 3) * BK);
        asm volatile("cp.async.commit_group;");
    }

    // epilogue: add bias, convert to fp16, store half2
#pragma unroll
    for (int mi = 0; mi < 2; mi++) {
        int row = m0 + wm + mi * 16 + lr;
#pragma unroll
        for (int ni = 0; ni < 4; ni++) {
            int col = n0 + wn + ni * 8 + lc * 2;
            float2 bv = *(const float2*)(bias + col);
            uint32_t p0 = pkh(__float2half_rn(c[mi][ni][0] + bv.x),
                              __float2half_rn(c[mi][ni][1] + bv.y));
            uint32_t p1 = pkh(__float2half_rn(c[mi][ni][2] + bv.x),
                              __float2half_rn(c[mi][ni][3] + bv.y));
            *(uint32_t*)(g_pre + (size_t)row * NF + col) = p0;
            *(uint32_t*)(g_pre + (size_t)(row + 8) * NF + col) = p1;
        }
    }
}

// ---------------- misc small kernels ---------------------------------------
__global__ void init_active_kernel() {
    int f = blockIdx.x * blockDim.x + threadIdx.x;
    if (f < NF) g_active[f] = 0;
}

__global__ void dead_kernel(const long long* __restrict__ steps) {
    int f = blockIdx.x * blockDim.x + threadIdx.x;
    if (f < NF)
        g_dead[f] = (g_active[f] == 0 && (steps[f] + 1) >= (long long)DEADTH) ? 1 : 0;
}

// ---------------- per-row top-k: 2-pass radix on 16-bit keys -----------------
// parallel suffix-scan bin selection; parallel tie-fill; exact band refine.
__global__ __launch_bounds__(256)
void topk_kernel(int k, int is_aux, float* __restrict__ coeffs_out,
                 const float* __restrict__ xin, const float* __restrict__ Wenc,
                 const float* __restrict__ be) {
    extern __shared__ char shm_raw[];
    double*   redd     = (double*)shm_raw;                 // 256
    unsigned* hist     = (unsigned*)(redd + 256);          // 256
    unsigned* suf      = hist + 256;                       // 256
    int*      cand_idx = (int*)(suf + 256);                // 256
    unsigned* cand_key = (unsigned*)(cand_idx + 256);      // 256
    float*    exv      = (float*)(cand_key + 256);         // 256
    unsigned short* keys = (unsigned short*)(exv + 256);   // NF
    __shared__ int s_bin, s_rem, s_cnt, s_pos, s_nhi, s_nc;

    const int r = blockIdx.x;
    const int tid = threadIdx.x;
    const __half* row = g_pre + (size_t)r * NF;

    // build 16-bit keys (pairs for coalescing)
    for (int i = tid; i < NF / 2; i += 256) {
        uint32_t pair = ((const uint32_t*)row)[i];
        unsigned short k0 = mapk16((unsigned short)(pair & 0xFFFFu));
        unsigned short k1 = mapk16((unsigned short)(pair >> 16));
        if (is_aux) {
            if (g_dead[2 * i] == 0)     k0 = 0;
            if (g_dead[2 * i + 1] == 0) k1 = 0;
        }
        keys[2 * i] = k0;
        keys[2 * i + 1] = k1;
    }
    __syncthreads();

    unsigned prefix = 0;
    int remaining = k;
#pragma unroll
    for (int shift = 8; shift >= 0; shift -= 8) {
        hist[tid] = 0;
        __syncthreads();
        unsigned himask = (shift == 8) ? 0u : 0xFF00u;
        for (int i = tid; i < NF; i += 256) {
            unsigned u = keys[i];
            if ((u & himask) == prefix) atomicAdd(&hist[(u >> shift) & 255u], 1u);
        }
        __syncthreads();
        // parallel inclusive suffix scan of hist
        suf[tid] = hist[tid];
        __syncthreads();
#pragma unroll
        for (int d = 1; d < 256; d <<= 1) {
            unsigned v = suf[tid];
            unsigned add = (tid + d < 256) ? suf[tid + d] : 0u;
            __syncthreads();
            suf[tid] = v + add;
            __syncthreads();
        }
        if ((int)suf[tid] >= remaining &&
            (tid == 255 || (int)suf[tid + 1] < remaining)) {
            s_bin = tid;
            s_rem = remaining - (tid == 255 ? 0 : (int)suf[tid + 1]);
        }
        __syncthreads();
        prefix |= ((unsigned)s_bin) << shift;
        remaining = s_rem;
        __syncthreads();
    }
    const unsigned thr = prefix;   // 16-bit key of k-th largest

    if (tid == 0) { s_cnt = 0; s_pos = 0; s_nhi = 0; s_nc = 0; }
    __syncthreads();

    if (!is_aux) {
        // -------- main top-32 with band refinement --------
        const float DELTA = 3e-3f;
        const float v32 = val16(thr);
        const float vhi = v32 + DELTA, vlo = v32 - DELTA;

        for (int i = tid; i < NF; i += 256) {
            unsigned u = keys[i];
            float v = val16(u);
            if (v > vhi) {
                atomicAdd(&s_nhi, 1);
                if (v > 0.f) {
                    int p = atomicAdd(&s_pos, 1);
                    g_tk_idx[r * TOPK + p] = i;
                    g_tk_val[r * TOPK + p] = v;
                    coeffs_out[(size_t)r * NF + i] = v;
                    g_active[i] = 1;
                }
            } else if (v >= vlo) {
                int p = atomicAdd(&s_nc, 1);
                if (p < CAND_MAX) { cand_idx[p] = i; cand_key[p] = u; }
            }
        }
        __syncthreads();

        const int need = TOPK - s_nhi;
        const int nc = (s_nc < CAND_MAX) ? s_nc : CAND_MAX;

        auto sel_write = [&](int i, float v) {
            if (v > 0.f) {
                int p = atomicAdd(&s_pos, 1);
                g_tk_idx[r * TOPK + p] = i;
                g_tk_val[r * TOPK + p] = v;
                coeffs_out[(size_t)r * NF + i] = v;
                g_active[i] = 1;
            }
        };

        if (nc == need) {
            if (tid < nc) sel_write(cand_idx[tid], val16(cand_key[tid]));
        } else {
            // EXACT recompute of candidates from fp32 x / W_enc
            const float* xr = xin + (size_t)r * D_INV;
            for (int t = 0; t < nc; t++) {
                const float* Wc = Wenc + cand_idx[t];
                double part = 0.0;
#pragma unroll
                for (int q = 0; q < 8; q++) {
                    int p = tid + q * 256;
                    part += (double)xr[p] * (double)Wc[(size_t)p * NF];
                }
                redd[tid] = part; __syncthreads();
                for (int s = 128; s > 0; s >>= 1) {
                    if (tid < s) redd[tid] += redd[tid + s];
                    __syncthreads();
                }
                if (tid == 0) exv[t] = (float)(redd[0] + (double)be[cand_idx[t]]);
                __syncthreads();
            }
            if (tid < nc) {
                float mv = exv[tid];
                int mi = cand_idx[tid];
                int rank = 0;
                for (int u = 0; u < nc; u++) {
                    if (exv[u] > mv || (exv[u] == mv && cand_idx[u] < mi)) rank++;
                }
                if (rank < need) sel_write(mi, mv);
            }
        }
        __syncthreads();
        if (tid == 0) g_tk_cnt[r] = s_pos;
    } else {
        // -------- aux top-256: approx selection + parallel tie-fill ---------
        for (int i = tid; i < NF; i += 256) {
            unsigned u = keys[i];
            if (u > thr) {
                atomicAdd(&s_cnt, 1);
                float v = val16(u);
                if (v > 0.f) {
                    int p = atomicAdd(&s_pos, 1);
                    if (p < KAUX) {
                        g_ax_idx[r * KAUX + p] = i;
                        g_ax_val[r * KAUX + p] = v;
                    }
                }
            }
        }
        __syncthreads();

        const int need = k - s_cnt;   // ties at thr to take (>=1 typically)
        if (need > 0 && thr != 0u) {
            // collect all key==thr matches in parallel (reuse cand_idx)
            for (int i = tid; i < NF; i += 256) {
                if (keys[i] == thr) {
                    int p = atomicAdd(&s_nc, 1);
                    if (p < CAND_MAX) cand_idx[p] = i;
                }
            }
            __syncthreads();
            const int m = (s_nc < CAND_MAX) ? s_nc : CAND_MAX;
            const float tv = val16(thr);
            if (tid < m && tv > 0.f) {
                int mi = cand_idx[tid];
                int rank = 0;
                for (int u2 = 0; u2 < m; u2++)
                    if (cand_idx[u2] < mi) rank++;
                if (rank < need) {
                    int p = atomicAdd(&s_pos, 1);
                    if (p < KAUX) {
                        g_ax_idx[r * KAUX + p] = mi;
                        g_ax_val[r * KAUX + p] = tv;
                    }
                }
            }
        }
        __syncthreads();
        if (tid == 0) g_ax_cnt[r] = (s_pos < KAUX) ? s_pos : KAUX;
    }
}

// ---------------- sparse decode + deterministic MSE/aux partials -----------
__global__ __launch_bounds__(256)
void decode_kernel(const float* __restrict__ x,
                   const float* __restrict__ bd, float* __restrict__ recon) {
    const int r = blockIdx.x, tid = threadIdx.x;
    __shared__ int   sidx_[KAUX];
    __shared__ float sval[KAUX];
    __shared__ double sred[256];

    const int cnt = g_tk_cnt[r];
    if (tid < cnt) { sidx_[tid] = g_tk_idx[r * TOPK + tid]; sval[tid] = g_tk_val[r * TOPK + tid]; }
    __syncthreads();

    float2 bdv[4], acc[4];
#pragma unroll
    for (int q = 0; q < 4; q++) {
        bdv[q] = *(const float2*)(bd + (size_t)(tid + 256 * q) * 2);
        acc[q] = bdv[q];
    }

    for (int t = 0; t < cnt; t++) {
        const uint32_t* wq = g_Wd16u + (size_t)sidx_[t] * (D_INV / 2);
        float v = sval[t];
#pragma unroll
        for (int q = 0; q < 4; q++) {
            float2 wf = uph(wq[tid + 256 * q]);
            acc[q].x += v * wf.x;
            acc[q].y += v * wf.y;
        }
    }

    float2 xr[4];
#pragma unroll
    for (int q = 0; q < 4; q++)
        xr[q] = *(const float2*)(x + (size_t)r * D_INV + (size_t)(tid + 256 * q) * 2);

    double pm = 0.0;
#pragma unroll
    for (int q = 0; q < 4; q++) {
        *(float2*)(recon + (size_t)r * D_INV + (size_t)(tid + 256 * q) * 2) = acc[q];
        float ex = acc[q].x - xr[q].x, ey = acc[q].y - xr[q].y;
        pm += (double)ex * ex + (double)ey * ey;
    }

    __syncthreads();
    const int acnt = g_ax_cnt[r];
    if (tid < acnt) { sidx_[tid] = g_ax_idx[r * KAUX + tid]; sval[tid] = g_ax_val[r * KAUX + tid]; }
    __syncthreads();

    float2 aacc[4];
#pragma unroll
    for (int q = 0; q < 4; q++) aacc[q] = bdv[q];
    for (int t = 0; t < acnt; t++) {
        const uint32_t* wq = g_Wd16u + (size_t)sidx_[t] * (D_INV / 2);
        float v = sval[t];
#pragma unroll
        for (int q = 0; q < 4; q++) {
            float2 wf = uph(wq[tid + 256 * q]);
            aacc[q].x += v * wf.x;
            aacc[q].y += v * wf.y;
        }
    }

    double pa = 0.0;
#pragma unroll
    for (int q = 0; q < 4; q++) {
        float rx = xr[q].x - acc[q].x, ry = xr[q].y - acc[q].y;
        float ex = aacc[q].x - rx, ey = aacc[q].y - ry;
        pa += (double)ex * ex + (double)ey * ey;
    }

    sred[tid] = pm; __syncthreads();
    for (int s = 128; s > 0; s >>= 1) { if (tid < s) sred[tid] += sred[tid + s]; __syncthreads(); }
    if (tid == 0) g_pmse[r] = sred[0];
    __syncthreads();
    sred[tid] = pa; __syncthreads();
    for (int s = 128; s > 0; s >>= 1) { if (tid < s) sred[tid] += sred[tid + s]; __syncthreads(); }
    if (tid == 0) g_paux[r] = sred[0];
}

__global__ void finalize_kernel(float* __restrict__ scal) {
    __shared__ double sm[256], sa[256];
    const int tid = threadIdx.x;
    double m = 0.0, a = 0.0;
    for (int i = tid; i < B_TOK; i += 256) { m += g_pmse[i]; a += g_paux[i]; }
    sm[tid] = m; sa[tid] = a; __syncthreads();
    for (int s = 128; s > 0; s >>= 1) {
        if (tid < s) { sm[tid] += sm[tid + s]; sa[tid] += sa[tid + s]; }
        __syncthreads();
    }
    if (tid == 0) {
        const double denom = (double)B_TOK * (double)D_INV;
        double mse = sm[0] / denom;
        double aux = sa[0] / denom;
        scal[0] = (float)(mse + aux);
        scal[1] = (float)mse;
        scal[2] = (float)aux;
    }
}

// ---------------- launch ----------------------------------------------------
extern "C" void kernel_launch(void* const* d_in, const int* in_sizes, int n_in,
                              void* d_out, int out_size) {
    const float*     x     = (const float*)d_in[0];
    const float*     We    = (const float*)d_in[1];
    const float*     be    = (const float*)d_in[2];
    const float*     Wd    = (const float*)d_in[3];
    const float*     bd    = (const float*)d_in[4];
    const long long* steps = (const long long*)d_in[5];

    float* out    = (float*)d_out;
    float* recon  = out;                                       // [4096,2048]
    float* coeffs = out + (size_t)B_TOK * D_INV;               // [4096,16384]
    float* scal   = coeffs + (size_t)B_TOK * NF;               // loss, mse, aux

    // smem: redd(2048) + 5x256x4 (5120) + keys (32768) = 39936 B
    const size_t topk_smem = 2048 + 5 * 256 * 4 + (size_t)NF * 2;
    cudaFuncSetAttribute(topk_kernel, cudaFuncAttributeMaxDynamicSharedMemorySize,
                         (int)topk_smem);
    cudaFuncSetAttribute(gemm_f16_kernel, cudaFuncAttributeMaxDynamicSharedMemorySize,
                         GEMM_SMEM);

    // zero coeffs region + active flags
    cudaMemsetAsync(coeffs, 0, (size_t)B_TOK * NF * sizeof(float));
    init_active_kernel<<<(NF + 255) / 256, 256>>>();

    // fp16 conversion (A rounded, B transposed + rounded, Wd rounded)
    conv_a_kernel<<<(B_TOK * D_INV / 4) / 256, 256>>>(x);
    conv_b_kernel<<<dim3(NF / 32, D_INV / 32), 256>>>(We);
    conv_wd_kernel<<<((size_t)NF * D_INV / 4) / 256, 256>>>(Wd);

    // tensor-core encoder GEMM -> g_pre fp16
    gemm_f16_kernel<<<dim3(B_TOK / TM, NF / TN), 512, GEMM_SMEM>>>(be);

    // main top-32 (band-refined; exact fp32 recompute for borderline)
    topk_kernel<<<B_TOK, 256, topk_smem>>>(TOPK, 0, coeffs, x, We, be);

    // dead mask
    dead_kernel<<<(NF + 255) / 256, 256>>>(steps);

    // aux top-256 over dead features
    topk_kernel<<<B_TOK, 256, topk_smem>>>(KAUX, 1, nullptr, x, We, be);

    // sparse decode + partial sums (fp16 W_dec for both paths)
    decode_kernel<<<B_TOK, 256>>>(x, bd, recon);

    // deterministic final reduction + scalars
    finalize_kernel<<<1, 256>>>(scal);
}

// round 10
// speedup vs baseline: 7.4937x; 1.1768x over previous
#include <cuda_runtime.h>
#include <cuda_fp16.h>
#include <cstdint>

#define B_TOK 4096
#define D_INV 2048
#define NF    16384
#define TOPK  32
#define KAUX  256
#define DEADTH 100

// GEMM tiling
#define TM 128
#define TN 128
#define BK 64
#define NIT (D_INV / BK)          // 32
#define STAGE_U32 8192            // A(128x32) + B(128x32) u32 = 32KB
#define GEMM_SMEM (3 * STAGE_U32 * 4)   // 98304 bytes, 3 stages

#define CAND_MAX 256
#define WD8_SCALE 128.0f
#define WD8_INV   0.0078125f

// ---------------- scratch (device globals; no allocation allowed) ----------
__device__ __half   g_pre[(size_t)B_TOK * NF];        // 128 MB (fp16)
__device__ uint32_t g_A16u[(size_t)B_TOK * D_INV / 2];    // fp16 pairs
__device__ uint32_t g_B16u[(size_t)NF * D_INV / 2];       // fp16 W_enc^T [NF][D/2]
__device__ uint32_t g_Wd16u[(size_t)NF * D_INV / 2];      // fp16 W_dec (main)
__device__ unsigned short g_Wd8u[(size_t)NF * D_INV / 2]; // fp8x2 W_dec*128 (aux)
__device__ int    g_tk_idx[B_TOK * TOPK];
__device__ float  g_tk_val[B_TOK * TOPK];
__device__ int    g_tk_cnt[B_TOK];
__device__ int    g_ax_idx[B_TOK * KAUX];
__device__ float  g_ax_val[B_TOK * KAUX];
__device__ int    g_ax_cnt[B_TOK];
__device__ int    g_active[NF];
__device__ int    g_dead[NF];
__device__ double g_pmse[B_TOK];
__device__ double g_paux[B_TOK];

// ---------------- helpers ----------------------------------------------------
__device__ __forceinline__ uint32_t smem_u32(const void* p) {
    uint32_t a;
    asm("{ .reg .u64 t; cvta.to.shared.u64 t, %1; cvt.u32.u64 %0, t; }"
        : "=r"(a) : "l"(p));
    return a;
}
__device__ __forceinline__ void cpa16(uint32_t dst, const void* src) {
    asm volatile("cp.async.cg.shared.global [%0], [%1], 16;" :: "r"(dst), "l"(src));
}
__device__ __forceinline__ uint32_t pkh(__half a, __half b) {
    __half2 t = __halves2half2(a, b);
    return *reinterpret_cast<uint32_t*>(&t);
}
__device__ __forceinline__ float2 uph(uint32_t u) {
    __half2 t = *reinterpret_cast<__half2*>(&u);
    return __half22float2(t);
}
__device__ __forceinline__ unsigned short mapk16(unsigned short h) {
    return (h & 0x8000u) ? (unsigned short)(~h) : (unsigned short)(h | 0x8000u);
}
__device__ __forceinline__ float val16(unsigned u) {
    unsigned short b = (u & 0x8000u) ? (unsigned short)(u ^ 0x8000u)
                                     : (unsigned short)(~u & 0xFFFFu);
    return __half2float(__ushort_as_half(b));
}

#define MMA_F16(C, A, B) \
    asm volatile("mma.sync.aligned.m16n8k16.row.col.f32.f16.f16.f32 " \
        "{%0,%1,%2,%3}, {%4,%5,%6,%7}, {%8,%9}, {%0,%1,%2,%3};" \
        : "+f"((C)[0]), "+f"((C)[1]), "+f"((C)[2]), "+f"((C)[3]) \
        : "r"((A)[0]), "r"((A)[1]), "r"((A)[2]), "r"((A)[3]), \
          "r"((B)[0]), "r"((B)[1]))

#define LDSM4(R0, R1, R2, R3, ADDR) \
    asm volatile("ldmatrix.sync.aligned.m8n8.x4.shared.b16 {%0,%1,%2,%3}, [%4];" \
        : "=r"(R0), "=r"(R1), "=r"(R2), "=r"(R3) : "r"(ADDR))

// ---------------- convert pre-pass -------------------------------------------
__global__ __launch_bounds__(256) void conv_a_kernel(const float* __restrict__ A) {
    size_t i = (size_t)blockIdx.x * 256 + threadIdx.x;   // float4 index
    const float4 v = ((const float4*)A)[i];
    ((uint2*)g_A16u)[i] = make_uint2(
        pkh(__float2half_rn(v.x), __float2half_rn(v.y)),
        pkh(__float2half_rn(v.z), __float2half_rn(v.w)));
}

// W_dec -> fp16 plane (main decode) AND fp8*128 plane (aux decode)
__global__ __launch_bounds__(256) void conv_wd_kernel(const float* __restrict__ Wd) {
    size_t i = (size_t)blockIdx.x * 256 + threadIdx.x;   // float4 index
    const float4 v = ((const float4*)Wd)[i];
    ((uint2*)g_Wd16u)[i] = make_uint2(
        pkh(__float2half_rn(v.x), __float2half_rn(v.y)),
        pkh(__float2half_rn(v.z), __float2half_rn(v.w)));
    unsigned short lo, hi;
    asm("cvt.rn.satfinite.e4m3x2.f32 %0, %1, %2;"
        : "=h"(lo) : "f"(v.y * WD8_SCALE), "f"(v.x * WD8_SCALE));
    asm("cvt.rn.satfinite.e4m3x2.f32 %0, %1, %2;"
        : "=h"(hi) : "f"(v.w * WD8_SCALE), "f"(v.z * WD8_SCALE));
    ((uint32_t*)g_Wd8u)[i] = (uint32_t)lo | ((uint32_t)hi << 16);
}

// B [D_INV][NF] -> [NF][D_INV/2] fp16-pair plane via 32x32 smem transpose
__global__ __launch_bounds__(256) void conv_b_kernel(const float* __restrict__ B) {
    __shared__ float sh[32][33];
    const int n0 = blockIdx.x * 32;
    const int k0 = blockIdx.y * 32;
    const int tx = threadIdx.x & 31, ty = threadIdx.x >> 5;
#pragma unroll
    for (int q = 0; q < 4; q++) {
        int k = ty + q * 8;
        sh[k][tx] = B[(size_t)(k0 + k) * NF + n0 + tx];
    }
    __syncthreads();
#pragma unroll
    for (int q = 0; q < 2; q++) {
        int idx = threadIdx.x + q * 256;   // 0..511
        int n = idx & 31, kp = idx >> 5;   // kp 0..15
        float v0 = sh[kp * 2][n], v1 = sh[kp * 2 + 1][n];
        size_t o = (size_t)(n0 + n) * (D_INV / 2) + (k0 >> 1) + kp;
        g_B16u[o] = pkh(__float2half_rn(v0), __float2half_rn(v1));
    }
}

// ---------------- single-term fp16 mma.sync GEMM ----------------------------
// 128x128 tile, BK=64, 256 threads (8 warps, 32x64 warp tiles), 3-stage, occ 2.
__global__ __launch_bounds__(256, 2)
void gemm_f16_kernel(const float* __restrict__ bias) {
    extern __shared__ uint32_t smw[];   // 3 stages x 8192 u32
    const int tid = threadIdx.x;
    const int w = tid >> 5, lane = tid & 31;
    const int m0 = blockIdx.x * TM;
    const int n0 = blockIdx.y * TN;
    const int wm = (w & 3) * 32;          // 4 m-warps of 32 rows
    const int wn = (w >> 2) * 64;         // 2 n-warps of 64 cols
    const int lr = lane >> 2, lc = lane & 3;
    const uint32_t smbase = smem_u32(smw);

    float c[2][8][4];
#pragma unroll
    for (int mi = 0; mi < 2; mi++)
#pragma unroll
        for (int ni = 0; ni < 8; ni++)
#pragma unroll
            for (int j = 0; j < 4; j++) c[mi][ni][j] = 0.f;

    auto loadStage = [&](int s, int kt) {
        uint32_t* st = smw + s * STAGE_U32;
        const int ktu = kt >> 1;
#pragma unroll
        for (int q = 0; q < 8; q++) {
            int t = tid + q * 256;        // 0..2047
            int pl = t >> 10;             // 0: A, 1: B
            int rem = t & 1023;
            int row = rem >> 3, ch = rem & 7;
            const uint32_t* base = pl ? g_B16u : g_A16u;
            const uint32_t* src = base +
                (size_t)((pl ? n0 : m0) + row) * (D_INV / 2) + ktu + ch * 4;
            uint32_t* dst = st + pl * 4096 + row * 32 + ((ch ^ (row & 7)) << 2);
            cpa16(smem_u32(dst), src);
        }
    };

    loadStage(0, 0);
    asm volatile("cp.async.commit_group;");
    loadStage(1, BK);
    asm volatile("cp.async.commit_group;");

    const int a_rowadd = ((lane >> 3) & 1) * 8 + (lane & 7);
    const int a_chadd  = lane >> 4;
    const int b_rowadd = (lane >> 4) * 8 + (lane & 7);
    const int b_chadd  = (lane >> 3) & 1;

    int s_cur = 0, s_nxt = 2;
    for (int i = 0; i < NIT; i++) {
        asm volatile("cp.async.wait_group 1;" ::: "memory");
        __syncthreads();

        const uint32_t sb = smbase + s_cur * (STAGE_U32 * 4);

#pragma unroll
        for (int ks = 0; ks < 4; ks++) {
            const int c0 = 2 * ks;
            uint32_t aa[2][4], bb[8][2];
#pragma unroll
            for (int mi = 0; mi < 2; mi++) {
                int R = wm + mi * 16 + a_rowadd;
                int ch = c0 + a_chadd;
                uint32_t off = (uint32_t)(R * 32 + ((ch ^ (R & 7)) << 2)) * 4;
                LDSM4(aa[mi][0], aa[mi][1], aa[mi][2], aa[mi][3], sb + off);
            }
#pragma unroll
            for (int nip = 0; nip < 4; nip++) {
                int N = wn + nip * 16 + b_rowadd;
                int ch = c0 + b_chadd;
                uint32_t off = (uint32_t)(N * 32 + ((ch ^ (N & 7)) << 2)) * 4;
                LDSM4(bb[2 * nip][0], bb[2 * nip][1],
                      bb[2 * nip + 1][0], bb[2 * nip + 1][1], sb + 16384 + off);
            }
#pragma unroll
            for (int mi = 0; mi < 2; mi++)
#pragma unroll
                for (int ni = 0; ni < 8; ni++)
                    MMA_F16(c[mi][ni], aa[mi], bb[ni]);
        }
        if (i + 2 < NIT) loadStage(s_nxt, (i + 2) * BK);
        asm volatile("cp.async.commit_group;");
        s_cur = (s_cur == 2) ? 0 : s_cur + 1;
        s_nxt = (s_nxt == 2) ? 0 : s_nxt + 1;
    }

    // epilogue: add bias, convert to fp16, store half2
#pragma unroll
    for (int mi = 0; mi < 2; mi++) {
        int row = m0 + wm + mi * 16 + lr;
#pragma unroll
        for (int ni = 0; ni < 8; ni++) {
            int col = n0 + wn + ni * 8 + lc * 2;
            float2 bv = *(const float2*)(bias + col);
            uint32_t p0 = pkh(__float2half_rn(c[mi][ni][0] + bv.x),
                              __float2half_rn(c[mi][ni][1] + bv.y));
            uint32_t p1 = pkh(__float2half_rn(c[mi][ni][2] + bv.x),
                              __float2half_rn(c[mi][ni][3] + bv.y));
            *(uint32_t*)(g_pre + (size_t)row * NF + col) = p0;
            *(uint32_t*)(g_pre + (size_t)(row + 8) * NF + col) = p1;
        }
    }
}

// ---------------- misc small kernels ---------------------------------------
__global__ void init_active_kernel() {
    int f = blockIdx.x * blockDim.x + threadIdx.x;
    if (f < NF) g_active[f] = 0;
}

__global__ void dead_kernel(const long long* __restrict__ steps) {
    int f = blockIdx.x * blockDim.x + threadIdx.x;
    if (f < NF)
        g_dead[f] = (g_active[f] == 0 && (steps[f] + 1) >= (long long)DEADTH) ? 1 : 0;
}

// ---------------- per-row top-k: 2-pass radix on 16-bit keys -----------------
__global__ __launch_bounds__(256)
void topk_kernel(int k, int is_aux, float* __restrict__ coeffs_out,
                 const float* __restrict__ xin, const float* __restrict__ Wenc,
                 const float* __restrict__ be) {
    extern __shared__ char shm_raw[];
    double*   redd     = (double*)shm_raw;                 // 256
    unsigned* hist     = (unsigned*)(redd + 256);          // 256
    unsigned* suf      = hist + 256;                       // 256
    int*      cand_idx = (int*)(suf + 256);                // 256
    unsigned* cand_key = (unsigned*)(cand_idx + 256);      // 256
    float*    exv      = (float*)(cand_key + 256);         // 256
    unsigned short* keys = (unsigned short*)(exv + 256);   // NF
    __shared__ int s_bin, s_rem, s_cnt, s_pos, s_nhi, s_nc;

    const int r = blockIdx.x;
    const int tid = threadIdx.x;
    const __half* row = g_pre + (size_t)r * NF;

    for (int i = tid; i < NF / 2; i += 256) {
        uint32_t pair = ((const uint32_t*)row)[i];
        unsigned short k0 = mapk16((unsigned short)(pair & 0xFFFFu));
        unsigned short k1 = mapk16((unsigned short)(pair >> 16));
        if (is_aux) {
            if (g_dead[2 * i] == 0)     k0 = 0;
            if (g_dead[2 * i + 1] == 0) k1 = 0;
        }
        keys[2 * i] = k0;
        keys[2 * i + 1] = k1;
    }
    __syncthreads();

    unsigned prefix = 0;
    int remaining = k;
#pragma unroll
    for (int shift = 8; shift >= 0; shift -= 8) {
        hist[tid] = 0;
        __syncthreads();
        unsigned himask = (shift == 8) ? 0u : 0xFF00u;
        for (int i = tid; i < NF; i += 256) {
            unsigned u = keys[i];
            if ((u & himask) == prefix) atomicAdd(&hist[(u >> shift) & 255u], 1u);
        }
        __syncthreads();
        suf[tid] = hist[tid];
        __syncthreads();
#pragma unroll
        for (int d = 1; d < 256; d <<= 1) {
            unsigned v = suf[tid];
            unsigned add = (tid + d < 256) ? suf[tid + d] : 0u;
            __syncthreads();
            suf[tid] = v + add;
            __syncthreads();
        }
        if ((int)suf[tid] >= remaining &&
            (tid == 255 || (int)suf[tid + 1] < remaining)) {
            s_bin = tid;
            s_rem = remaining - (tid == 255 ? 0 : (int)suf[tid + 1]);
        }
        __syncthreads();
        prefix |= ((unsigned)s_bin) << shift;
        remaining = s_rem;
        __syncthreads();
    }
    const unsigned thr = prefix;

    if (tid == 0) { s_cnt = 0; s_pos = 0; s_nhi = 0; s_nc = 0; }
    __syncthreads();

    if (!is_aux) {
        const float DELTA = 3e-3f;
        const float v32 = val16(thr);
        const float vhi = v32 + DELTA, vlo = v32 - DELTA;

        for (int i = tid; i < NF; i += 256) {
            unsigned u = keys[i];
            float v = val16(u);
            if (v > vhi) {
                atomicAdd(&s_nhi, 1);
                if (v > 0.f) {
                    int p = atomicAdd(&s_pos, 1);
                    g_tk_idx[r * TOPK + p] = i;
                    g_tk_val[r * TOPK + p] = v;
                    coeffs_out[(size_t)r * NF + i] = v;
                    g_active[i] = 1;
                }
            } else if (v >= vlo) {
                int p = atomicAdd(&s_nc, 1);
                if (p < CAND_MAX) { cand_idx[p] = i; cand_key[p] = u; }
            }
        }
        __syncthreads();

        const int need = TOPK - s_nhi;
        const int nc = (s_nc < CAND_MAX) ? s_nc : CAND_MAX;

        auto sel_write = [&](int i, float v) {
            if (v > 0.f) {
                int p = atomicAdd(&s_pos, 1);
                g_tk_idx[r * TOPK + p] = i;
                g_tk_val[r * TOPK + p] = v;
                coeffs_out[(size_t)r * NF + i] = v;
                g_active[i] = 1;
            }
        };

        if (nc == need) {
            if (tid < nc) sel_write(cand_idx[tid], val16(cand_key[tid]));
        } else {
            const float* xr = xin + (size_t)r * D_INV;
            for (int t = 0; t < nc; t++) {
                const float* Wc = Wenc + cand_idx[t];
                double part = 0.0;
#pragma unroll
                for (int q = 0; q < 8; q++) {
                    int p = tid + q * 256;
                    part += (double)xr[p] * (double)Wc[(size_t)p * NF];
                }
                redd[tid] = part; __syncthreads();
                for (int s = 128; s > 0; s >>= 1) {
                    if (tid < s) redd[tid] += redd[tid + s];
                    __syncthreads();
                }
                if (tid == 0) exv[t] = (float)(redd[0] + (double)be[cand_idx[t]]);
                __syncthreads();
            }
            if (tid < nc) {
                float mv = exv[tid];
                int mi = cand_idx[tid];
                int rank = 0;
                for (int u = 0; u < nc; u++) {
                    if (exv[u] > mv || (exv[u] == mv && cand_idx[u] < mi)) rank++;
                }
                if (rank < need) sel_write(mi, mv);
            }
        }
        __syncthreads();
        if (tid == 0) g_tk_cnt[r] = s_pos;
    } else {
        for (int i = tid; i < NF; i += 256) {
            unsigned u = keys[i];
            if (u > thr) {
                atomicAdd(&s_cnt, 1);
                float v = val16(u);
                if (v > 0.f) {
                    int p = atomicAdd(&s_pos, 1);
                    if (p < KAUX) {
                        g_ax_idx[r * KAUX + p] = i;
                        g_ax_val[r * KAUX + p] = v;
                    }
                }
            }
        }
        __syncthreads();

        const int need = k - s_cnt;
        if (need > 0 && thr != 0u) {
            for (int i = tid; i < NF; i += 256) {
                if (keys[i] == thr) {
                    int p = atomicAdd(&s_nc, 1);
                    if (p < CAND_MAX) cand_idx[p] = i;
                }
            }
            __syncthreads();
            const int m = (s_nc < CAND_MAX) ? s_nc : CAND_MAX;
            const float tv = val16(thr);
            if (tid < m && tv > 0.f) {
                int mi = cand_idx[tid];
                int rank = 0;
                for (int u2 = 0; u2 < m; u2++)
                    if (cand_idx[u2] < mi) rank++;
                if (rank < need) {
                    int p = atomicAdd(&s_pos, 1);
                    if (p < KAUX) {
                        g_ax_idx[r * KAUX + p] = mi;
                        g_ax_val[r * KAUX + p] = tv;
                    }
                }
            }
        }
        __syncthreads();
        if (tid == 0) g_ax_cnt[r] = (s_pos < KAUX) ? s_pos : KAUX;
    }
}

// ---------------- sparse decode + deterministic MSE/aux partials -----------
// main: fp16 W_dec; aux: fp8 W_dec (scaled by 128)
__global__ __launch_bounds__(256)
void decode_kernel(const float* __restrict__ x,
                   const float* __restrict__ bd, float* __restrict__ recon) {
    const int r = blockIdx.x, tid = threadIdx.x;
    __shared__ int   sidx_[KAUX];
    __shared__ float sval[KAUX];
    __shared__ double sred[256];

    const int cnt = g_tk_cnt[r];
    if (tid < cnt) { sidx_[tid] = g_tk_idx[r * TOPK + tid]; sval[tid] = g_tk_val[r * TOPK + tid]; }
    __syncthreads();

    float2 bdv[4], acc[4];
#pragma unroll
    for (int q = 0; q < 4; q++) {
        bdv[q] = *(const float2*)(bd + (size_t)(tid + 256 * q) * 2);
        acc[q] = bdv[q];
    }

    for (int t = 0; t < cnt; t++) {
        const uint32_t* wq = g_Wd16u + (size_t)sidx_[t] * (D_INV / 2);
        float v = sval[t];
#pragma unroll
        for (int q = 0; q < 4; q++) {
            float2 wf = uph(wq[tid + 256 * q]);
            acc[q].x += v * wf.x;
            acc[q].y += v * wf.y;
        }
    }

    float2 xr[4];
#pragma unroll
    for (int q = 0; q < 4; q++)
        xr[q] = *(const float2*)(x + (size_t)r * D_INV + (size_t)(tid + 256 * q) * 2);

    double pm = 0.0;
#pragma unroll
    for (int q = 0; q < 4; q++) {
        *(float2*)(recon + (size_t)r * D_INV + (size_t)(tid + 256 * q) * 2) = acc[q];
        float ex = acc[q].x - xr[q].x, ey = acc[q].y - xr[q].y;
        pm += (double)ex * ex + (double)ey * ey;
    }

    __syncthreads();
    const int acnt = g_ax_cnt[r];
    if (tid < acnt) { sidx_[tid] = g_ax_idx[r * KAUX + tid]; sval[tid] = g_ax_val[r * KAUX + tid]; }
    __syncthreads();

    float2 aacc[4];
#pragma unroll
    for (int q = 0; q < 4; q++) aacc[q] = bdv[q];
    for (int t = 0; t < acnt; t++) {
        const unsigned short* wq = g_Wd8u + (size_t)sidx_[t] * (D_INV / 2);
        float vs = sval[t] * WD8_INV;
#pragma unroll
        for (int q = 0; q < 4; q++) {
            uint32_t h2;
            asm("cvt.rn.f16x2.e4m3x2 %0, %1;" : "=r"(h2) : "h"(wq[tid + 256 * q]));
            float2 wf = uph(h2);
            aacc[q].x += vs * wf.x;
            aacc[q].y += vs * wf.y;
        }
    }

    double pa = 0.0;
#pragma unroll
    for (int q = 0; q < 4; q++) {
        float rx = xr[q].x - acc[q].x, ry = xr[q].y - acc[q].y;
        float ex = aacc[q].x - rx, ey = aacc[q].y - ry;
        pa += (double)ex * ex + (double)ey * ey;
    }

    sred[tid] = pm; __syncthreads();
    for (int s = 128; s > 0; s >>= 1) { if (tid < s) sred[tid] += sred[tid + s]; __syncthreads(); }
    if (tid == 0) g_pmse[r] = sred[0];
    __syncthreads();
    sred[tid] = pa; __syncthreads();
    for (int s = 128; s > 0; s >>= 1) { if (tid < s) sred[tid] += sred[tid + s]; __syncthreads(); }
    if (tid == 0) g_paux[r] = sred[0];
}

__global__ void finalize_kernel(float* __restrict__ scal) {
    __shared__ double sm[256], sa[256];
    const int tid = threadIdx.x;
    double m = 0.0, a = 0.0;
    for (int i = tid; i < B_TOK; i += 256) { m += g_pmse[i]; a += g_paux[i]; }
    sm[tid] = m; sa[tid] = a; __syncthreads();
    for (int s = 128; s > 0; s >>= 1) {
        if (tid < s) { sm[tid] += sm[tid + s]; sa[tid] += sa[tid + s]; }
        __syncthreads();
    }
    if (tid == 0) {
        const double denom = (double)B_TOK * (double)D_INV;
        double mse = sm[0] / denom;
        double aux = sa[0] / denom;
        scal[0] = (float)(mse + aux);
        scal[1] = (float)mse;
        scal[2] = (float)aux;
    }
}

// ---------------- launch ----------------------------------------------------
extern "C" void kernel_launch(void* const* d_in, const int* in_sizes, int n_in,
                              void* d_out, int out_size) {
    const float*     x     = (const float*)d_in[0];
    const float*     We    = (const float*)d_in[1];
    const float*     be    = (const float*)d_in[2];
    const float*     Wd    = (const float*)d_in[3];
    const float*     bd    = (const float*)d_in[4];
    const long long* steps = (const long long*)d_in[5];

    float* out    = (float*)d_out;
    float* recon  = out;                                       // [4096,2048]
    float* coeffs = out + (size_t)B_TOK * D_INV;               // [4096,16384]
    float* scal   = coeffs + (size_t)B_TOK * NF;               // loss, mse, aux

    const size_t topk_smem = 2048 + 5 * 256 * 4 + (size_t)NF * 2;  // 39936 B
    cudaFuncSetAttribute(topk_kernel, cudaFuncAttributeMaxDynamicSharedMemorySize,
                         (int)topk_smem);
    cudaFuncSetAttribute(gemm_f16_kernel, cudaFuncAttributeMaxDynamicSharedMemorySize,
                         GEMM_SMEM);

    // zero coeffs region + active flags
    cudaMemsetAsync(coeffs, 0, (size_t)B_TOK * NF * sizeof(float));
    init_active_kernel<<<(NF + 255) / 256, 256>>>();

    // fp16/fp8 conversion
    conv_a_kernel<<<(B_TOK * D_INV / 4) / 256, 256>>>(x);
    conv_b_kernel<<<dim3(NF / 32, D_INV / 32), 256>>>(We);
    conv_wd_kernel<<<((size_t)NF * D_INV / 4) / 256, 256>>>(Wd);

    // tensor-core encoder GEMM -> g_pre fp16
    gemm_f16_kernel<<<dim3(B_TOK / TM, NF / TN), 256, GEMM_SMEM>>>(be);

    // main top-32 (band-refined; exact fp32 recompute for borderline)
    topk_kernel<<<B_TOK, 256, topk_smem>>>(TOPK, 0, coeffs, x, We, be);

    // dead mask
    dead_kernel<<<(NF + 255) / 256, 256>>>(steps);

    // aux top-256 over dead features
    topk_kernel<<<B_TOK, 256, topk_smem>>>(KAUX, 1, nullptr, x, We, be);

    // sparse decode + partial sums (fp16 main / fp8 aux W_dec)
    decode_kernel<<<B_TOK, 256>>>(x, bd, recon);

    // deterministic final reduction + scalars
    finalize_kernel<<<1, 256>>>(scal);
}

// round 11
// speedup vs baseline: 7.5926x; 1.0132x over previous
#include <cuda_runtime.h>
#include <cuda_fp16.h>
#include <cstdint>

#define B_TOK 4096
#define D_INV 2048
#define NF    16384
#define TOPK  32
#define KAUX  256
#define DEADTH 100

// GEMM tiling
#define TM 128
#define TN 128
#define BK 64
#define NIT (D_INV / BK)          // 32
#define STAGE_U32 8192            // A(128x32) + B(128x32) u32 = 32KB
#define GEMM_SMEM (3 * STAGE_U32 * 4)   // 98304 bytes, 3 stages

#define CAND_MAX 256
#define WD8_SCALE 128.0f
#define WD8_INV   0.0078125f

// ---------------- scratch (device globals; no allocation allowed) ----------
__device__ __half   g_pre[(size_t)B_TOK * NF];        // 128 MB (fp16)
__device__ uint32_t g_A16u[(size_t)B_TOK * D_INV / 2];    // fp16 pairs
__device__ uint32_t g_B16u[(size_t)NF * D_INV / 2];       // fp16 W_enc^T [NF][D/2]
__device__ uint32_t g_Wd16u[(size_t)NF * D_INV / 2];      // fp16 W_dec (main)
__device__ unsigned short g_Wd8u[(size_t)NF * D_INV / 2]; // fp8x2 W_dec*128 (aux)
__device__ int    g_tk_idx[B_TOK * TOPK];
__device__ float  g_tk_val[B_TOK * TOPK];
__device__ int    g_tk_cnt[B_TOK];
__device__ int    g_ax_idx[B_TOK * KAUX];
__device__ float  g_ax_val[B_TOK * KAUX];
__device__ int    g_ax_cnt[B_TOK];
__device__ int    g_active[NF];
__device__ unsigned g_deadbits[NF / 32];
__device__ double g_pmse[B_TOK];
__device__ double g_paux[B_TOK];

// ---------------- helpers ----------------------------------------------------
__device__ __forceinline__ uint32_t smem_u32(const void* p) {
    uint32_t a;
    asm("{ .reg .u64 t; cvta.to.shared.u64 t, %1; cvt.u32.u64 %0, t; }"
        : "=r"(a) : "l"(p));
    return a;
}
__device__ __forceinline__ void cpa16(uint32_t dst, const void* src) {
    asm volatile("cp.async.cg.shared.global [%0], [%1], 16;" :: "r"(dst), "l"(src));
}
__device__ __forceinline__ uint32_t pkh(__half a, __half b) {
    __half2 t = __halves2half2(a, b);
    return *reinterpret_cast<uint32_t*>(&t);
}
__device__ __forceinline__ float2 uph(uint32_t u) {
    __half2 t = *reinterpret_cast<__half2*>(&u);
    return __half22float2(t);
}
__device__ __forceinline__ unsigned short mapk16(unsigned short h) {
    return (h & 0x8000u) ? (unsigned short)(~h) : (unsigned short)(h | 0x8000u);
}
__device__ __forceinline__ float val16(unsigned u) {
    unsigned short b = (u & 0x8000u) ? (unsigned short)(u ^ 0x8000u)
                                     : (unsigned short)(~u & 0xFFFFu);
    return __half2float(__ushort_as_half(b));
}

#define MMA_F16(C, A, B) \
    asm volatile("mma.sync.aligned.m16n8k16.row.col.f32.f16.f16.f32 " \
        "{%0,%1,%2,%3}, {%4,%5,%6,%7}, {%8,%9}, {%0,%1,%2,%3};" \
        : "+f"((C)[0]), "+f"((C)[1]), "+f"((C)[2]), "+f"((C)[3]) \
        : "r"((A)[0]), "r"((A)[1]), "r"((A)[2]), "r"((A)[3]), \
          "r"((B)[0]), "r"((B)[1]))

#define LDSM4(R0, R1, R2, R3, ADDR) \
    asm volatile("ldmatrix.sync.aligned.m8n8.x4.shared.b16 {%0,%1,%2,%3}, [%4];" \
        : "=r"(R0), "=r"(R1), "=r"(R2), "=r"(R3) : "r"(ADDR))

// ---------------- convert pre-pass -------------------------------------------
__global__ __launch_bounds__(256) void conv_a_kernel(const float* __restrict__ A) {
    size_t i = (size_t)blockIdx.x * 256 + threadIdx.x;   // float4 index
    const float4 v = ((const float4*)A)[i];
    ((uint2*)g_A16u)[i] = make_uint2(
        pkh(__float2half_rn(v.x), __float2half_rn(v.y)),
        pkh(__float2half_rn(v.z), __float2half_rn(v.w)));
}

// W_dec -> fp16 plane (main decode) AND fp8*128 plane (aux decode)
__global__ __launch_bounds__(256) void conv_wd_kernel(const float* __restrict__ Wd) {
    size_t i = (size_t)blockIdx.x * 256 + threadIdx.x;   // float4 index
    const float4 v = ((const float4*)Wd)[i];
    ((uint2*)g_Wd16u)[i] = make_uint2(
        pkh(__float2half_rn(v.x), __float2half_rn(v.y)),
        pkh(__float2half_rn(v.z), __float2half_rn(v.w)));
    unsigned short lo, hi;
    asm("cvt.rn.satfinite.e4m3x2.f32 %0, %1, %2;"
        : "=h"(lo) : "f"(v.y * WD8_SCALE), "f"(v.x * WD8_SCALE));
    asm("cvt.rn.satfinite.e4m3x2.f32 %0, %1, %2;"
        : "=h"(hi) : "f"(v.w * WD8_SCALE), "f"(v.z * WD8_SCALE));
    ((uint32_t*)g_Wd8u)[i] = (uint32_t)lo | ((uint32_t)hi << 16);
}

// B [D_INV][NF] -> [NF][D_INV/2] fp16-pair plane via 32x32 smem transpose.
// Also zero-inits g_active (blockIdx.y == 0 rows).
__global__ __launch_bounds__(256) void conv_b_kernel(const float* __restrict__ B) {
    __shared__ float sh[32][33];
    const int n0 = blockIdx.x * 32;
    const int k0 = blockIdx.y * 32;
    const int tx = threadIdx.x & 31, ty = threadIdx.x >> 5;
    if (blockIdx.y == 0 && threadIdx.x < 32) g_active[n0 + threadIdx.x] = 0;
#pragma unroll
    for (int q = 0; q < 4; q++) {
        int k = ty + q * 8;
        sh[k][tx] = B[(size_t)(k0 + k) * NF + n0 + tx];
    }
    __syncthreads();
#pragma unroll
    for (int q = 0; q < 2; q++) {
        int idx = threadIdx.x + q * 256;   // 0..511
        int n = idx & 31, kp = idx >> 5;   // kp 0..15
        float v0 = sh[kp * 2][n], v1 = sh[kp * 2 + 1][n];
        size_t o = (size_t)(n0 + n) * (D_INV / 2) + (k0 >> 1) + kp;
        g_B16u[o] = pkh(__float2half_rn(v0), __float2half_rn(v1));
    }
}

// ---------------- single-term fp16 mma.sync GEMM ----------------------------
__global__ __launch_bounds__(256, 2)
void gemm_f16_kernel(const float* __restrict__ bias) {
    extern __shared__ uint32_t smw[];   // 3 stages x 8192 u32
    const int tid = threadIdx.x;
    const int w = tid >> 5, lane = tid & 31;
    const int m0 = blockIdx.x * TM;
    const int n0 = blockIdx.y * TN;
    const int wm = (w & 3) * 32;
    const int wn = (w >> 2) * 64;
    const int lr = lane >> 2, lc = lane & 3;
    const uint32_t smbase = smem_u32(smw);

    float c[2][8][4];
#pragma unroll
    for (int mi = 0; mi < 2; mi++)
#pragma unroll
        for (int ni = 0; ni < 8; ni++)
#pragma unroll
            for (int j = 0; j < 4; j++) c[mi][ni][j] = 0.f;

    auto loadStage = [&](int s, int kt) {
        uint32_t* st = smw + s * STAGE_U32;
        const int ktu = kt >> 1;
#pragma unroll
        for (int q = 0; q < 8; q++) {
            int t = tid + q * 256;
            int pl = t >> 10;
            int rem = t & 1023;
            int row = rem >> 3, ch = rem & 7;
            const uint32_t* base = pl ? g_B16u : g_A16u;
            const uint32_t* src = base +
                (size_t)((pl ? n0 : m0) + row) * (D_INV / 2) + ktu + ch * 4;
            uint32_t* dst = st + pl * 4096 + row * 32 + ((ch ^ (row & 7)) << 2);
            cpa16(smem_u32(dst), src);
        }
    };

    loadStage(0, 0);
    asm volatile("cp.async.commit_group;");
    loadStage(1, BK);
    asm volatile("cp.async.commit_group;");

    const int a_rowadd = ((lane >> 3) & 1) * 8 + (lane & 7);
    const int a_chadd  = lane >> 4;
    const int b_rowadd = (lane >> 4) * 8 + (lane & 7);
    const int b_chadd  = (lane >> 3) & 1;

    int s_cur = 0, s_nxt = 2;
    for (int i = 0; i < NIT; i++) {
        asm volatile("cp.async.wait_group 1;" ::: "memory");
        __syncthreads();

        const uint32_t sb = smbase + s_cur * (STAGE_U32 * 4);

#pragma unroll
        for (int ks = 0; ks < 4; ks++) {
            const int c0 = 2 * ks;
            uint32_t aa[2][4], bb[8][2];
#pragma unroll
            for (int mi = 0; mi < 2; mi++) {
                int R = wm + mi * 16 + a_rowadd;
                int ch = c0 + a_chadd;
                uint32_t off = (uint32_t)(R * 32 + ((ch ^ (R & 7)) << 2)) * 4;
                LDSM4(aa[mi][0], aa[mi][1], aa[mi][2], aa[mi][3], sb + off);
            }
#pragma unroll
            for (int nip = 0; nip < 4; nip++) {
                int N = wn + nip * 16 + b_rowadd;
                int ch = c0 + b_chadd;
                uint32_t off = (uint32_t)(N * 32 + ((ch ^ (N & 7)) << 2)) * 4;
                LDSM4(bb[2 * nip][0], bb[2 * nip][1],
                      bb[2 * nip + 1][0], bb[2 * nip + 1][1], sb + 16384 + off);
            }
#pragma unroll
            for (int mi = 0; mi < 2; mi++)
#pragma unroll
                for (int ni = 0; ni < 8; ni++)
                    MMA_F16(c[mi][ni], aa[mi], bb[ni]);
        }
        if (i + 2 < NIT) loadStage(s_nxt, (i + 2) * BK);
        asm volatile("cp.async.commit_group;");
        s_cur = (s_cur == 2) ? 0 : s_cur + 1;
        s_nxt = (s_nxt == 2) ? 0 : s_nxt + 1;
    }

    // epilogue: add bias, convert to fp16, store half2
#pragma unroll
    for (int mi = 0; mi < 2; mi++) {
        int row = m0 + wm + mi * 16 + lr;
#pragma unroll
        for (int ni = 0; ni < 8; ni++) {
            int col = n0 + wn + ni * 8 + lc * 2;
            float2 bv = *(const float2*)(bias + col);
            uint32_t p0 = pkh(__float2half_rn(c[mi][ni][0] + bv.x),
                              __float2half_rn(c[mi][ni][1] + bv.y));
            uint32_t p1 = pkh(__float2half_rn(c[mi][ni][2] + bv.x),
                              __float2half_rn(c[mi][ni][3] + bv.y));
            *(uint32_t*)(g_pre + (size_t)row * NF + col) = p0;
            *(uint32_t*)(g_pre + (size_t)(row + 8) * NF + col) = p1;
        }
    }
}

// ---------------- dead mask (bitmask via ballot) -----------------------------
__global__ void dead_kernel(const long long* __restrict__ steps) {
    int f = blockIdx.x * blockDim.x + threadIdx.x;
    bool dead = false;
    if (f < NF)
        dead = (g_active[f] == 0 && (steps[f] + 1) >= (long long)DEADTH);
    unsigned m = __ballot_sync(0xFFFFFFFFu, dead);
    if ((threadIdx.x & 31) == 0 && f < NF) g_deadbits[f >> 5] = m;
}

// ---------------- per-row top-k: 2-pass radix on 16-bit keys -----------------
// warp-shuffle suffix scan; dead bitmask in smem; exact band refine.
__global__ __launch_bounds__(256)
void topk_kernel(int k, int is_aux, float* __restrict__ coeffs_out,
                 const float* __restrict__ xin, const float* __restrict__ Wenc,
                 const float* __restrict__ be) {
    extern __shared__ char shm_raw[];
    double*   redd     = (double*)shm_raw;                 // 256
    unsigned* hist     = (unsigned*)(redd + 256);          // 256
    unsigned* wsum     = hist + 256;                       // 8 (+pad to 256)
    int*      cand_idx = (int*)(wsum + 256);               // 256
    unsigned* cand_key = (unsigned*)(cand_idx + 256);      // 256
    float*    exv      = (float*)(cand_key + 256);         // 256
    unsigned* sdead    = (unsigned*)(exv + 256);           // NF/32 = 512
    unsigned short* keys = (unsigned short*)(sdead + 512); // NF
    __shared__ int s_bin, s_rem, s_cnt, s_pos, s_nhi, s_nc;

    const int r = blockIdx.x;
    const int tid = threadIdx.x;
    const int lane = tid & 31, wid = tid >> 5;
    const __half* row = g_pre + (size_t)r * NF;

    if (is_aux)
        for (int i = tid; i < NF / 32; i += 256) sdead[i] = g_deadbits[i];
    __syncthreads();

    for (int i = tid; i < NF / 2; i += 256) {
        uint32_t pair = ((const uint32_t*)row)[i];
        unsigned short k0 = mapk16((unsigned short)(pair & 0xFFFFu));
        unsigned short k1 = mapk16((unsigned short)(pair >> 16));
        if (is_aux) {
            unsigned db = sdead[i >> 4];       // word covering bits 2i, 2i+1
            if (!((db >> ((2 * i) & 31)) & 1u))     k0 = 0;
            if (!((db >> ((2 * i + 1) & 31)) & 1u)) k1 = 0;
        }
        keys[2 * i] = k0;
        keys[2 * i + 1] = k1;
    }
    __syncthreads();

    unsigned prefix = 0;
    int remaining = k;
#pragma unroll
    for (int shift = 8; shift >= 0; shift -= 8) {
        hist[tid] = 0;
        __syncthreads();
        unsigned himask = (shift == 8) ? 0u : 0xFF00u;
        for (int i = tid; i < NF; i += 256) {
            unsigned u = keys[i];
            if ((u & himask) == prefix) atomicAdd(&hist[(u >> shift) & 255u], 1u);
        }
        __syncthreads();
        // warp-shuffle inclusive suffix scan over 256 bins
        unsigned v = hist[tid];
        unsigned myh = v;
#pragma unroll
        for (int d = 1; d < 32; d <<= 1) {
            unsigned t = __shfl_down_sync(0xFFFFFFFFu, v, d);
            if (lane + d < 32) v += t;
        }
        if (lane == 0) wsum[wid] = v;
        __syncthreads();
        if (tid < 8) {
            unsigned wv = wsum[tid];
#pragma unroll
            for (int d = 1; d < 8; d <<= 1) {
                unsigned t = __shfl_down_sync(0xFFu, wv, d, 8);
                if (tid + d < 8) wv += t;
            }
            wsum[tid] = wv;
        }
        __syncthreads();
        unsigned suffix = v + ((wid < 7) ? wsum[wid + 1] : 0u);
        unsigned suffix_excl = suffix - myh;
        if ((int)suffix >= remaining && (int)suffix_excl < remaining) {
            s_bin = tid;
            s_rem = remaining - (int)suffix_excl;
        }
        __syncthreads();
        prefix |= ((unsigned)s_bin) << shift;
        remaining = s_rem;
        __syncthreads();
    }
    const unsigned thr = prefix;

    if (tid == 0) { s_cnt = 0; s_pos = 0; s_nhi = 0; s_nc = 0; }
    __syncthreads();

    if (!is_aux) {
        const float DELTA = 3e-3f;
        const float v32 = val16(thr);
        const float vhi = v32 + DELTA, vlo = v32 - DELTA;

        for (int i = tid; i < NF; i += 256) {
            unsigned u = keys[i];
            float v = val16(u);
            if (v > vhi) {
                atomicAdd(&s_nhi, 1);
                if (v > 0.f) {
                    int p = atomicAdd(&s_pos, 1);
                    g_tk_idx[r * TOPK + p] = i;
                    g_tk_val[r * TOPK + p] = v;
                    coeffs_out[(size_t)r * NF + i] = v;
                    g_active[i] = 1;
                }
            } else if (v >= vlo) {
                int p = atomicAdd(&s_nc, 1);
                if (p < CAND_MAX) { cand_idx[p] = i; cand_key[p] = u; }
            }
        }
        __syncthreads();

        const int need = TOPK - s_nhi;
        const int nc = (s_nc < CAND_MAX) ? s_nc : CAND_MAX;

        auto sel_write = [&](int i, float v) {
            if (v > 0.f) {
                int p = atomicAdd(&s_pos, 1);
                g_tk_idx[r * TOPK + p] = i;
                g_tk_val[r * TOPK + p] = v;
                coeffs_out[(size_t)r * NF + i] = v;
                g_active[i] = 1;
            }
        };

        if (nc == need) {
            if (tid < nc) sel_write(cand_idx[tid], val16(cand_key[tid]));
        } else {
            const float* xr = xin + (size_t)r * D_INV;
            for (int t = 0; t < nc; t++) {
                const float* Wc = Wenc + cand_idx[t];
                double part = 0.0;
#pragma unroll
                for (int q = 0; q < 8; q++) {
                    int p = tid + q * 256;
                    part += (double)xr[p] * (double)Wc[(size_t)p * NF];
                }
                redd[tid] = part; __syncthreads();
                for (int s = 128; s > 0; s >>= 1) {
                    if (tid < s) redd[tid] += redd[tid + s];
                    __syncthreads();
                }
                if (tid == 0) exv[t] = (float)(redd[0] + (double)be[cand_idx[t]]);
                __syncthreads();
            }
            if (tid < nc) {
                float mv = exv[tid];
                int mi = cand_idx[tid];
                int rank = 0;
                for (int u = 0; u < nc; u++) {
                    if (exv[u] > mv || (exv[u] == mv && cand_idx[u] < mi)) rank++;
                }
                if (rank < need) sel_write(mi, mv);
            }
        }
        __syncthreads();
        if (tid == 0) g_tk_cnt[r] = s_pos;
    } else {
        for (int i = tid; i < NF; i += 256) {
            unsigned u = keys[i];
            if (u > thr) {
                atomicAdd(&s_cnt, 1);
                float v = val16(u);
                if (v > 0.f) {
                    int p = atomicAdd(&s_pos, 1);
                    if (p < KAUX) {
                        g_ax_idx[r * KAUX + p] = i;
                        g_ax_val[r * KAUX + p] = v;
                    }
                }
            }
        }
        __syncthreads();

        const int need = k - s_cnt;
        if (need > 0 && thr != 0u) {
            for (int i = tid; i < NF; i += 256) {
                if (keys[i] == thr) {
                    int p = atomicAdd(&s_nc, 1);
                    if (p < CAND_MAX) cand_idx[p] = i;
                }
            }
            __syncthreads();
            const int m = (s_nc < CAND_MAX) ? s_nc : CAND_MAX;
            const float tv = val16(thr);
            if (tid < m && tv > 0.f) {
                int mi = cand_idx[tid];
                int rank = 0;
                for (int u2 = 0; u2 < m; u2++)
                    if (cand_idx[u2] < mi) rank++;
                if (rank < need) {
                    int p = atomicAdd(&s_pos, 1);
                    if (p < KAUX) {
                        g_ax_idx[r * KAUX + p] = mi;
                        g_ax_val[r * KAUX + p] = tv;
                    }
                }
            }
        }
        __syncthreads();
        if (tid == 0) g_ax_cnt[r] = (s_pos < KAUX) ? s_pos : KAUX;
    }
}

// ---------------- sparse decode + deterministic MSE/aux partials -----------
__global__ __launch_bounds__(256)
void decode_kernel(const float* __restrict__ x,
                   const float* __restrict__ bd, float* __restrict__ recon) {
    const int r = blockIdx.x, tid = threadIdx.x;
    __shared__ int   sidx_[KAUX];
    __shared__ float sval[KAUX];
    __shared__ double sred[256];

    const int cnt = g_tk_cnt[r];
    if (tid < cnt) { sidx_[tid] = g_tk_idx[r * TOPK + tid]; sval[tid] = g_tk_val[r * TOPK + tid]; }
    __syncthreads();

    float2 bdv[4], acc[4];
#pragma unroll
    for (int q = 0; q < 4; q++) {
        bdv[q] = *(const float2*)(bd + (size_t)(tid + 256 * q) * 2);
        acc[q] = bdv[q];
    }

    for (int t = 0; t < cnt; t++) {
        const uint32_t* wq = g_Wd16u + (size_t)sidx_[t] * (D_INV / 2);
        float v = sval[t];
#pragma unroll
        for (int q = 0; q < 4; q++) {
            float2 wf = uph(wq[tid + 256 * q]);
            acc[q].x += v * wf.x;
            acc[q].y += v * wf.y;
        }
    }

    float2 xr[4];
#pragma unroll
    for (int q = 0; q < 4; q++)
        xr[q] = *(const float2*)(x + (size_t)r * D_INV + (size_t)(tid + 256 * q) * 2);

    double pm = 0.0;
#pragma unroll
    for (int q = 0; q < 4; q++) {
        *(float2*)(recon + (size_t)r * D_INV + (size_t)(tid + 256 * q) * 2) = acc[q];
        float ex = acc[q].x - xr[q].x, ey = acc[q].y - xr[q].y;
        pm += (double)ex * ex + (double)ey * ey;
    }

    __syncthreads();
    const int acnt = g_ax_cnt[r];
    if (tid < acnt) { sidx_[tid] = g_ax_idx[r * KAUX + tid]; sval[tid] = g_ax_val[r * KAUX + tid]; }
    __syncthreads();

    float2 aacc[4];
#pragma unroll
    for (int q = 0; q < 4; q++) aacc[q] = bdv[q];
    for (int t = 0; t < acnt; t++) {
        const unsigned short* wq = g_Wd8u + (size_t)sidx_[t] * (D_INV / 2);
        float vs = sval[t] * WD8_INV;
#pragma unroll
        for (int q = 0; q < 4; q++) {
            uint32_t h2;
            asm("cvt.rn.f16x2.e4m3x2 %0, %1;" : "=r"(h2) : "h"(wq[tid + 256 * q]));
            float2 wf = uph(h2);
            aacc[q].x += vs * wf.x;
            aacc[q].y += vs * wf.y;
        }
    }

    double pa = 0.0;
#pragma unroll
    for (int q = 0; q < 4; q++) {
        float rx = xr[q].x - acc[q].x, ry = xr[q].y - acc[q].y;
        float ex = aacc[q].x - rx, ey = aacc[q].y - ry;
        pa += (double)ex * ex + (double)ey * ey;
    }

    sred[tid] = pm; __syncthreads();
    for (int s = 128; s > 0; s >>= 1) { if (tid < s) sred[tid] += sred[tid + s]; __syncthreads(); }
    if (tid == 0) g_pmse[r] = sred[0];
    __syncthreads();
    sred[tid] = pa; __syncthreads();
    for (int s = 128; s > 0; s >>= 1) { if (tid < s) sred[tid] += sred[tid + s]; __syncthreads(); }
    if (tid == 0) g_paux[r] = sred[0];
}

__global__ void finalize_kernel(float* __restrict__ scal) {
    __shared__ double sm[256], sa[256];
    const int tid = threadIdx.x;
    double m = 0.0, a = 0.0;
    for (int i = tid; i < B_TOK; i += 256) { m += g_pmse[i]; a += g_paux[i]; }
    sm[tid] = m; sa[tid] = a; __syncthreads();
    for (int s = 128; s > 0; s >>= 1) {
        if (tid < s) { sm[tid] += sm[tid + s]; sa[tid] += sa[tid + s]; }
        __syncthreads();
    }
    if (tid == 0) {
        const double denom = (double)B_TOK * (double)D_INV;
        double mse = sm[0] / denom;
        double aux = sa[0] / denom;
        scal[0] = (float)(mse + aux);
        scal[1] = (float)mse;
        scal[2] = (float)aux;
    }
}

// ---------------- launch ----------------------------------------------------
extern "C" void kernel_launch(void* const* d_in, const int* in_sizes, int n_in,
                              void* d_out, int out_size) {
    const float*     x     = (const float*)d_in[0];
    const float*     We    = (const float*)d_in[1];
    const float*     be    = (const float*)d_in[2];
    const float*     Wd    = (const float*)d_in[3];
    const float*     bd    = (const float*)d_in[4];
    const long long* steps = (const long long*)d_in[5];

    float* out    = (float*)d_out;
    float* recon  = out;                                       // [4096,2048]
    float* coeffs = out + (size_t)B_TOK * D_INV;               // [4096,16384]
    float* scal   = coeffs + (size_t)B_TOK * NF;               // loss, mse, aux

    // smem: redd(2048) + hist/wsum/cand_idx/cand_key/exv (5*1024) + sdead(2048)
    //       + keys (32768) = 41984 B
    const size_t topk_smem = 2048 + 5 * 256 * 4 + 2048 + (size_t)NF * 2;
    cudaFuncSetAttribute(topk_kernel, cudaFuncAttributeMaxDynamicSharedMemorySize,
                         (int)topk_smem);
    cudaFuncSetAttribute(gemm_f16_kernel, cudaFuncAttributeMaxDynamicSharedMemorySize,
                         GEMM_SMEM);

    // fork-join side stream: conv_wd + coeffs memset overlap the GEMM chain
    cudaStream_t side;
    cudaStreamCreateWithFlags(&side, cudaStreamNonBlocking);
    cudaEvent_t evFork, evJoin;
    cudaEventCreateWithFlags(&evFork, cudaEventDisableTiming);
    cudaEventCreateWithFlags(&evJoin, cudaEventDisableTiming);

    cudaEventRecord(evFork, 0);
    cudaStreamWaitEvent(side, evFork, 0);
    conv_wd_kernel<<<((size_t)NF * D_INV / 4) / 256, 256, 0, side>>>(Wd);
    cudaMemsetAsync(coeffs, 0, (size_t)B_TOK * NF * sizeof(float), side);
    cudaEventRecord(evJoin, side);

    // main stream: conversions + GEMM
    conv_a_kernel<<<(B_TOK * D_INV / 4) / 256, 256>>>(x);
    conv_b_kernel<<<dim3(NF / 32, D_INV / 32), 256>>>(We);   // also inits g_active
    gemm_f16_kernel<<<dim3(B_TOK / TM, NF / TN), 256, GEMM_SMEM>>>(be);

    // join before topk_main (needs zeroed coeffs; conv_wd needed by decode later)
    cudaStreamWaitEvent(0, evJoin, 0);

    // main top-32 (band-refined; exact fp32 recompute for borderline)
    topk_kernel<<<B_TOK, 256, topk_smem>>>(TOPK, 0, coeffs, x, We, be);

    // dead bitmask
    dead_kernel<<<(NF + 255) / 256, 256>>>(steps);

    // aux top-256 over dead features
    topk_kernel<<<B_TOK, 256, topk_smem>>>(KAUX, 1, nullptr, x, We, be);

    // sparse decode + partial sums (fp16 main / fp8 aux W_dec)
    decode_kernel<<<B_TOK, 256>>>(x, bd, recon);

    // deterministic final reduction + scalars
    finalize_kernel<<<1, 256>>>(scal);
}